// round 1
// baseline (speedup 1.0000x reference)
#include <cuda_runtime.h>
#include <math.h>
#include <stdint.h>

// ---------------------------------------------------------------------------
// TransformerBlock: B=4, S=2048, E=1024, H=16, D=64  (all fp32)
//   x   = LN1(inp)
//   q,k,v = x@W{q,k,v}+b  (per-head split is pure indexing: col = h*64+d)
//   ctx = softmax(q kT / 8) v        (flash-style, per (b,h,qtile))
//   x2  = x + ctx@Wo + bo            (residual from LN1 output, per reference)
//   x3  = LN2(x2)
//   out = gelu(x3@W1+b1)@W2 + b2 + x3
// ---------------------------------------------------------------------------

#define MDIM 8192      // B*S
#define EDIM 1024
#define SDIM 2048
#define BDIM 4
#define HDIM 16
#define FDIM 2048      // 2*E

// Scratch (allocation-free rule: __device__ globals)
__device__ float g_xln1[MDIM * EDIM];
__device__ float g_q  [MDIM * EDIM];
__device__ float g_k  [MDIM * EDIM];
__device__ float g_v  [MDIM * EDIM];
__device__ float g_ctx[MDIM * EDIM];
__device__ float g_x2 [MDIM * EDIM];
__device__ float g_x3 [MDIM * EDIM];
__device__ float g_h1 [MDIM * FDIM];

// ---------------------------------------------------------------------------
// LayerNorm over E=1024. One block (256 threads) per row; float4 IO.
// ---------------------------------------------------------------------------
__global__ __launch_bounds__(256) void ln_kernel(
    const float* __restrict__ x, const float* __restrict__ g,
    const float* __restrict__ b, float* __restrict__ y)
{
    const int row = blockIdx.x;
    const int tid = threadIdx.x;
    const float4 v = reinterpret_cast<const float4*>(x + (size_t)row * EDIM)[tid];

    float s  = v.x + v.y + v.z + v.w;
    float ss = v.x * v.x + v.y * v.y + v.z * v.z + v.w * v.w;

    #pragma unroll
    for (int off = 16; off > 0; off >>= 1) {
        s  += __shfl_down_sync(0xffffffffu, s,  off);
        ss += __shfl_down_sync(0xffffffffu, ss, off);
    }
    __shared__ float wsum[8], wsq[8];
    __shared__ float s_mu, s_rstd;
    const int wid = tid >> 5, lane = tid & 31;
    if (lane == 0) { wsum[wid] = s; wsq[wid] = ss; }
    __syncthreads();
    if (tid == 0) {
        float ts = 0.f, tss = 0.f;
        #pragma unroll
        for (int i = 0; i < 8; i++) { ts += wsum[i]; tss += wsq[i]; }
        const float mu  = ts * (1.0f / EDIM);
        const float var = tss * (1.0f / EDIM) - mu * mu;
        s_mu   = mu;
        s_rstd = rsqrtf(var + 1e-5f);
    }
    __syncthreads();
    const float mu = s_mu, rstd = s_rstd;

    const float4 gv = reinterpret_cast<const float4*>(g)[tid];
    const float4 bv = reinterpret_cast<const float4*>(b)[tid];
    float4 o;
    o.x = (v.x - mu) * rstd * gv.x + bv.x;
    o.y = (v.y - mu) * rstd * gv.y + bv.y;
    o.z = (v.z - mu) * rstd * gv.z + bv.z;
    o.w = (v.w - mu) * rstd * gv.w + bv.w;
    reinterpret_cast<float4*>(y + (size_t)row * EDIM)[tid] = o;
}

// ---------------------------------------------------------------------------
// SGEMM: C[M,N] = A[M,K] @ W[K,N] + bias, fused epilogue.
// 128x128 block, K-tile 8, 8x8 per thread, 256 threads.
// OP: 0 = bias only, 1 = bias + residual, 2 = bias + exact GELU
// ---------------------------------------------------------------------------
template <int OP>
__global__ __launch_bounds__(256) void sgemm_kernel(
    const float* __restrict__ A, const float* __restrict__ W,
    const float* __restrict__ bias, const float* __restrict__ res,
    float* __restrict__ C, int M, int N, int K)
{
    __shared__ float As[8][128];
    __shared__ float Bs[8][128];

    const int tid = threadIdx.x;
    const int tx = tid & 15, ty = tid >> 4;
    const int row0 = blockIdx.y * 128;
    const int col0 = blockIdx.x * 128;

    const int arow = tid >> 1;            // 0..127
    const int acol = (tid & 1) * 4;       // 0,4
    const int brow = tid >> 5;            // 0..7
    const int bcol = (tid & 31) * 4;      // 0..124

    float acc[8][8];
    #pragma unroll
    for (int i = 0; i < 8; i++)
        #pragma unroll
        for (int j = 0; j < 8; j++) acc[i][j] = 0.f;

    const float* Ap = A + (size_t)(row0 + arow) * K + acol;
    const float* Wp = W + (size_t)brow * N + col0 + bcol;

    for (int k0 = 0; k0 < K; k0 += 8) {
        const float4 a4 = *reinterpret_cast<const float4*>(Ap + k0);
        const float4 b4 = *reinterpret_cast<const float4*>(Wp + (size_t)k0 * N);
        As[acol + 0][arow] = a4.x;
        As[acol + 1][arow] = a4.y;
        As[acol + 2][arow] = a4.z;
        As[acol + 3][arow] = a4.w;
        *reinterpret_cast<float4*>(&Bs[brow][bcol]) = b4;
        __syncthreads();

        #pragma unroll
        for (int kk = 0; kk < 8; kk++) {
            float af[8], bf[8];
            #pragma unroll
            for (int i = 0; i < 8; i++) af[i] = As[kk][ty * 8 + i];
            #pragma unroll
            for (int j = 0; j < 8; j++) bf[j] = Bs[kk][tx * 8 + j];
            #pragma unroll
            for (int i = 0; i < 8; i++)
                #pragma unroll
                for (int j = 0; j < 8; j++)
                    acc[i][j] = fmaf(af[i], bf[j], acc[i][j]);
        }
        __syncthreads();
    }

    float bvv[8];
    #pragma unroll
    for (int j = 0; j < 8; j++) bvv[j] = bias[col0 + tx * 8 + j];

    #pragma unroll
    for (int i = 0; i < 8; i++) {
        const size_t r = (size_t)(row0 + ty * 8 + i) * N + col0 + tx * 8;
        #pragma unroll
        for (int j = 0; j < 8; j++) {
            float val = acc[i][j] + bvv[j];
            if (OP == 2) {
                val = 0.5f * val * (1.0f + erff(val * 0.70710678118654752f));
            }
            if (OP == 1) {
                val += res[r + j];
            }
            C[r + j] = val;
        }
    }
}

// ---------------------------------------------------------------------------
// Flash attention (fp32). Block = 128 threads handles one (b,h,qtile of 64).
// Online softmax over 32 k-tiles of 64. Shared: Q/K/V/P tiles, stride 65.
// Layout: q/k/v/ctx stored as [B*S, E] with head cols h*64..h*64+63.
// ---------------------------------------------------------------------------
#define ALD 65
#define ATTN_SMEM (4 * 64 * ALD * (int)sizeof(float))

__global__ __launch_bounds__(128) void attn_kernel(
    const float* __restrict__ Q, const float* __restrict__ K,
    const float* __restrict__ V, float* __restrict__ O)
{
    extern __shared__ float sm[];
    float* Qs = sm;
    float* Ks = Qs + 64 * ALD;
    float* Vs = Ks + 64 * ALD;
    float* Ps = Vs + 64 * ALD;
    __shared__ float s_alpha[64];

    const int tid = threadIdx.x;
    const int tx = tid & 15, ty = tid >> 4;
    const int q0 = blockIdx.x * 64;
    const int h  = blockIdx.y;
    const int b  = blockIdx.z;
    const size_t base = (size_t)b * SDIM * EDIM + (size_t)h * 64;

    // Load Q tile, pre-scaled by 1/sqrt(D)=0.125
    #pragma unroll 4
    for (int i = 0; i < 32; i++) {
        const int idx = i * 128 + tid;
        const int r = idx >> 6, c = idx & 63;
        Qs[r * ALD + c] = Q[base + (size_t)(q0 + r) * EDIM + c] * 0.125f;
    }

    float o[8][4];
    #pragma unroll
    for (int i = 0; i < 8; i++)
        #pragma unroll
        for (int j = 0; j < 4; j++) o[i][j] = 0.f;
    float m_i = -1e30f, l_i = 0.f;   // valid on tid<64

    __syncthreads();

    for (int kt = 0; kt < 32; kt++) {
        const int k0 = kt * 64;
        #pragma unroll 4
        for (int i = 0; i < 32; i++) {
            const int idx = i * 128 + tid;
            const int r = idx >> 6, c = idx & 63;
            const size_t g = base + (size_t)(k0 + r) * EDIM + c;
            Ks[r * ALD + c] = K[g];
            Vs[r * ALD + c] = V[g];
        }
        __syncthreads();

        // S = Qs @ KsT  (64x64), each thread 8x4
        float s[8][4];
        #pragma unroll
        for (int i = 0; i < 8; i++)
            #pragma unroll
            for (int j = 0; j < 4; j++) s[i][j] = 0.f;
        #pragma unroll 4
        for (int d = 0; d < 64; d++) {
            float qv[8], kv[4];
            #pragma unroll
            for (int i = 0; i < 8; i++) qv[i] = Qs[(ty * 8 + i) * ALD + d];
            #pragma unroll
            for (int j = 0; j < 4; j++) kv[j] = Ks[(tx * 4 + j) * ALD + d];
            #pragma unroll
            for (int i = 0; i < 8; i++)
                #pragma unroll
                for (int j = 0; j < 4; j++)
                    s[i][j] = fmaf(qv[i], kv[j], s[i][j]);
        }
        #pragma unroll
        for (int i = 0; i < 8; i++)
            #pragma unroll
            for (int j = 0; j < 4; j++)
                Ps[(ty * 8 + i) * ALD + tx * 4 + j] = s[i][j];
        __syncthreads();

        // Online softmax: thread r<64 owns row r
        if (tid < 64) {
            const int r = tid;
            float mx = -1e30f;
            #pragma unroll 8
            for (int c = 0; c < 64; c++) mx = fmaxf(mx, Ps[r * ALD + c]);
            const float mnew  = fmaxf(m_i, mx);
            const float alpha = __expf(m_i - mnew);
            float sum = 0.f;
            #pragma unroll 8
            for (int c = 0; c < 64; c++) {
                const float p = __expf(Ps[r * ALD + c] - mnew);
                Ps[r * ALD + c] = p;
                sum += p;
            }
            l_i = l_i * alpha + sum;
            m_i = mnew;
            s_alpha[r] = alpha;
        }
        __syncthreads();

        // O = O*alpha + P @ V
        float al[8];
        #pragma unroll
        for (int i = 0; i < 8; i++) al[i] = s_alpha[ty * 8 + i];
        #pragma unroll
        for (int i = 0; i < 8; i++)
            #pragma unroll
            for (int j = 0; j < 4; j++) o[i][j] *= al[i];
        #pragma unroll 4
        for (int k = 0; k < 64; k++) {
            float pv[8], vv[4];
            #pragma unroll
            for (int i = 0; i < 8; i++) pv[i] = Ps[(ty * 8 + i) * ALD + k];
            #pragma unroll
            for (int j = 0; j < 4; j++) vv[j] = Vs[k * ALD + tx * 4 + j];
            #pragma unroll
            for (int i = 0; i < 8; i++)
                #pragma unroll
                for (int j = 0; j < 4; j++)
                    o[i][j] = fmaf(pv[i], vv[j], o[i][j]);
        }
        __syncthreads();
    }

    if (tid < 64) s_alpha[tid] = 1.0f / l_i;
    __syncthreads();

    #pragma unroll
    for (int i = 0; i < 8; i++) {
        const float inv = s_alpha[ty * 8 + i];
        const size_t r = base + (size_t)(q0 + ty * 8 + i) * EDIM + tx * 4;
        #pragma unroll
        for (int j = 0; j < 4; j++)
            O[r + j] = o[i][j] * inv;
    }
}

// ---------------------------------------------------------------------------
// Launch
// ---------------------------------------------------------------------------
extern "C" void kernel_launch(void* const* d_in, const int* in_sizes, int n_in,
                              void* d_out, int out_size)
{
    const float* inp   = (const float*)d_in[0];
    const float* ln1_g = (const float*)d_in[1];
    const float* ln1_b = (const float*)d_in[2];
    const float* Wq    = (const float*)d_in[3];
    const float* bq    = (const float*)d_in[4];
    const float* Wk    = (const float*)d_in[5];
    const float* bk    = (const float*)d_in[6];
    const float* Wv    = (const float*)d_in[7];
    const float* bv    = (const float*)d_in[8];
    const float* Wo    = (const float*)d_in[9];
    const float* bo    = (const float*)d_in[10];
    const float* ln2_g = (const float*)d_in[11];
    const float* ln2_b = (const float*)d_in[12];
    const float* W1    = (const float*)d_in[13];
    const float* b1    = (const float*)d_in[14];
    const float* W2    = (const float*)d_in[15];
    const float* b2    = (const float*)d_in[16];
    float* out = (float*)d_out;

    float *xln1, *q, *k, *v, *ctx, *x2, *x3, *h1;
    cudaGetSymbolAddress((void**)&xln1, g_xln1);
    cudaGetSymbolAddress((void**)&q,    g_q);
    cudaGetSymbolAddress((void**)&k,    g_k);
    cudaGetSymbolAddress((void**)&v,    g_v);
    cudaGetSymbolAddress((void**)&ctx,  g_ctx);
    cudaGetSymbolAddress((void**)&x2,   g_x2);
    cudaGetSymbolAddress((void**)&x3,   g_x3);
    cudaGetSymbolAddress((void**)&h1,   g_h1);

    cudaFuncSetAttribute(attn_kernel,
                         cudaFuncAttributeMaxDynamicSharedMemorySize, ATTN_SMEM);

    // 1. LN1
    ln_kernel<<<MDIM, 256>>>(inp, ln1_g, ln1_b, xln1);

    // 2. QKV projections
    dim3 gE(EDIM / 128, MDIM / 128);
    sgemm_kernel<0><<<gE, 256>>>(xln1, Wq, bq, nullptr, q, MDIM, EDIM, EDIM);
    sgemm_kernel<0><<<gE, 256>>>(xln1, Wk, bk, nullptr, k, MDIM, EDIM, EDIM);
    sgemm_kernel<0><<<gE, 256>>>(xln1, Wv, bv, nullptr, v, MDIM, EDIM, EDIM);

    // 3. Attention
    dim3 gA(SDIM / 64, HDIM, BDIM);
    attn_kernel<<<gA, 128, ATTN_SMEM>>>(q, k, v, ctx);

    // 4. O-proj + residual (residual from LN1 output, matching reference)
    sgemm_kernel<1><<<gE, 256>>>(ctx, Wo, bo, xln1, x2, MDIM, EDIM, EDIM);

    // 5. LN2
    ln_kernel<<<MDIM, 256>>>(x2, ln2_g, ln2_b, x3);

    // 6. MLP
    dim3 gF(FDIM / 128, MDIM / 128);
    sgemm_kernel<2><<<gF, 256>>>(x3, W1, b1, nullptr, h1, MDIM, FDIM, EDIM);
    sgemm_kernel<1><<<gE, 256>>>(h1, W2, b2, x3, out, MDIM, EDIM, FDIM);
}

// round 3
// speedup vs baseline: 2.1364x; 2.1364x over previous
#include <cuda_runtime.h>
#include <math.h>
#include <stdint.h>

// ---------------------------------------------------------------------------
// TransformerBlock B=4,S=2048,E=1024,H=16,D=64.
// GEMMs + attention matmuls on mma.sync.m16n8k8 tf32 (sm_100 baseline ISA).
// ---------------------------------------------------------------------------

#define MDIM 8192
#define EDIM 1024
#define SDIM 2048
#define BDIM 4
#define HDIM 16
#define FDIM 2048

// Scratch (allocation-free rule: __device__ globals)
__device__ float g_xln1r[MDIM * EDIM];   // tf32-rounded (GEMM input)
__device__ float g_xln1f[MDIM * EDIM];   // full fp32 (residual)
__device__ float g_q  [MDIM * EDIM];
__device__ float g_k  [MDIM * EDIM];
__device__ float g_v  [MDIM * EDIM];
__device__ float g_ctx[MDIM * EDIM];
__device__ float g_x2 [MDIM * EDIM];
__device__ float g_x3r[MDIM * EDIM];
__device__ float g_x3f[MDIM * EDIM];
__device__ float g_h1 [MDIM * FDIM];
__device__ float g_wtq[EDIM * EDIM];
__device__ float g_wtk[EDIM * EDIM];
__device__ float g_wtv[EDIM * EDIM];
__device__ float g_wto[EDIM * EDIM];
__device__ float g_wt1[FDIM * EDIM];     // [N=2048][K=1024]
__device__ float g_wt2[EDIM * FDIM];     // [N=1024][K=2048]

// ---------------------------------------------------------------------------
// Helpers
// ---------------------------------------------------------------------------
__device__ __forceinline__ uint32_t smem_u32(const void* p) {
    uint32_t a;
    asm("{ .reg .u64 t; cvta.to.shared.u64 t, %1; cvt.u32.u64 %0, t; }"
        : "=r"(a) : "l"(p));
    return a;
}
__device__ __forceinline__ float tf32r(float v) {
    uint32_t r;
    asm("cvt.rna.tf32.f32 %0, %1;" : "=r"(r) : "f"(v));
    return __uint_as_float(r);
}
__device__ __forceinline__ void cpa16(uint32_t s, const void* g) {
    asm volatile("cp.async.cg.shared.global [%0], [%1], 16;" :: "r"(s), "l"(g));
}
#define CP_COMMIT() asm volatile("cp.async.commit_group;" ::: "memory")
#define CP_WAIT1()  asm volatile("cp.async.wait_group 1;" ::: "memory")

__device__ __forceinline__ void mma8(float* c, const uint32_t* a,
                                     uint32_t b0, uint32_t b1) {
    asm volatile(
        "mma.sync.aligned.m16n8k8.row.col.f32.tf32.tf32.f32 "
        "{%0,%1,%2,%3}, {%4,%5,%6,%7}, {%8,%9}, {%0,%1,%2,%3};"
        : "+f"(c[0]), "+f"(c[1]), "+f"(c[2]), "+f"(c[3])
        : "r"(a[0]), "r"(a[1]), "r"(a[2]), "r"(a[3]), "r"(b0), "r"(b1));
}

// ---------------------------------------------------------------------------
// Weight transpose + tf32 rounding: WT[n*K+k] = round(W[k*N+n])
// ---------------------------------------------------------------------------
__global__ __launch_bounds__(256) void transpose_round(
    const float* __restrict__ W, float* __restrict__ WT, int K, int N)
{
    __shared__ float t[32][33];
    const int n0 = blockIdx.x * 32, k0 = blockIdx.y * 32;
    const int x = threadIdx.x & 31, y = threadIdx.x >> 5;
    #pragma unroll
    for (int i = 0; i < 32; i += 8)
        t[y + i][x] = W[(size_t)(k0 + y + i) * N + n0 + x];
    __syncthreads();
    #pragma unroll
    for (int i = 0; i < 32; i += 8)
        WT[(size_t)(n0 + y + i) * K + k0 + x] = tf32r(t[x][y + i]);
}

// ---------------------------------------------------------------------------
// LayerNorm: writes tf32-rounded copy (yr) and full copy (yf)
// ---------------------------------------------------------------------------
__global__ __launch_bounds__(256) void ln_kernel(
    const float* __restrict__ x, const float* __restrict__ g,
    const float* __restrict__ b, float* __restrict__ yr, float* __restrict__ yf)
{
    const int row = blockIdx.x;
    const int tid = threadIdx.x;
    const float4 v = reinterpret_cast<const float4*>(x + (size_t)row * EDIM)[tid];

    float s  = v.x + v.y + v.z + v.w;
    float ss = v.x * v.x + v.y * v.y + v.z * v.z + v.w * v.w;
    #pragma unroll
    for (int off = 16; off > 0; off >>= 1) {
        s  += __shfl_down_sync(0xffffffffu, s,  off);
        ss += __shfl_down_sync(0xffffffffu, ss, off);
    }
    __shared__ float wsum[8], wsq[8];
    __shared__ float s_mu, s_rstd;
    const int wid = tid >> 5, lane = tid & 31;
    if (lane == 0) { wsum[wid] = s; wsq[wid] = ss; }
    __syncthreads();
    if (tid == 0) {
        float ts = 0.f, tss = 0.f;
        #pragma unroll
        for (int i = 0; i < 8; i++) { ts += wsum[i]; tss += wsq[i]; }
        const float mu  = ts * (1.0f / EDIM);
        const float var = tss * (1.0f / EDIM) - mu * mu;
        s_mu = mu; s_rstd = rsqrtf(var + 1e-5f);
    }
    __syncthreads();
    const float mu = s_mu, rstd = s_rstd;
    const float4 gv = reinterpret_cast<const float4*>(g)[tid];
    const float4 bv = reinterpret_cast<const float4*>(b)[tid];
    float4 o;
    o.x = (v.x - mu) * rstd * gv.x + bv.x;
    o.y = (v.y - mu) * rstd * gv.y + bv.y;
    o.z = (v.z - mu) * rstd * gv.z + bv.z;
    o.w = (v.w - mu) * rstd * gv.w + bv.w;
    reinterpret_cast<float4*>(yf + (size_t)row * EDIM)[tid] = o;
    float4 orr;
    orr.x = tf32r(o.x); orr.y = tf32r(o.y);
    orr.z = tf32r(o.z); orr.w = tf32r(o.w);
    reinterpret_cast<float4*>(yr + (size_t)row * EDIM)[tid] = orr;
}

// ---------------------------------------------------------------------------
// tf32 mma.sync GEMM: C[M,N] = A[M,K] @ Bt[N,K]^T + bias (+epilogue)
// 128x128 tile, 256 threads (8 warps, warp tile 64x32), KCH=32, 3 stages.
// OP: 0 = bias; 1 = bias + residual; 2 = bias + exact GELU (tf32-rounded)
// ---------------------------------------------------------------------------
#define KCH 32
#define AST 36                        // floats per smem row (32 + 4 pad)
#define STG_FL (2 * 128 * AST)        // floats per stage (A then B)
#define GEMM_SMEM (3 * STG_FL * (int)sizeof(float))

template <int OP>
__global__ __launch_bounds__(256) void mm_gemm(
    const float* __restrict__ A, const float* __restrict__ Bt,
    const float* __restrict__ bias, const float* __restrict__ res,
    float* __restrict__ C, int M, int N, int K)
{
    extern __shared__ float sm[];
    const int tid = threadIdx.x;
    const int wid = tid >> 5, lane = tid & 31;
    const int row0 = blockIdx.y * 128, col0 = blockIdx.x * 128;

    // copy mapping: thread -> A row (tid>>1), 4 x 16B segments
    const int crow = tid >> 1;
    const int cseg = (tid & 1) * 4;
    const float* gA = A  + (size_t)(row0 + crow) * K + cseg * 4;
    const float* gB = Bt + (size_t)(col0 + crow) * K + cseg * 4;
    const uint32_t sm0 = smem_u32(sm);
    const uint32_t dstA = sm0 + (uint32_t)(crow * AST + cseg * 4) * 4u;
    const uint32_t dstB = dstA + (uint32_t)(128 * AST) * 4u;

    const int nch = K >> 5;

    // prologue: chunks 0,1
    #pragma unroll
    for (int c = 0; c < 2; c++) {
        const uint32_t so = (uint32_t)(c * STG_FL) * 4u;
        #pragma unroll
        for (int u = 0; u < 4; u++) {
            cpa16(dstA + so + u * 16u, gA + c * KCH + u * 4);
            cpa16(dstB + so + u * 16u, gB + c * KCH + u * 4);
        }
        CP_COMMIT();
    }

    // warp tile position
    const int wm = wid & 1, wn = wid >> 1;
    const int lr = lane >> 2, lk = lane & 3;
    const int aoff = (wm * 64 + lr) * AST + lk;
    const int boff = (wn * 32 + lr) * AST + lk;

    float acc[4][4][4];
    #pragma unroll
    for (int mt = 0; mt < 4; mt++)
        #pragma unroll
        for (int nt = 0; nt < 4; nt++)
            #pragma unroll
            for (int r = 0; r < 4; r++) acc[mt][nt][r] = 0.f;

    for (int i = 0; i < nch; i++) {
        CP_WAIT1();
        __syncthreads();
        const int j = i + 2;
        if (j < nch) {
            const uint32_t so = (uint32_t)((j % 3) * STG_FL) * 4u;
            #pragma unroll
            for (int u = 0; u < 4; u++) {
                cpa16(dstA + so + u * 16u, gA + j * KCH + u * 4);
                cpa16(dstB + so + u * 16u, gB + j * KCH + u * 4);
            }
        }
        CP_COMMIT();

        const float* sA = sm + (i % 3) * STG_FL;
        const float* sB = sA + 128 * AST;
        const uint32_t* uA = reinterpret_cast<const uint32_t*>(sA + aoff);
        const uint32_t* uB = reinterpret_cast<const uint32_t*>(sB + boff);

        #pragma unroll
        for (int ks = 0; ks < 4; ks++) {
            uint32_t a[4][4];
            #pragma unroll
            for (int mt = 0; mt < 4; mt++) {
                const uint32_t* p = uA + mt * (16 * AST) + ks * 8;
                a[mt][0] = p[0];
                a[mt][1] = p[8 * AST];
                a[mt][2] = p[4];
                a[mt][3] = p[8 * AST + 4];
            }
            #pragma unroll
            for (int nt = 0; nt < 4; nt++) {
                const uint32_t* p = uB + nt * (8 * AST) + ks * 8;
                const uint32_t b0 = p[0], b1 = p[4];
                #pragma unroll
                for (int mt = 0; mt < 4; mt++)
                    mma8(acc[mt][nt], a[mt], b0, b1);
            }
        }
    }

    // epilogue
    const int lc = 2 * (lane & 3);
    #pragma unroll
    for (int nt = 0; nt < 4; nt++) {
        const int col = col0 + wn * 32 + nt * 8 + lc;
        const float bx = bias[col], by = bias[col + 1];
        #pragma unroll
        for (int mt = 0; mt < 4; mt++) {
            const int row = row0 + wm * 64 + mt * 16 + lr;
            #pragma unroll
            for (int h = 0; h < 2; h++) {
                const int r = row + h * 8;
                float vx = acc[mt][nt][2 * h + 0] + bx;
                float vy = acc[mt][nt][2 * h + 1] + by;
                if (OP == 2) {
                    vx = tf32r(0.5f * vx * (1.0f + erff(vx * 0.70710678118654752f)));
                    vy = tf32r(0.5f * vy * (1.0f + erff(vy * 0.70710678118654752f)));
                }
                if (OP == 1) {
                    const float* rp = res + (size_t)r * N + col;
                    vx += rp[0]; vy += rp[1];
                }
                float2 v2 = make_float2(vx, vy);
                *reinterpret_cast<float2*>(C + (size_t)r * N + col) = v2;
            }
        }
    }
}

// ---------------------------------------------------------------------------
// Flash attention with tf32 mma.sync. 128 threads / (b,h,64-row q tile).
// Qs/Ks/Vst stride 68 (conflict-free frag loads), Ps stride 65 (softmax).
// ---------------------------------------------------------------------------
#define QLD 68
#define PLD 65
#define ATTN_SMEM ((3 * 64 * QLD + 64 * PLD) * (int)sizeof(float))

__global__ __launch_bounds__(128) void attn_kernel(
    const float* __restrict__ Q, const float* __restrict__ K,
    const float* __restrict__ V, float* __restrict__ O)
{
    extern __shared__ float smf[];
    float* Qs  = smf;
    float* Ks  = Qs + 64 * QLD;
    float* Vst = Ks + 64 * QLD;
    float* Ps  = Vst + 64 * QLD;
    __shared__ float s_alpha[64];

    const int tid = threadIdx.x;
    const int w = tid >> 5, lane = tid & 31;
    const int lr = lane >> 2, lk = lane & 3;
    const int qr = w * 16 + lr;
    const int q0 = blockIdx.x * 64;
    const int h  = blockIdx.y;
    const int b  = blockIdx.z;
    const size_t base = (size_t)b * SDIM * EDIM + (size_t)h * 64;

    // Q tile (scaled by 1/8, tf32-rounded)
    #pragma unroll 4
    for (int i = 0; i < 32; i++) {
        const int idx = i * 128 + tid;
        const int r = idx >> 6, c = idx & 63;
        Qs[r * QLD + c] = tf32r(Q[base + (size_t)(q0 + r) * EDIM + c] * 0.125f);
    }

    float oacc[8][4];
    #pragma unroll
    for (int nt = 0; nt < 8; nt++)
        #pragma unroll
        for (int r = 0; r < 4; r++) oacc[nt][r] = 0.f;
    float m_i = -1e30f, l_i = 0.f;   // valid on tid<64

    for (int kt = 0; kt < 32; kt++) {
        const int k0 = kt * 64;
        #pragma unroll 4
        for (int i = 0; i < 32; i++) {
            const int idx = i * 128 + tid;
            const int r = idx >> 6, c = idx & 63;
            const size_t g = base + (size_t)(k0 + r) * EDIM + c;
            Ks[r * QLD + c]  = tf32r(K[g]);
            Vst[c * QLD + r] = tf32r(V[g]);
        }
        __syncthreads();

        // S = Q @ K^T  (warp w: rows w*16..w*16+15)
        float sacc[8][4];
        #pragma unroll
        for (int nt = 0; nt < 8; nt++)
            #pragma unroll
            for (int r = 0; r < 4; r++) sacc[nt][r] = 0.f;

        const uint32_t* uQ = reinterpret_cast<const uint32_t*>(Qs + qr * QLD + lk);
        const uint32_t* uK = reinterpret_cast<const uint32_t*>(Ks + lr * QLD + lk);
        #pragma unroll
        for (int ks = 0; ks < 8; ks++) {
            uint32_t a[4];
            a[0] = uQ[ks * 8];
            a[1] = uQ[8 * QLD + ks * 8];
            a[2] = uQ[ks * 8 + 4];
            a[3] = uQ[8 * QLD + ks * 8 + 4];
            #pragma unroll
            for (int nt = 0; nt < 8; nt++) {
                const uint32_t* p = uK + nt * (8 * QLD) + ks * 8;
                mma8(sacc[nt], a, p[0], p[4]);
            }
        }
        // scatter S to Ps
        const int pc = 2 * lk;
        #pragma unroll
        for (int nt = 0; nt < 8; nt++) {
            const int c = nt * 8 + pc;
            Ps[qr * PLD + c]           = sacc[nt][0];
            Ps[qr * PLD + c + 1]       = sacc[nt][1];
            Ps[(qr + 8) * PLD + c]     = sacc[nt][2];
            Ps[(qr + 8) * PLD + c + 1] = sacc[nt][3];
        }
        __syncthreads();

        // online softmax: thread r<64 owns row r
        if (tid < 64) {
            const int r = tid;
            float mx = -1e30f;
            #pragma unroll 8
            for (int c = 0; c < 64; c++) mx = fmaxf(mx, Ps[r * PLD + c]);
            const float mnew  = fmaxf(m_i, mx);
            const float alpha = __expf(m_i - mnew);
            float sum = 0.f;
            #pragma unroll 8
            for (int c = 0; c < 64; c++) {
                const float p = __expf(Ps[r * PLD + c] - mnew);
                Ps[r * PLD + c] = p;
                sum += p;
            }
            l_i = l_i * alpha + sum;
            m_i = mnew;
            s_alpha[r] = alpha;
        }
        __syncthreads();

        // O = O*alpha + P @ V
        const float al0 = s_alpha[qr], al1 = s_alpha[qr + 8];
        #pragma unroll
        for (int nt = 0; nt < 8; nt++) {
            oacc[nt][0] *= al0; oacc[nt][1] *= al0;
            oacc[nt][2] *= al1; oacc[nt][3] *= al1;
        }
        const uint32_t* uP = reinterpret_cast<const uint32_t*>(Ps + qr * PLD + lk);
        const uint32_t* uV = reinterpret_cast<const uint32_t*>(Vst + lr * QLD + lk);
        #pragma unroll
        for (int ks = 0; ks < 8; ks++) {
            uint32_t a[4];
            a[0] = uP[ks * 8];
            a[1] = uP[8 * PLD + ks * 8];
            a[2] = uP[ks * 8 + 4];
            a[3] = uP[8 * PLD + ks * 8 + 4];
            #pragma unroll
            for (int nt = 0; nt < 8; nt++) {
                const uint32_t* p = uV + nt * (8 * QLD) + ks * 8;
                mma8(oacc[nt], a, p[0], p[4]);
            }
        }
        __syncthreads();
    }

    if (tid < 64) s_alpha[tid] = 1.0f / l_i;
    __syncthreads();

    const float inv0 = s_alpha[qr], inv1 = s_alpha[qr + 8];
    const int pc = 2 * lk;
    #pragma unroll
    for (int nt = 0; nt < 8; nt++) {
        const int c = nt * 8 + pc;
        float* p0 = O + base + (size_t)(q0 + qr) * EDIM + c;
        float* p1 = O + base + (size_t)(q0 + qr + 8) * EDIM + c;
        p0[0] = tf32r(oacc[nt][0] * inv0);
        p0[1] = tf32r(oacc[nt][1] * inv0);
        p1[0] = tf32r(oacc[nt][2] * inv1);
        p1[1] = tf32r(oacc[nt][3] * inv1);
    }
}

// ---------------------------------------------------------------------------
// Launch
// ---------------------------------------------------------------------------
extern "C" void kernel_launch(void* const* d_in, const int* in_sizes, int n_in,
                              void* d_out, int out_size)
{
    const float* inp   = (const float*)d_in[0];
    const float* ln1_g = (const float*)d_in[1];
    const float* ln1_b = (const float*)d_in[2];
    const float* Wq    = (const float*)d_in[3];
    const float* bq    = (const float*)d_in[4];
    const float* Wk    = (const float*)d_in[5];
    const float* bk    = (const float*)d_in[6];
    const float* Wv    = (const float*)d_in[7];
    const float* bv    = (const float*)d_in[8];
    const float* Wo    = (const float*)d_in[9];
    const float* bo    = (const float*)d_in[10];
    const float* ln2_g = (const float*)d_in[11];
    const float* ln2_b = (const float*)d_in[12];
    const float* W1    = (const float*)d_in[13];
    const float* b1    = (const float*)d_in[14];
    const float* W2    = (const float*)d_in[15];
    const float* b2    = (const float*)d_in[16];
    float* out = (float*)d_out;

    float *xln1r, *xln1f, *q, *k, *v, *ctx, *x2, *x3r, *x3f, *h1;
    float *wtq, *wtk, *wtv, *wto, *wt1, *wt2;
    cudaGetSymbolAddress((void**)&xln1r, g_xln1r);
    cudaGetSymbolAddress((void**)&xln1f, g_xln1f);
    cudaGetSymbolAddress((void**)&q,    g_q);
    cudaGetSymbolAddress((void**)&k,    g_k);
    cudaGetSymbolAddress((void**)&v,    g_v);
    cudaGetSymbolAddress((void**)&ctx,  g_ctx);
    cudaGetSymbolAddress((void**)&x2,   g_x2);
    cudaGetSymbolAddress((void**)&x3r,  g_x3r);
    cudaGetSymbolAddress((void**)&x3f,  g_x3f);
    cudaGetSymbolAddress((void**)&h1,   g_h1);
    cudaGetSymbolAddress((void**)&wtq,  g_wtq);
    cudaGetSymbolAddress((void**)&wtk,  g_wtk);
    cudaGetSymbolAddress((void**)&wtv,  g_wtv);
    cudaGetSymbolAddress((void**)&wto,  g_wto);
    cudaGetSymbolAddress((void**)&wt1,  g_wt1);
    cudaGetSymbolAddress((void**)&wt2,  g_wt2);

    cudaFuncSetAttribute(attn_kernel,
                         cudaFuncAttributeMaxDynamicSharedMemorySize, ATTN_SMEM);
    cudaFuncSetAttribute(mm_gemm<0>,
                         cudaFuncAttributeMaxDynamicSharedMemorySize, GEMM_SMEM);
    cudaFuncSetAttribute(mm_gemm<1>,
                         cudaFuncAttributeMaxDynamicSharedMemorySize, GEMM_SMEM);
    cudaFuncSetAttribute(mm_gemm<2>,
                         cudaFuncAttributeMaxDynamicSharedMemorySize, GEMM_SMEM);

    // 0. Transpose + tf32-round weights
    transpose_round<<<dim3(EDIM / 32, EDIM / 32), 256>>>(Wq, wtq, EDIM, EDIM);
    transpose_round<<<dim3(EDIM / 32, EDIM / 32), 256>>>(Wk, wtk, EDIM, EDIM);
    transpose_round<<<dim3(EDIM / 32, EDIM / 32), 256>>>(Wv, wtv, EDIM, EDIM);
    transpose_round<<<dim3(EDIM / 32, EDIM / 32), 256>>>(Wo, wto, EDIM, EDIM);
    transpose_round<<<dim3(FDIM / 32, EDIM / 32), 256>>>(W1, wt1, EDIM, FDIM);
    transpose_round<<<dim3(EDIM / 32, FDIM / 32), 256>>>(W2, wt2, FDIM, EDIM);

    // 1. LN1
    ln_kernel<<<MDIM, 256>>>(inp, ln1_g, ln1_b, xln1r, xln1f);

    // 2. QKV projections
    dim3 gE(EDIM / 128, MDIM / 128);
    mm_gemm<0><<<gE, 256, GEMM_SMEM>>>(xln1r, wtq, bq, nullptr, q, MDIM, EDIM, EDIM);
    mm_gemm<0><<<gE, 256, GEMM_SMEM>>>(xln1r, wtk, bk, nullptr, k, MDIM, EDIM, EDIM);
    mm_gemm<0><<<gE, 256, GEMM_SMEM>>>(xln1r, wtv, bv, nullptr, v, MDIM, EDIM, EDIM);

    // 3. Attention (writes tf32-rounded ctx)
    dim3 gA(SDIM / 64, HDIM, BDIM);
    attn_kernel<<<gA, 128, ATTN_SMEM>>>(q, k, v, ctx);

    // 4. O-proj + residual(LN1 full)
    mm_gemm<1><<<gE, 256, GEMM_SMEM>>>(ctx, wto, bo, xln1f, x2, MDIM, EDIM, EDIM);

    // 5. LN2
    ln_kernel<<<MDIM, 256>>>(x2, ln2_g, ln2_b, x3r, x3f);

    // 6. MLP
    dim3 gF(FDIM / 128, MDIM / 128);
    mm_gemm<2><<<gF, 256, GEMM_SMEM>>>(x3r, wt1, b1, nullptr, h1, MDIM, FDIM, EDIM);
    mm_gemm<1><<<gE, 256, GEMM_SMEM>>>(h1, wt2, b2, x3f, out, MDIM, EDIM, FDIM);
}

// round 4
// speedup vs baseline: 2.4430x; 1.1435x over previous
#include <cuda_runtime.h>
#include <math.h>
#include <stdint.h>

// ---------------------------------------------------------------------------
// TransformerBlock B=4,S=2048,E=1024,H=16,D=64 — tf32 mma.sync everywhere.
// R4: GEMM warp tile 64x64 (2x MMA:LDS), attention 128-row Q tile / 8 warps.
// ---------------------------------------------------------------------------

#define MDIM 8192
#define EDIM 1024
#define SDIM 2048
#define BDIM 4
#define HDIM 16
#define FDIM 2048

__device__ float g_xln1r[MDIM * EDIM];
__device__ float g_xln1f[MDIM * EDIM];
__device__ float g_q  [MDIM * EDIM];
__device__ float g_k  [MDIM * EDIM];
__device__ float g_v  [MDIM * EDIM];
__device__ float g_ctx[MDIM * EDIM];
__device__ float g_x2 [MDIM * EDIM];
__device__ float g_x3r[MDIM * EDIM];
__device__ float g_x3f[MDIM * EDIM];
__device__ float g_h1 [MDIM * FDIM];
__device__ float g_wtq[EDIM * EDIM];
__device__ float g_wtk[EDIM * EDIM];
__device__ float g_wtv[EDIM * EDIM];
__device__ float g_wto[EDIM * EDIM];
__device__ float g_wt1[FDIM * EDIM];
__device__ float g_wt2[EDIM * FDIM];

// ---------------------------------------------------------------------------
__device__ __forceinline__ uint32_t smem_u32(const void* p) {
    uint32_t a;
    asm("{ .reg .u64 t; cvta.to.shared.u64 t, %1; cvt.u32.u64 %0, t; }"
        : "=r"(a) : "l"(p));
    return a;
}
__device__ __forceinline__ float tf32r(float v) {
    uint32_t r;
    asm("cvt.rna.tf32.f32 %0, %1;" : "=r"(r) : "f"(v));
    return __uint_as_float(r);
}
__device__ __forceinline__ void cpa16(uint32_t s, const void* g) {
    asm volatile("cp.async.cg.shared.global [%0], [%1], 16;" :: "r"(s), "l"(g));
}
#define CP_COMMIT() asm volatile("cp.async.commit_group;" ::: "memory")
#define CP_WAIT0()  asm volatile("cp.async.wait_group 0;" ::: "memory")
#define CP_WAIT1()  asm volatile("cp.async.wait_group 1;" ::: "memory")

__device__ __forceinline__ void mma8(float* c, const uint32_t* a,
                                     uint32_t b0, uint32_t b1) {
    asm volatile(
        "mma.sync.aligned.m16n8k8.row.col.f32.tf32.tf32.f32 "
        "{%0,%1,%2,%3}, {%4,%5,%6,%7}, {%8,%9}, {%0,%1,%2,%3};"
        : "+f"(c[0]), "+f"(c[1]), "+f"(c[2]), "+f"(c[3])
        : "r"(a[0]), "r"(a[1]), "r"(a[2]), "r"(a[3]), "r"(b0), "r"(b1));
}

// ---------------------------------------------------------------------------
// All 6 weight transposes in ONE launch (keeps ncu -s 5 on attn_kernel).
// WT[n*K+k] = tf32round(W[k*N+n])
// ---------------------------------------------------------------------------
__global__ __launch_bounds__(256) void transpose_all(
    const float* __restrict__ Wq, const float* __restrict__ Wk,
    const float* __restrict__ Wv, const float* __restrict__ Wo,
    const float* __restrict__ W1, const float* __restrict__ W2,
    float* __restrict__ wtq, float* __restrict__ wtk,
    float* __restrict__ wtv, float* __restrict__ wto,
    float* __restrict__ wt1, float* __restrict__ wt2)
{
    const float* W; float* WT; int K, N;
    switch (blockIdx.z) {
        case 0: W = Wq; WT = wtq; K = EDIM; N = EDIM; break;
        case 1: W = Wk; WT = wtk; K = EDIM; N = EDIM; break;
        case 2: W = Wv; WT = wtv; K = EDIM; N = EDIM; break;
        case 3: W = Wo; WT = wto; K = EDIM; N = EDIM; break;
        case 4: W = W1; WT = wt1; K = EDIM; N = FDIM; break;
        default: W = W2; WT = wt2; K = FDIM; N = EDIM; break;
    }
    const int n0 = blockIdx.x * 32, k0 = blockIdx.y * 32;
    if (n0 >= N || k0 >= K) return;
    __shared__ float t[32][33];
    const int x = threadIdx.x & 31, y = threadIdx.x >> 5;
    #pragma unroll
    for (int i = 0; i < 32; i += 8)
        t[y + i][x] = W[(size_t)(k0 + y + i) * N + n0 + x];
    __syncthreads();
    #pragma unroll
    for (int i = 0; i < 32; i += 8)
        WT[(size_t)(n0 + y + i) * K + k0 + x] = tf32r(t[x][y + i]);
}

// ---------------------------------------------------------------------------
// LayerNorm: rounded copy (yr) + full copy (yf)
// ---------------------------------------------------------------------------
__global__ __launch_bounds__(256) void ln_kernel(
    const float* __restrict__ x, const float* __restrict__ g,
    const float* __restrict__ b, float* __restrict__ yr, float* __restrict__ yf)
{
    const int row = blockIdx.x;
    const int tid = threadIdx.x;
    const float4 v = reinterpret_cast<const float4*>(x + (size_t)row * EDIM)[tid];

    float s  = v.x + v.y + v.z + v.w;
    float ss = v.x * v.x + v.y * v.y + v.z * v.z + v.w * v.w;
    #pragma unroll
    for (int off = 16; off > 0; off >>= 1) {
        s  += __shfl_down_sync(0xffffffffu, s,  off);
        ss += __shfl_down_sync(0xffffffffu, ss, off);
    }
    __shared__ float wsum[8], wsq[8];
    __shared__ float s_mu, s_rstd;
    const int wid = tid >> 5, lane = tid & 31;
    if (lane == 0) { wsum[wid] = s; wsq[wid] = ss; }
    __syncthreads();
    if (tid == 0) {
        float ts = 0.f, tss = 0.f;
        #pragma unroll
        for (int i = 0; i < 8; i++) { ts += wsum[i]; tss += wsq[i]; }
        const float mu  = ts * (1.0f / EDIM);
        const float var = tss * (1.0f / EDIM) - mu * mu;
        s_mu = mu; s_rstd = rsqrtf(var + 1e-5f);
    }
    __syncthreads();
    const float mu = s_mu, rstd = s_rstd;
    const float4 gv = reinterpret_cast<const float4*>(g)[tid];
    const float4 bv = reinterpret_cast<const float4*>(b)[tid];
    float4 o;
    o.x = (v.x - mu) * rstd * gv.x + bv.x;
    o.y = (v.y - mu) * rstd * gv.y + bv.y;
    o.z = (v.z - mu) * rstd * gv.z + bv.z;
    o.w = (v.w - mu) * rstd * gv.w + bv.w;
    reinterpret_cast<float4*>(yf + (size_t)row * EDIM)[tid] = o;
    float4 orr;
    orr.x = tf32r(o.x); orr.y = tf32r(o.y);
    orr.z = tf32r(o.z); orr.w = tf32r(o.w);
    reinterpret_cast<float4*>(yr + (size_t)row * EDIM)[tid] = orr;
}

// ---------------------------------------------------------------------------
// tf32 GEMM: C[M,N] = A[M,K] @ Bt[N,K]^T + bias (+epilogue)
// 128x128 CTA tile, 128 threads (4 warps), warp tile 64x64, KCH=32, 3 stages.
// OP: 0 = bias + tf32 round; 1 = bias + residual; 2 = bias + GELU + round
// ---------------------------------------------------------------------------
#define KCH 32
#define AST 36
#define STG_FL (2 * 128 * AST)
#define GEMM_SMEM (3 * STG_FL * (int)sizeof(float))

template <int OP>
__global__ __launch_bounds__(128) void mm_gemm(
    const float* __restrict__ A, const float* __restrict__ Bt,
    const float* __restrict__ bias, const float* __restrict__ res,
    float* __restrict__ C, int M, int N, int K)
{
    extern __shared__ float sm[];
    const int tid = threadIdx.x;
    const int wid = tid >> 5, lane = tid & 31;
    const int row0 = blockIdx.y * 128, col0 = blockIdx.x * 128;

    // copy mapping: thread t handles row t (A) and row t (B), 8 x 16B segs
    const float* gA = A  + (size_t)(row0 + tid) * K;
    const float* gB = Bt + (size_t)(col0 + tid) * K;
    const uint32_t sm0 = smem_u32(sm);
    const uint32_t dA = sm0 + (uint32_t)(tid * AST) * 4u;
    const uint32_t dB = dA + (uint32_t)(128 * AST) * 4u;

    const int nch = K >> 5;

    #pragma unroll
    for (int c = 0; c < 2; c++) {
        const uint32_t so = (uint32_t)(c * STG_FL) * 4u;
        #pragma unroll
        for (int u = 0; u < 8; u++) {
            cpa16(dA + so + u * 16u, gA + c * KCH + u * 4);
            cpa16(dB + so + u * 16u, gB + c * KCH + u * 4);
        }
        CP_COMMIT();
    }

    const int wm = wid & 1, wn = wid >> 1;        // 2x2 warp grid
    const int lr = lane >> 2, lk = lane & 3;
    const int abase = (wm * 64 + lr) * AST + lk;
    const int bbase = (wn * 64 + lr) * AST + lk;

    float acc[4][8][4];
    #pragma unroll
    for (int mt = 0; mt < 4; mt++)
        #pragma unroll
        for (int nt = 0; nt < 8; nt++)
            #pragma unroll
            for (int r = 0; r < 4; r++) acc[mt][nt][r] = 0.f;

    for (int i = 0; i < nch; i++) {
        CP_WAIT1();
        __syncthreads();
        const int j = i + 2;
        if (j < nch) {
            const uint32_t so = (uint32_t)((j % 3) * STG_FL) * 4u;
            #pragma unroll
            for (int u = 0; u < 8; u++) {
                cpa16(dA + so + u * 16u, gA + j * KCH + u * 4);
                cpa16(dB + so + u * 16u, gB + j * KCH + u * 4);
            }
        }
        CP_COMMIT();

        const float* sA = sm + (i % 3) * STG_FL;
        const float* sB = sA + 128 * AST;
        const uint32_t* uA = reinterpret_cast<const uint32_t*>(sA + abase);
        const uint32_t* uB = reinterpret_cast<const uint32_t*>(sB + bbase);

        #pragma unroll
        for (int ks = 0; ks < 4; ks++) {
            uint32_t a[4][4];
            #pragma unroll
            for (int mt = 0; mt < 4; mt++) {
                const uint32_t* p = uA + mt * (16 * AST) + ks * 8;
                a[mt][0] = p[0];
                a[mt][1] = p[8 * AST];
                a[mt][2] = p[4];
                a[mt][3] = p[8 * AST + 4];
            }
            #pragma unroll
            for (int nt = 0; nt < 8; nt++) {
                const uint32_t* p = uB + nt * (8 * AST) + ks * 8;
                const uint32_t b0 = p[0], b1 = p[4];
                #pragma unroll
                for (int mt = 0; mt < 4; mt++)
                    mma8(acc[mt][nt], a[mt], b0, b1);
            }
        }
    }

    const int lc = 2 * lk;
    #pragma unroll
    for (int nt = 0; nt < 8; nt++) {
        const int col = col0 + wn * 64 + nt * 8 + lc;
        const float bx = bias[col], by = bias[col + 1];
        #pragma unroll
        for (int mt = 0; mt < 4; mt++) {
            const int row = row0 + wm * 64 + mt * 16 + lr;
            #pragma unroll
            for (int h = 0; h < 2; h++) {
                const int r = row + h * 8;
                float vx = acc[mt][nt][2 * h + 0] + bx;
                float vy = acc[mt][nt][2 * h + 1] + by;
                if (OP == 2) {
                    vx = tf32r(0.5f * vx * (1.0f + erff(vx * 0.70710678118654752f)));
                    vy = tf32r(0.5f * vy * (1.0f + erff(vy * 0.70710678118654752f)));
                }
                if (OP == 0) { vx = tf32r(vx); vy = tf32r(vy); }
                if (OP == 1) {
                    const float* rp = res + (size_t)r * N + col;
                    vx += rp[0]; vy += rp[1];
                }
                *reinterpret_cast<float2*>(C + (size_t)r * N + col)
                    = make_float2(vx, vy);
            }
        }
    }
}

// ---------------------------------------------------------------------------
// Flash attention, tf32 mma. 256 threads / (b,h,128-row q tile).
// Warp w: rows (w>>1)*32, cols (w&1)*32. kv tile = 64.
// Qs/Ks/Vs stride 68 (conflict-free frags + cp.async), Ps stride 76.
// ---------------------------------------------------------------------------
#define QLD 68
#define PLD 76
#define ATTN_SMEM ((128 * QLD + 64 * QLD + 64 * QLD + 128 * PLD) * (int)sizeof(float))

__global__ __launch_bounds__(256) void attn_kernel(
    const float* __restrict__ Q, const float* __restrict__ K,
    const float* __restrict__ V, float* __restrict__ O)
{
    extern __shared__ float smf[];
    float* Qs = smf;                    // [128][QLD]
    float* Ks = Qs + 128 * QLD;         // [64][QLD]
    float* Vs = Ks + 64 * QLD;          // [64][QLD] row-major (kv, d)
    float* Ps = Vs + 64 * QLD;          // [128][PLD]
    __shared__ float s_alpha[128];

    const int tid = threadIdx.x;
    const int w = tid >> 5, lane = tid & 31;
    const int lr = lane >> 2, lk = lane & 3;
    const int wm = w >> 1, wn = w & 1;
    const int q0 = blockIdx.x * 128;
    const size_t base = (size_t)blockIdx.z * SDIM * EDIM + (size_t)blockIdx.y * 64;

    const uint32_t sQ = smem_u32(Qs), sK = smem_u32(Ks), sV = smem_u32(Vs);

    // Q tile via cp.async (scale applied post-mma)
    #pragma unroll
    for (int u = 0; u < 8; u++) {
        const int idx = u * 256 + tid;
        const int r = idx >> 4, seg = idx & 15;
        cpa16(sQ + (uint32_t)(r * QLD + seg * 4) * 4u,
              Q + base + (size_t)(q0 + r) * EDIM + seg * 4);
    }
    CP_COMMIT();

    float oacc[2][4][4];
    #pragma unroll
    for (int mt = 0; mt < 2; mt++)
        #pragma unroll
        for (int nt = 0; nt < 4; nt++)
            #pragma unroll
            for (int r = 0; r < 4; r++) oacc[mt][nt][r] = 0.f;
    float m_i = -1e30f, l_i = 0.f;      // row tid>>1, replicated x2

    const int srow = tid >> 1;          // softmax row
    const int shalf = (tid & 1) * 32;

    for (int kt = 0; kt < 32; kt++) {
        const int k0 = kt * 64;
        #pragma unroll
        for (int u = 0; u < 4; u++) {
            const int idx = u * 256 + tid;
            const int r = idx >> 4, seg = idx & 15;
            const size_t g = base + (size_t)(k0 + r) * EDIM + seg * 4;
            cpa16(sK + (uint32_t)(r * QLD + seg * 4) * 4u, K + g);
            cpa16(sV + (uint32_t)(r * QLD + seg * 4) * 4u, V + g);
        }
        CP_COMMIT();
        CP_WAIT0();
        __syncthreads();

        // S = Q @ K^T : warp rows wm*32 (mt 0..1), cols wn*32 (nt 0..3)
        float sacc[2][4][4];
        #pragma unroll
        for (int mt = 0; mt < 2; mt++)
            #pragma unroll
            for (int nt = 0; nt < 4; nt++)
                #pragma unroll
                for (int r = 0; r < 4; r++) sacc[mt][nt][r] = 0.f;

        #pragma unroll
        for (int ks = 0; ks < 8; ks++) {
            uint32_t a[2][4];
            #pragma unroll
            for (int mt = 0; mt < 2; mt++) {
                const uint32_t* p = reinterpret_cast<const uint32_t*>(
                    Qs + (wm * 32 + mt * 16 + lr) * QLD + ks * 8 + lk);
                a[mt][0] = p[0];
                a[mt][1] = p[8 * QLD];
                a[mt][2] = p[4];
                a[mt][3] = p[8 * QLD + 4];
            }
            #pragma unroll
            for (int nt = 0; nt < 4; nt++) {
                const uint32_t* p = reinterpret_cast<const uint32_t*>(
                    Ks + (wn * 32 + nt * 8 + lr) * QLD + ks * 8 + lk);
                const uint32_t b0 = p[0], b1 = p[4];
                #pragma unroll
                for (int mt = 0; mt < 2; mt++)
                    mma8(sacc[mt][nt], a[mt], b0, b1);
            }
        }
        // scale + scatter to Ps
        #pragma unroll
        for (int mt = 0; mt < 2; mt++) {
            const int r0 = wm * 32 + mt * 16 + lr;
            #pragma unroll
            for (int nt = 0; nt < 4; nt++) {
                const int c = wn * 32 + nt * 8 + 2 * lk;
                *reinterpret_cast<float2*>(Ps + r0 * PLD + c)
                    = make_float2(sacc[mt][nt][0] * 0.125f, sacc[mt][nt][1] * 0.125f);
                *reinterpret_cast<float2*>(Ps + (r0 + 8) * PLD + c)
                    = make_float2(sacc[mt][nt][2] * 0.125f, sacc[mt][nt][3] * 0.125f);
            }
        }
        __syncthreads();

        // online softmax: 2 threads per row
        {
            float* pr = Ps + srow * PLD + shalf;
            float mx = -1e30f;
            #pragma unroll 8
            for (int c = 0; c < 32; c++) mx = fmaxf(mx, pr[c]);
            mx = fmaxf(mx, __shfl_xor_sync(0xffffffffu, mx, 1));
            const float mnew  = fmaxf(m_i, mx);
            const float alpha = __expf(m_i - mnew);
            float sum = 0.f;
            #pragma unroll 8
            for (int c = 0; c < 32; c++) {
                const float p = __expf(pr[c] - mnew);
                pr[c] = p;
                sum += p;
            }
            sum += __shfl_xor_sync(0xffffffffu, sum, 1);
            l_i = l_i * alpha + sum;
            m_i = mnew;
            s_alpha[srow] = alpha;
        }
        __syncthreads();

        // O = O*alpha + P @ V
        #pragma unroll
        for (int mt = 0; mt < 2; mt++) {
            const int r0 = wm * 32 + mt * 16 + lr;
            const float al0 = s_alpha[r0], al1 = s_alpha[r0 + 8];
            #pragma unroll
            for (int nt = 0; nt < 4; nt++) {
                oacc[mt][nt][0] *= al0; oacc[mt][nt][1] *= al0;
                oacc[mt][nt][2] *= al1; oacc[mt][nt][3] *= al1;
            }
        }
        #pragma unroll
        for (int ks = 0; ks < 8; ks++) {
            uint32_t a[2][4];
            #pragma unroll
            for (int mt = 0; mt < 2; mt++) {
                const uint32_t* p = reinterpret_cast<const uint32_t*>(
                    Ps + (wm * 32 + mt * 16 + lr) * PLD + ks * 8 + lk);
                a[mt][0] = p[0];
                a[mt][1] = p[8 * PLD];
                a[mt][2] = p[4];
                a[mt][3] = p[8 * PLD + 4];
            }
            #pragma unroll
            for (int nt = 0; nt < 4; nt++) {
                // V row-major [kv][d]: b0=(k=lk,n=lr), b1=(k=lk+4,n=lr)
                const uint32_t b0 = *reinterpret_cast<const uint32_t*>(
                    Vs + (ks * 8 + lk) * QLD + wn * 32 + nt * 8 + lr);
                const uint32_t b1 = *reinterpret_cast<const uint32_t*>(
                    Vs + (ks * 8 + lk + 4) * QLD + wn * 32 + nt * 8 + lr);
                #pragma unroll
                for (int mt = 0; mt < 2; mt++)
                    mma8(oacc[mt][nt], a[mt], b0, b1);
            }
        }
        __syncthreads();   // before next tile overwrites Ks/Vs/Ps
    }

    s_alpha[srow] = 1.0f / l_i;
    __syncthreads();

    #pragma unroll
    for (int mt = 0; mt < 2; mt++) {
        const int r0 = wm * 32 + mt * 16 + lr;
        const float inv0 = s_alpha[r0], inv1 = s_alpha[r0 + 8];
        #pragma unroll
        for (int nt = 0; nt < 4; nt++) {
            const int c = wn * 32 + nt * 8 + 2 * lk;
            float* p0 = O + base + (size_t)(q0 + r0) * EDIM + c;
            float* p1 = O + base + (size_t)(q0 + r0 + 8) * EDIM + c;
            *reinterpret_cast<float2*>(p0) = make_float2(
                tf32r(oacc[mt][nt][0] * inv0), tf32r(oacc[mt][nt][1] * inv0));
            *reinterpret_cast<float2*>(p1) = make_float2(
                tf32r(oacc[mt][nt][2] * inv1), tf32r(oacc[mt][nt][3] * inv1));
        }
    }
}

// ---------------------------------------------------------------------------
extern "C" void kernel_launch(void* const* d_in, const int* in_sizes, int n_in,
                              void* d_out, int out_size)
{
    const float* inp   = (const float*)d_in[0];
    const float* ln1_g = (const float*)d_in[1];
    const float* ln1_b = (const float*)d_in[2];
    const float* Wq    = (const float*)d_in[3];
    const float* bq    = (const float*)d_in[4];
    const float* Wk    = (const float*)d_in[5];
    const float* bk    = (const float*)d_in[6];
    const float* Wv    = (const float*)d_in[7];
    const float* bv    = (const float*)d_in[8];
    const float* Wo    = (const float*)d_in[9];
    const float* bo    = (const float*)d_in[10];
    const float* ln2_g = (const float*)d_in[11];
    const float* ln2_b = (const float*)d_in[12];
    const float* W1    = (const float*)d_in[13];
    const float* b1    = (const float*)d_in[14];
    const float* W2    = (const float*)d_in[15];
    const float* b2    = (const float*)d_in[16];
    float* out = (float*)d_out;

    float *xln1r, *xln1f, *q, *k, *v, *ctx, *x2, *x3r, *x3f, *h1;
    float *wtq, *wtk, *wtv, *wto, *wt1, *wt2;
    cudaGetSymbolAddress((void**)&xln1r, g_xln1r);
    cudaGetSymbolAddress((void**)&xln1f, g_xln1f);
    cudaGetSymbolAddress((void**)&q,    g_q);
    cudaGetSymbolAddress((void**)&k,    g_k);
    cudaGetSymbolAddress((void**)&v,    g_v);
    cudaGetSymbolAddress((void**)&ctx,  g_ctx);
    cudaGetSymbolAddress((void**)&x2,   g_x2);
    cudaGetSymbolAddress((void**)&x3r,  g_x3r);
    cudaGetSymbolAddress((void**)&x3f,  g_x3f);
    cudaGetSymbolAddress((void**)&h1,   g_h1);
    cudaGetSymbolAddress((void**)&wtq,  g_wtq);
    cudaGetSymbolAddress((void**)&wtk,  g_wtk);
    cudaGetSymbolAddress((void**)&wtv,  g_wtv);
    cudaGetSymbolAddress((void**)&wto,  g_wto);
    cudaGetSymbolAddress((void**)&wt1,  g_wt1);
    cudaGetSymbolAddress((void**)&wt2,  g_wt2);

    cudaFuncSetAttribute(attn_kernel,
                         cudaFuncAttributeMaxDynamicSharedMemorySize, ATTN_SMEM);
    cudaFuncSetAttribute(mm_gemm<0>,
                         cudaFuncAttributeMaxDynamicSharedMemorySize, GEMM_SMEM);
    cudaFuncSetAttribute(mm_gemm<1>,
                         cudaFuncAttributeMaxDynamicSharedMemorySize, GEMM_SMEM);
    cudaFuncSetAttribute(mm_gemm<2>,
                         cudaFuncAttributeMaxDynamicSharedMemorySize, GEMM_SMEM);

    // 0. all weight transposes (one launch)
    transpose_all<<<dim3(64, 64, 6), 256>>>(Wq, Wk, Wv, Wo, W1, W2,
                                            wtq, wtk, wtv, wto, wt1, wt2);
    // 1. LN1
    ln_kernel<<<MDIM, 256>>>(inp, ln1_g, ln1_b, xln1r, xln1f);

    // 2. QKV
    dim3 gE(EDIM / 128, MDIM / 128);
    mm_gemm<0><<<gE, 128, GEMM_SMEM>>>(xln1r, wtq, bq, nullptr, q, MDIM, EDIM, EDIM);
    mm_gemm<0><<<gE, 128, GEMM_SMEM>>>(xln1r, wtk, bk, nullptr, k, MDIM, EDIM, EDIM);
    mm_gemm<0><<<gE, 128, GEMM_SMEM>>>(xln1r, wtv, bv, nullptr, v, MDIM, EDIM, EDIM);

    // 3. Attention  (launch index 5 -> ncu capture)
    dim3 gA(SDIM / 128, HDIM, BDIM);
    attn_kernel<<<gA, 256, ATTN_SMEM>>>(q, k, v, ctx);

    // 4. O-proj + residual(LN1 full)
    mm_gemm<1><<<gE, 128, GEMM_SMEM>>>(ctx, wto, bo, xln1f, x2, MDIM, EDIM, EDIM);

    // 5. LN2
    ln_kernel<<<MDIM, 256>>>(x2, ln2_g, ln2_b, x3r, x3f);

    // 6. MLP
    dim3 gF(FDIM / 128, MDIM / 128);
    mm_gemm<2><<<gF, 128, GEMM_SMEM>>>(x3r, wt1, b1, nullptr, h1, MDIM, FDIM, EDIM);
    mm_gemm<1><<<gE, 128, GEMM_SMEM>>>(h1, wt2, b2, x3f, out, MDIM, EDIM, FDIM);
}

// round 5
// speedup vs baseline: 2.7301x; 1.1175x over previous
#include <cuda_runtime.h>
#include <math.h>
#include <stdint.h>

// ---------------------------------------------------------------------------
// TransformerBlock B=4,S=2048,E=1024,H=16,D=64 — tf32 mma.sync everywhere.
// R5: GEMM CTA tile 128x256, 256 thr (8 warps 2x4, warp tile 64x64),
//     2-stage cp.async pipeline -> 16 warps/SM.
// ---------------------------------------------------------------------------

#define MDIM 8192
#define EDIM 1024
#define SDIM 2048
#define BDIM 4
#define HDIM 16
#define FDIM 2048

__device__ float g_xln1r[MDIM * EDIM];
__device__ float g_xln1f[MDIM * EDIM];
__device__ float g_q  [MDIM * EDIM];
__device__ float g_k  [MDIM * EDIM];
__device__ float g_v  [MDIM * EDIM];
__device__ float g_ctx[MDIM * EDIM];
__device__ float g_x2 [MDIM * EDIM];
__device__ float g_x3r[MDIM * EDIM];
__device__ float g_x3f[MDIM * EDIM];
__device__ float g_h1 [MDIM * FDIM];
__device__ float g_wtq[EDIM * EDIM];
__device__ float g_wtk[EDIM * EDIM];
__device__ float g_wtv[EDIM * EDIM];
__device__ float g_wto[EDIM * EDIM];
__device__ float g_wt1[FDIM * EDIM];
__device__ float g_wt2[EDIM * FDIM];

// ---------------------------------------------------------------------------
__device__ __forceinline__ uint32_t smem_u32(const void* p) {
    uint32_t a;
    asm("{ .reg .u64 t; cvta.to.shared.u64 t, %1; cvt.u32.u64 %0, t; }"
        : "=r"(a) : "l"(p));
    return a;
}
__device__ __forceinline__ float tf32r(float v) {
    uint32_t r;
    asm("cvt.rna.tf32.f32 %0, %1;" : "=r"(r) : "f"(v));
    return __uint_as_float(r);
}
__device__ __forceinline__ void cpa16(uint32_t s, const void* g) {
    asm volatile("cp.async.cg.shared.global [%0], [%1], 16;" :: "r"(s), "l"(g));
}
#define CP_COMMIT() asm volatile("cp.async.commit_group;" ::: "memory")
#define CP_WAIT0()  asm volatile("cp.async.wait_group 0;" ::: "memory")
#define CP_WAIT1()  asm volatile("cp.async.wait_group 1;" ::: "memory")

__device__ __forceinline__ void mma8(float* c, const uint32_t* a,
                                     uint32_t b0, uint32_t b1) {
    asm volatile(
        "mma.sync.aligned.m16n8k8.row.col.f32.tf32.tf32.f32 "
        "{%0,%1,%2,%3}, {%4,%5,%6,%7}, {%8,%9}, {%0,%1,%2,%3};"
        : "+f"(c[0]), "+f"(c[1]), "+f"(c[2]), "+f"(c[3])
        : "r"(a[0]), "r"(a[1]), "r"(a[2]), "r"(a[3]), "r"(b0), "r"(b1));
}

// ---------------------------------------------------------------------------
// All 6 weight transposes in ONE launch. WT[n*K+k] = tf32round(W[k*N+n])
// ---------------------------------------------------------------------------
__global__ __launch_bounds__(256) void transpose_all(
    const float* __restrict__ Wq, const float* __restrict__ Wk,
    const float* __restrict__ Wv, const float* __restrict__ Wo,
    const float* __restrict__ W1, const float* __restrict__ W2,
    float* __restrict__ wtq, float* __restrict__ wtk,
    float* __restrict__ wtv, float* __restrict__ wto,
    float* __restrict__ wt1, float* __restrict__ wt2)
{
    const float* W; float* WT; int K, N;
    switch (blockIdx.z) {
        case 0: W = Wq; WT = wtq; K = EDIM; N = EDIM; break;
        case 1: W = Wk; WT = wtk; K = EDIM; N = EDIM; break;
        case 2: W = Wv; WT = wtv; K = EDIM; N = EDIM; break;
        case 3: W = Wo; WT = wto; K = EDIM; N = EDIM; break;
        case 4: W = W1; WT = wt1; K = EDIM; N = FDIM; break;
        default: W = W2; WT = wt2; K = FDIM; N = EDIM; break;
    }
    const int n0 = blockIdx.x * 32, k0 = blockIdx.y * 32;
    if (n0 >= N || k0 >= K) return;
    __shared__ float t[32][33];
    const int x = threadIdx.x & 31, y = threadIdx.x >> 5;
    #pragma unroll
    for (int i = 0; i < 32; i += 8)
        t[y + i][x] = W[(size_t)(k0 + y + i) * N + n0 + x];
    __syncthreads();
    #pragma unroll
    for (int i = 0; i < 32; i += 8)
        WT[(size_t)(n0 + y + i) * K + k0 + x] = tf32r(t[x][y + i]);
}

// ---------------------------------------------------------------------------
// LayerNorm: rounded copy (yr) + full copy (yf)
// ---------------------------------------------------------------------------
__global__ __launch_bounds__(256) void ln_kernel(
    const float* __restrict__ x, const float* __restrict__ g,
    const float* __restrict__ b, float* __restrict__ yr, float* __restrict__ yf)
{
    const int row = blockIdx.x;
    const int tid = threadIdx.x;
    const float4 v = reinterpret_cast<const float4*>(x + (size_t)row * EDIM)[tid];

    float s  = v.x + v.y + v.z + v.w;
    float ss = v.x * v.x + v.y * v.y + v.z * v.z + v.w * v.w;
    #pragma unroll
    for (int off = 16; off > 0; off >>= 1) {
        s  += __shfl_down_sync(0xffffffffu, s,  off);
        ss += __shfl_down_sync(0xffffffffu, ss, off);
    }
    __shared__ float wsum[8], wsq[8];
    __shared__ float s_mu, s_rstd;
    const int wid = tid >> 5, lane = tid & 31;
    if (lane == 0) { wsum[wid] = s; wsq[wid] = ss; }
    __syncthreads();
    if (tid == 0) {
        float ts = 0.f, tss = 0.f;
        #pragma unroll
        for (int i = 0; i < 8; i++) { ts += wsum[i]; tss += wsq[i]; }
        const float mu  = ts * (1.0f / EDIM);
        const float var = tss * (1.0f / EDIM) - mu * mu;
        s_mu = mu; s_rstd = rsqrtf(var + 1e-5f);
    }
    __syncthreads();
    const float mu = s_mu, rstd = s_rstd;
    const float4 gv = reinterpret_cast<const float4*>(g)[tid];
    const float4 bv = reinterpret_cast<const float4*>(b)[tid];
    float4 o;
    o.x = (v.x - mu) * rstd * gv.x + bv.x;
    o.y = (v.y - mu) * rstd * gv.y + bv.y;
    o.z = (v.z - mu) * rstd * gv.z + bv.z;
    o.w = (v.w - mu) * rstd * gv.w + bv.w;
    reinterpret_cast<float4*>(yf + (size_t)row * EDIM)[tid] = o;
    float4 orr;
    orr.x = tf32r(o.x); orr.y = tf32r(o.y);
    orr.z = tf32r(o.z); orr.w = tf32r(o.w);
    reinterpret_cast<float4*>(yr + (size_t)row * EDIM)[tid] = orr;
}

// ---------------------------------------------------------------------------
// tf32 GEMM: C[M,N] = A[M,K] @ Bt[N,K]^T + bias (+epilogue)
// CTA tile 128x256, 256 threads (8 warps 2x4), warp tile 64x64, KCH=32,
// 2-stage cp.async pipeline (108 KB smem -> 2 CTA/SM, 16 warps/SM).
// OP: 0 = bias + tf32 round; 1 = bias + residual; 2 = bias + GELU + round
// ---------------------------------------------------------------------------
#define KCH 32
#define AST 36
#define A_FL (128 * AST)
#define B_FL (256 * AST)
#define STG_FL (A_FL + B_FL)
#define GEMM_SMEM (2 * STG_FL * (int)sizeof(float))

template <int OP>
__global__ __launch_bounds__(256) void mm_gemm(
    const float* __restrict__ A, const float* __restrict__ Bt,
    const float* __restrict__ bias, const float* __restrict__ res,
    float* __restrict__ C, int M, int N, int K)
{
    extern __shared__ float sm[];
    const int tid = threadIdx.x;
    const int wid = tid >> 5, lane = tid & 31;
    const int row0 = blockIdx.y * 128, col0 = blockIdx.x * 256;

    // copy mapping: A row tid>>1 (2 thr/row, 4x16B each); B row tid (8x16B)
    const float* gA = A  + (size_t)(row0 + (tid >> 1)) * K + (tid & 1) * 16;
    const float* gB = Bt + (size_t)(col0 + tid) * K;
    const uint32_t sm0 = smem_u32(sm);
    const uint32_t dA = sm0 + (uint32_t)(((tid >> 1) * AST + (tid & 1) * 16) * 4);
    const uint32_t dB = sm0 + (uint32_t)((A_FL + tid * AST) * 4);

    const int nch = K >> 5;

    // prologue: chunk 0 -> stage 0
    #pragma unroll
    for (int u = 0; u < 4; u++) cpa16(dA + u * 16u, gA + u * 4);
    #pragma unroll
    for (int u = 0; u < 8; u++) cpa16(dB + u * 16u, gB + u * 4);
    CP_COMMIT();

    const int wm = wid & 1, wn = wid >> 1;        // 2 x 4 warp grid
    const int lr = lane >> 2, lk = lane & 3;
    const int abase = (wm * 64 + lr) * AST + lk;
    const int bbase = A_FL + (wn * 64 + lr) * AST + lk;

    float acc[4][8][4];
    #pragma unroll
    for (int mt = 0; mt < 4; mt++)
        #pragma unroll
        for (int nt = 0; nt < 8; nt++)
            #pragma unroll
            for (int r = 0; r < 4; r++) acc[mt][nt][r] = 0.f;

    for (int i = 0; i < nch; i++) {
        __syncthreads();                           // stage (i+1)&1 free to fill
        const int j = i + 1;
        if (j < nch) {
            const uint32_t so = (uint32_t)((j & 1) * STG_FL) * 4u;
            #pragma unroll
            for (int u = 0; u < 4; u++)
                cpa16(dA + so + u * 16u, gA + j * KCH + u * 4);
            #pragma unroll
            for (int u = 0; u < 8; u++)
                cpa16(dB + so + u * 16u, gB + j * KCH + u * 4);
        }
        CP_COMMIT();
        CP_WAIT1();                                // chunk i resident
        __syncthreads();

        const float* st = sm + (i & 1) * STG_FL;
        const uint32_t* uA = reinterpret_cast<const uint32_t*>(st + abase);
        const uint32_t* uB = reinterpret_cast<const uint32_t*>(st + bbase);

        #pragma unroll
        for (int ks = 0; ks < 4; ks++) {
            uint32_t a[4][4];
            #pragma unroll
            for (int mt = 0; mt < 4; mt++) {
                const uint32_t* p = uA + mt * (16 * AST) + ks * 8;
                a[mt][0] = p[0];
                a[mt][1] = p[8 * AST];
                a[mt][2] = p[4];
                a[mt][3] = p[8 * AST + 4];
            }
            #pragma unroll
            for (int nt = 0; nt < 8; nt++) {
                const uint32_t* p = uB + nt * (8 * AST) + ks * 8;
                const uint32_t b0 = p[0], b1 = p[4];
                #pragma unroll
                for (int mt = 0; mt < 4; mt++)
                    mma8(acc[mt][nt], a[mt], b0, b1);
            }
        }
    }

    const int lc = 2 * lk;
    #pragma unroll
    for (int nt = 0; nt < 8; nt++) {
        const int col = col0 + wn * 64 + nt * 8 + lc;
        const float bx = bias[col], by = bias[col + 1];
        #pragma unroll
        for (int mt = 0; mt < 4; mt++) {
            const int row = row0 + wm * 64 + mt * 16 + lr;
            #pragma unroll
            for (int h = 0; h < 2; h++) {
                const int r = row + h * 8;
                float vx = acc[mt][nt][2 * h + 0] + bx;
                float vy = acc[mt][nt][2 * h + 1] + by;
                if (OP == 2) {
                    vx = tf32r(0.5f * vx * (1.0f + erff(vx * 0.70710678118654752f)));
                    vy = tf32r(0.5f * vy * (1.0f + erff(vy * 0.70710678118654752f)));
                }
                if (OP == 0) { vx = tf32r(vx); vy = tf32r(vy); }
                if (OP == 1) {
                    const float* rp = res + (size_t)r * N + col;
                    vx += rp[0]; vy += rp[1];
                }
                *reinterpret_cast<float2*>(C + (size_t)r * N + col)
                    = make_float2(vx, vy);
            }
        }
    }
}

// ---------------------------------------------------------------------------
// Flash attention, tf32 mma. 256 threads / (b,h,128-row q tile). (unchanged)
// ---------------------------------------------------------------------------
#define QLD 68
#define PLD 76
#define ATTN_SMEM ((128 * QLD + 64 * QLD + 64 * QLD + 128 * PLD) * (int)sizeof(float))

__global__ __launch_bounds__(256) void attn_kernel(
    const float* __restrict__ Q, const float* __restrict__ K,
    const float* __restrict__ V, float* __restrict__ O)
{
    extern __shared__ float smf[];
    float* Qs = smf;
    float* Ks = Qs + 128 * QLD;
    float* Vs = Ks + 64 * QLD;
    float* Ps = Vs + 64 * QLD;
    __shared__ float s_alpha[128];

    const int tid = threadIdx.x;
    const int w = tid >> 5, lane = tid & 31;
    const int lr = lane >> 2, lk = lane & 3;
    const int wm = w >> 1, wn = w & 1;
    const int q0 = blockIdx.x * 128;
    const size_t base = (size_t)blockIdx.z * SDIM * EDIM + (size_t)blockIdx.y * 64;

    const uint32_t sQ = smem_u32(Qs), sK = smem_u32(Ks), sV = smem_u32(Vs);

    #pragma unroll
    for (int u = 0; u < 8; u++) {
        const int idx = u * 256 + tid;
        const int r = idx >> 4, seg = idx & 15;
        cpa16(sQ + (uint32_t)(r * QLD + seg * 4) * 4u,
              Q + base + (size_t)(q0 + r) * EDIM + seg * 4);
    }
    CP_COMMIT();

    float oacc[2][4][4];
    #pragma unroll
    for (int mt = 0; mt < 2; mt++)
        #pragma unroll
        for (int nt = 0; nt < 4; nt++)
            #pragma unroll
            for (int r = 0; r < 4; r++) oacc[mt][nt][r] = 0.f;
    float m_i = -1e30f, l_i = 0.f;

    const int srow = tid >> 1;
    const int shalf = (tid & 1) * 32;

    for (int kt = 0; kt < 32; kt++) {
        const int k0 = kt * 64;
        #pragma unroll
        for (int u = 0; u < 4; u++) {
            const int idx = u * 256 + tid;
            const int r = idx >> 4, seg = idx & 15;
            const size_t g = base + (size_t)(k0 + r) * EDIM + seg * 4;
            cpa16(sK + (uint32_t)(r * QLD + seg * 4) * 4u, K + g);
            cpa16(sV + (uint32_t)(r * QLD + seg * 4) * 4u, V + g);
        }
        CP_COMMIT();
        CP_WAIT0();
        __syncthreads();

        float sacc[2][4][4];
        #pragma unroll
        for (int mt = 0; mt < 2; mt++)
            #pragma unroll
            for (int nt = 0; nt < 4; nt++)
                #pragma unroll
                for (int r = 0; r < 4; r++) sacc[mt][nt][r] = 0.f;

        #pragma unroll
        for (int ks = 0; ks < 8; ks++) {
            uint32_t a[2][4];
            #pragma unroll
            for (int mt = 0; mt < 2; mt++) {
                const uint32_t* p = reinterpret_cast<const uint32_t*>(
                    Qs + (wm * 32 + mt * 16 + lr) * QLD + ks * 8 + lk);
                a[mt][0] = p[0];
                a[mt][1] = p[8 * QLD];
                a[mt][2] = p[4];
                a[mt][3] = p[8 * QLD + 4];
            }
            #pragma unroll
            for (int nt = 0; nt < 4; nt++) {
                const uint32_t* p = reinterpret_cast<const uint32_t*>(
                    Ks + (wn * 32 + nt * 8 + lr) * QLD + ks * 8 + lk);
                const uint32_t b0 = p[0], b1 = p[4];
                #pragma unroll
                for (int mt = 0; mt < 2; mt++)
                    mma8(sacc[mt][nt], a[mt], b0, b1);
            }
        }
        #pragma unroll
        for (int mt = 0; mt < 2; mt++) {
            const int r0 = wm * 32 + mt * 16 + lr;
            #pragma unroll
            for (int nt = 0; nt < 4; nt++) {
                const int c = wn * 32 + nt * 8 + 2 * lk;
                *reinterpret_cast<float2*>(Ps + r0 * PLD + c)
                    = make_float2(sacc[mt][nt][0] * 0.125f, sacc[mt][nt][1] * 0.125f);
                *reinterpret_cast<float2*>(Ps + (r0 + 8) * PLD + c)
                    = make_float2(sacc[mt][nt][2] * 0.125f, sacc[mt][nt][3] * 0.125f);
            }
        }
        __syncthreads();

        {
            float* pr = Ps + srow * PLD + shalf;
            float mx = -1e30f;
            #pragma unroll 8
            for (int c = 0; c < 32; c++) mx = fmaxf(mx, pr[c]);
            mx = fmaxf(mx, __shfl_xor_sync(0xffffffffu, mx, 1));
            const float mnew  = fmaxf(m_i, mx);
            const float alpha = __expf(m_i - mnew);
            float sum = 0.f;
            #pragma unroll 8
            for (int c = 0; c < 32; c++) {
                const float p = __expf(pr[c] - mnew);
                pr[c] = p;
                sum += p;
            }
            sum += __shfl_xor_sync(0xffffffffu, sum, 1);
            l_i = l_i * alpha + sum;
            m_i = mnew;
            s_alpha[srow] = alpha;
        }
        __syncthreads();

        #pragma unroll
        for (int mt = 0; mt < 2; mt++) {
            const int r0 = wm * 32 + mt * 16 + lr;
            const float al0 = s_alpha[r0], al1 = s_alpha[r0 + 8];
            #pragma unroll
            for (int nt = 0; nt < 4; nt++) {
                oacc[mt][nt][0] *= al0; oacc[mt][nt][1] *= al0;
                oacc[mt][nt][2] *= al1; oacc[mt][nt][3] *= al1;
            }
        }
        #pragma unroll
        for (int ks = 0; ks < 8; ks++) {
            uint32_t a[2][4];
            #pragma unroll
            for (int mt = 0; mt < 2; mt++) {
                const uint32_t* p = reinterpret_cast<const uint32_t*>(
                    Ps + (wm * 32 + mt * 16 + lr) * PLD + ks * 8 + lk);
                a[mt][0] = p[0];
                a[mt][1] = p[8 * PLD];
                a[mt][2] = p[4];
                a[mt][3] = p[8 * PLD + 4];
            }
            #pragma unroll
            for (int nt = 0; nt < 4; nt++) {
                const uint32_t b0 = *reinterpret_cast<const uint32_t*>(
                    Vs + (ks * 8 + lk) * QLD + wn * 32 + nt * 8 + lr);
                const uint32_t b1 = *reinterpret_cast<const uint32_t*>(
                    Vs + (ks * 8 + lk + 4) * QLD + wn * 32 + nt * 8 + lr);
                #pragma unroll
                for (int mt = 0; mt < 2; mt++)
                    mma8(oacc[mt][nt], a[mt], b0, b1);
            }
        }
        __syncthreads();
    }

    s_alpha[srow] = 1.0f / l_i;
    __syncthreads();

    #pragma unroll
    for (int mt = 0; mt < 2; mt++) {
        const int r0 = wm * 32 + mt * 16 + lr;
        const float inv0 = s_alpha[r0], inv1 = s_alpha[r0 + 8];
        #pragma unroll
        for (int nt = 0; nt < 4; nt++) {
            const int c = wn * 32 + nt * 8 + 2 * lk;
            float* p0 = O + base + (size_t)(q0 + r0) * EDIM + c;
            float* p1 = O + base + (size_t)(q0 + r0 + 8) * EDIM + c;
            *reinterpret_cast<float2*>(p0) = make_float2(
                tf32r(oacc[mt][nt][0] * inv0), tf32r(oacc[mt][nt][1] * inv0));
            *reinterpret_cast<float2*>(p1) = make_float2(
                tf32r(oacc[mt][nt][2] * inv1), tf32r(oacc[mt][nt][3] * inv1));
        }
    }
}

// ---------------------------------------------------------------------------
extern "C" void kernel_launch(void* const* d_in, const int* in_sizes, int n_in,
                              void* d_out, int out_size)
{
    const float* inp   = (const float*)d_in[0];
    const float* ln1_g = (const float*)d_in[1];
    const float* ln1_b = (const float*)d_in[2];
    const float* Wq    = (const float*)d_in[3];
    const float* bq    = (const float*)d_in[4];
    const float* Wk    = (const float*)d_in[5];
    const float* bk    = (const float*)d_in[6];
    const float* Wv    = (const float*)d_in[7];
    const float* bv    = (const float*)d_in[8];
    const float* Wo    = (const float*)d_in[9];
    const float* bo    = (const float*)d_in[10];
    const float* ln2_g = (const float*)d_in[11];
    const float* ln2_b = (const float*)d_in[12];
    const float* W1    = (const float*)d_in[13];
    const float* b1    = (const float*)d_in[14];
    const float* W2    = (const float*)d_in[15];
    const float* b2    = (const float*)d_in[16];
    float* out = (float*)d_out;

    float *xln1r, *xln1f, *q, *k, *v, *ctx, *x2, *x3r, *x3f, *h1;
    float *wtq, *wtk, *wtv, *wto, *wt1, *wt2;
    cudaGetSymbolAddress((void**)&xln1r, g_xln1r);
    cudaGetSymbolAddress((void**)&xln1f, g_xln1f);
    cudaGetSymbolAddress((void**)&q,    g_q);
    cudaGetSymbolAddress((void**)&k,    g_k);
    cudaGetSymbolAddress((void**)&v,    g_v);
    cudaGetSymbolAddress((void**)&ctx,  g_ctx);
    cudaGetSymbolAddress((void**)&x2,   g_x2);
    cudaGetSymbolAddress((void**)&x3r,  g_x3r);
    cudaGetSymbolAddress((void**)&x3f,  g_x3f);
    cudaGetSymbolAddress((void**)&h1,   g_h1);
    cudaGetSymbolAddress((void**)&wtq,  g_wtq);
    cudaGetSymbolAddress((void**)&wtk,  g_wtk);
    cudaGetSymbolAddress((void**)&wtv,  g_wtv);
    cudaGetSymbolAddress((void**)&wto,  g_wto);
    cudaGetSymbolAddress((void**)&wt1,  g_wt1);
    cudaGetSymbolAddress((void**)&wt2,  g_wt2);

    cudaFuncSetAttribute(attn_kernel,
                         cudaFuncAttributeMaxDynamicSharedMemorySize, ATTN_SMEM);
    cudaFuncSetAttribute(mm_gemm<0>,
                         cudaFuncAttributeMaxDynamicSharedMemorySize, GEMM_SMEM);
    cudaFuncSetAttribute(mm_gemm<1>,
                         cudaFuncAttributeMaxDynamicSharedMemorySize, GEMM_SMEM);
    cudaFuncSetAttribute(mm_gemm<2>,
                         cudaFuncAttributeMaxDynamicSharedMemorySize, GEMM_SMEM);

    // 0. all weight transposes (one launch)
    transpose_all<<<dim3(64, 64, 6), 256>>>(Wq, Wk, Wv, Wo, W1, W2,
                                            wtq, wtk, wtv, wto, wt1, wt2);
    // 1. LN1
    ln_kernel<<<MDIM, 256>>>(inp, ln1_g, ln1_b, xln1r, xln1f);

    // 2. QKV
    dim3 gE(EDIM / 256, MDIM / 128);
    mm_gemm<0><<<gE, 256, GEMM_SMEM>>>(xln1r, wtq, bq, nullptr, q, MDIM, EDIM, EDIM);
    mm_gemm<0><<<gE, 256, GEMM_SMEM>>>(xln1r, wtk, bk, nullptr, k, MDIM, EDIM, EDIM);
    mm_gemm<0><<<gE, 256, GEMM_SMEM>>>(xln1r, wtv, bv, nullptr, v, MDIM, EDIM, EDIM);

    // 3. Attention (launch index 5 -> ncu capture)
    dim3 gA(SDIM / 128, HDIM, BDIM);
    attn_kernel<<<gA, 256, ATTN_SMEM>>>(q, k, v, ctx);

    // 4. O-proj + residual(LN1 full)
    mm_gemm<1><<<gE, 256, GEMM_SMEM>>>(ctx, wto, bo, xln1f, x2, MDIM, EDIM, EDIM);

    // 5. LN2
    ln_kernel<<<MDIM, 256>>>(x2, ln2_g, ln2_b, x3r, x3f);

    // 6. MLP
    dim3 gF(FDIM / 256, MDIM / 128);
    mm_gemm<2><<<gF, 256, GEMM_SMEM>>>(x3r, wt1, b1, nullptr, h1, MDIM, FDIM, EDIM);
    mm_gemm<1><<<gE, 256, GEMM_SMEM>>>(h1, wt2, b2, x3f, out, MDIM, EDIM, FDIM);
}

// round 7
// speedup vs baseline: 4.0181x; 1.4718x over previous
#include <cuda_runtime.h>
#include <cuda_fp16.h>
#include <math.h>
#include <stdint.h>

// ---------------------------------------------------------------------------
// TransformerBlock B=4,S=2048,E=1024,H=16,D=64.
// R7 (= R6 resubmit after infra failure): fp16 m16n8k16 GEMMs (fp32 accum),
// 128x128 CTA / 4 warps / 3 CTA/SM. Attention: fp16 QK^T + tf32 PV.
// ---------------------------------------------------------------------------

#define MDIM 8192
#define EDIM 1024
#define SDIM 2048
#define BDIM 4
#define HDIM 16
#define FDIM 2048

__device__ __half g_xln1h[MDIM * EDIM];
__device__ float  g_xln1f[MDIM * EDIM];
__device__ __half g_q  [MDIM * EDIM];
__device__ __half g_k  [MDIM * EDIM];
__device__ float  g_v  [MDIM * EDIM];
__device__ __half g_ctx[MDIM * EDIM];
__device__ float  g_x2 [MDIM * EDIM];
__device__ __half g_x3h[MDIM * EDIM];
__device__ float  g_x3f[MDIM * EDIM];
__device__ __half g_h1 [MDIM * FDIM];
__device__ __half g_wtq[EDIM * EDIM];
__device__ __half g_wtk[EDIM * EDIM];
__device__ __half g_wtv[EDIM * EDIM];
__device__ __half g_wto[EDIM * EDIM];
__device__ __half g_wt1[FDIM * EDIM];
__device__ __half g_wt2[EDIM * FDIM];

// ---------------------------------------------------------------------------
__device__ __forceinline__ uint32_t smem_u32(const void* p) {
    uint32_t a;
    asm("{ .reg .u64 t; cvta.to.shared.u64 t, %1; cvt.u32.u64 %0, t; }"
        : "=r"(a) : "l"(p));
    return a;
}
__device__ __forceinline__ void cpa16(uint32_t s, const void* g) {
    asm volatile("cp.async.cg.shared.global [%0], [%1], 16;" :: "r"(s), "l"(g));
}
#define CP_COMMIT() asm volatile("cp.async.commit_group;" ::: "memory")
#define CP_WAIT0()  asm volatile("cp.async.wait_group 0;" ::: "memory")
#define CP_WAIT1()  asm volatile("cp.async.wait_group 1;" ::: "memory")

// fp16 MMA, fp32 accumulate
__device__ __forceinline__ void mma16(float* c, const uint32_t* a,
                                      uint32_t b0, uint32_t b1) {
    asm volatile(
        "mma.sync.aligned.m16n8k16.row.col.f32.f16.f16.f32 "
        "{%0,%1,%2,%3}, {%4,%5,%6,%7}, {%8,%9}, {%0,%1,%2,%3};"
        : "+f"(c[0]), "+f"(c[1]), "+f"(c[2]), "+f"(c[3])
        : "r"(a[0]), "r"(a[1]), "r"(a[2]), "r"(a[3]), "r"(b0), "r"(b1));
}
// tf32 MMA (PV path)
__device__ __forceinline__ void mma8(float* c, const uint32_t* a,
                                     uint32_t b0, uint32_t b1) {
    asm volatile(
        "mma.sync.aligned.m16n8k8.row.col.f32.tf32.tf32.f32 "
        "{%0,%1,%2,%3}, {%4,%5,%6,%7}, {%8,%9}, {%0,%1,%2,%3};"
        : "+f"(c[0]), "+f"(c[1]), "+f"(c[2]), "+f"(c[3])
        : "r"(a[0]), "r"(a[1]), "r"(a[2]), "r"(a[3]), "r"(b0), "r"(b1));
}

// ---------------------------------------------------------------------------
// All 6 weight transposes in ONE launch. WT[n*K+k] = half(W[k*N+n])
// ---------------------------------------------------------------------------
__global__ __launch_bounds__(256) void transpose_all(
    const float* __restrict__ Wq, const float* __restrict__ Wk,
    const float* __restrict__ Wv, const float* __restrict__ Wo,
    const float* __restrict__ W1, const float* __restrict__ W2,
    __half* __restrict__ wtq, __half* __restrict__ wtk,
    __half* __restrict__ wtv, __half* __restrict__ wto,
    __half* __restrict__ wt1, __half* __restrict__ wt2)
{
    const float* W; __half* WT; int K, N;
    switch (blockIdx.z) {
        case 0: W = Wq; WT = wtq; K = EDIM; N = EDIM; break;
        case 1: W = Wk; WT = wtk; K = EDIM; N = EDIM; break;
        case 2: W = Wv; WT = wtv; K = EDIM; N = EDIM; break;
        case 3: W = Wo; WT = wto; K = EDIM; N = EDIM; break;
        case 4: W = W1; WT = wt1; K = EDIM; N = FDIM; break;
        default: W = W2; WT = wt2; K = FDIM; N = EDIM; break;
    }
    const int n0 = blockIdx.x * 32, k0 = blockIdx.y * 32;
    if (n0 >= N || k0 >= K) return;
    __shared__ float t[32][33];
    const int x = threadIdx.x & 31, y = threadIdx.x >> 5;
    #pragma unroll
    for (int i = 0; i < 32; i += 8)
        t[y + i][x] = W[(size_t)(k0 + y + i) * N + n0 + x];
    __syncthreads();
    #pragma unroll
    for (int i = 0; i < 32; i += 8)
        WT[(size_t)(n0 + y + i) * K + k0 + x] = __float2half_rn(t[x][y + i]);
}

// ---------------------------------------------------------------------------
// LayerNorm: half copy (yh, GEMM input) + full fp32 copy (yf, residual)
// ---------------------------------------------------------------------------
__global__ __launch_bounds__(256) void ln_kernel(
    const float* __restrict__ x, const float* __restrict__ g,
    const float* __restrict__ b, __half* __restrict__ yh, float* __restrict__ yf)
{
    const int row = blockIdx.x;
    const int tid = threadIdx.x;
    const float4 v = reinterpret_cast<const float4*>(x + (size_t)row * EDIM)[tid];

    float s  = v.x + v.y + v.z + v.w;
    float ss = v.x * v.x + v.y * v.y + v.z * v.z + v.w * v.w;
    #pragma unroll
    for (int off = 16; off > 0; off >>= 1) {
        s  += __shfl_down_sync(0xffffffffu, s,  off);
        ss += __shfl_down_sync(0xffffffffu, ss, off);
    }
    __shared__ float wsum[8], wsq[8];
    __shared__ float s_mu, s_rstd;
    const int wid = tid >> 5, lane = tid & 31;
    if (lane == 0) { wsum[wid] = s; wsq[wid] = ss; }
    __syncthreads();
    if (tid == 0) {
        float ts = 0.f, tss = 0.f;
        #pragma unroll
        for (int i = 0; i < 8; i++) { ts += wsum[i]; tss += wsq[i]; }
        const float mu  = ts * (1.0f / EDIM);
        const float var = tss * (1.0f / EDIM) - mu * mu;
        s_mu = mu; s_rstd = rsqrtf(var + 1e-5f);
    }
    __syncthreads();
    const float mu = s_mu, rstd = s_rstd;
    const float4 gv = reinterpret_cast<const float4*>(g)[tid];
    const float4 bv = reinterpret_cast<const float4*>(b)[tid];
    float4 o;
    o.x = (v.x - mu) * rstd * gv.x + bv.x;
    o.y = (v.y - mu) * rstd * gv.y + bv.y;
    o.z = (v.z - mu) * rstd * gv.z + bv.z;
    o.w = (v.w - mu) * rstd * gv.w + bv.w;
    reinterpret_cast<float4*>(yf + (size_t)row * EDIM)[tid] = o;
    __half2* hp = reinterpret_cast<__half2*>(yh + (size_t)row * EDIM);
    hp[2 * tid + 0] = __halves2half2(__float2half_rn(o.x), __float2half_rn(o.y));
    hp[2 * tid + 1] = __halves2half2(__float2half_rn(o.z), __float2half_rn(o.w));
}

// ---------------------------------------------------------------------------
// fp16 GEMM: C[M,N] = A[M,K] @ Bt[N,K]^T + bias (+epilogue).
// CTA 128x128, 128 thr (4 warps 2x2, warp tile 64x64), KCH=64, 2 stages,
// __launch_bounds__(128,3) -> 3 CTA/SM (12 warps).
// OP: 0 half out (bias); 1 float out (bias+residual);
//     2 half out (bias+GELU); 3 float out (bias)
// ---------------------------------------------------------------------------
#define KCH 64
#define AST 36                         // uint32 per smem row (72 halves)
#define TILE_U32 (128 * AST)           // one operand tile in u32
#define STG_U32 (2 * TILE_U32)
#define GEMM_SMEM (2 * STG_U32 * 4)    // 73728 B

template <int OP>
__global__ __launch_bounds__(128, 3) void mm_gemm(
    const __half* __restrict__ A, const __half* __restrict__ Bt,
    const float* __restrict__ bias, const float* __restrict__ res,
    void* __restrict__ Cv, int M, int N, int K)
{
    extern __shared__ uint32_t sm[];
    const int tid = threadIdx.x;
    const int wid = tid >> 5, lane = tid & 31;
    const int row0 = blockIdx.y * 128, col0 = blockIdx.x * 128;

    // copy mapping: thread t -> A row t, B row t; 8 x 16B segments each
    const __half* gA = A  + (size_t)(row0 + tid) * K;
    const __half* gB = Bt + (size_t)(col0 + tid) * K;
    const uint32_t sm0 = smem_u32(sm);
    const uint32_t dA = sm0 + (uint32_t)(tid * 144);
    const uint32_t dB = sm0 + (uint32_t)(TILE_U32 * 4 + tid * 144);

    const int nch = K / KCH;

    // prologue: chunk 0 -> stage 0
    #pragma unroll
    for (int u = 0; u < 8; u++) {
        cpa16(dA + u * 16u, gA + u * 8);
        cpa16(dB + u * 16u, gB + u * 8);
    }
    CP_COMMIT();

    const int wm = wid & 1, wn = wid >> 1;
    const int lr = lane >> 2, lk = lane & 3;
    const int abase = (wm * 64 + lr) * AST + lk;
    const int bbase = TILE_U32 + (wn * 64 + lr) * AST + lk;

    float acc[4][8][4];
    #pragma unroll
    for (int mt = 0; mt < 4; mt++)
        #pragma unroll
        for (int nt = 0; nt < 8; nt++)
            #pragma unroll
            for (int r = 0; r < 4; r++) acc[mt][nt][r] = 0.f;

    for (int i = 0; i < nch; i++) {
        __syncthreads();                         // prev compute done on stage (i+1)&1
        const int j = i + 1;
        if (j < nch) {
            const uint32_t so = (uint32_t)((j & 1) * STG_U32) * 4u;
            #pragma unroll
            for (int u = 0; u < 8; u++) {
                cpa16(dA + so + u * 16u, gA + j * KCH + u * 8);
                cpa16(dB + so + u * 16u, gB + j * KCH + u * 8);
            }
        }
        CP_COMMIT();
        CP_WAIT1();                              // chunk i resident
        __syncthreads();

        const uint32_t* st = sm + (i & 1) * STG_U32;
        const uint32_t* uA = st + abase;
        const uint32_t* uB = st + bbase;

        #pragma unroll
        for (int ks = 0; ks < 4; ks++) {         // 4 x k16 = 64
            uint32_t a[4][4];
            #pragma unroll
            for (int mt = 0; mt < 4; mt++) {
                const uint32_t* p = uA + mt * (16 * AST) + ks * 8;
                a[mt][0] = p[0];
                a[mt][1] = p[8 * AST];
                a[mt][2] = p[4];
                a[mt][3] = p[8 * AST + 4];
            }
            #pragma unroll
            for (int nt = 0; nt < 8; nt++) {
                const uint32_t* p = uB + nt * (8 * AST) + ks * 8;
                const uint32_t b0 = p[0], b1 = p[4];
                #pragma unroll
                for (int mt = 0; mt < 4; mt++)
                    mma16(acc[mt][nt], a[mt], b0, b1);
            }
        }
    }

    const int lc = 2 * lk;
    #pragma unroll
    for (int nt = 0; nt < 8; nt++) {
        const int col = col0 + wn * 64 + nt * 8 + lc;
        const float bx = bias[col], by = bias[col + 1];
        #pragma unroll
        for (int mt = 0; mt < 4; mt++) {
            const int row = row0 + wm * 64 + mt * 16 + lr;
            #pragma unroll
            for (int h = 0; h < 2; h++) {
                const int r = row + h * 8;
                float vx = acc[mt][nt][2 * h + 0] + bx;
                float vy = acc[mt][nt][2 * h + 1] + by;
                if (OP == 2) {
                    vx = 0.5f * vx * (1.0f + erff(vx * 0.70710678118654752f));
                    vy = 0.5f * vy * (1.0f + erff(vy * 0.70710678118654752f));
                }
                if (OP == 1) {
                    const float* rp = res + (size_t)r * N + col;
                    vx += rp[0]; vy += rp[1];
                }
                if (OP == 0 || OP == 2) {
                    __half2* cp = reinterpret_cast<__half2*>(
                        (__half*)Cv + (size_t)r * N + col);
                    *cp = __halves2half2(__float2half_rn(vx), __float2half_rn(vy));
                } else {
                    *reinterpret_cast<float2*>((float*)Cv + (size_t)r * N + col)
                        = make_float2(vx, vy);
                }
            }
        }
    }
}

// ---------------------------------------------------------------------------
// Flash attention: fp16 QK^T (m16n8k16), tf32 PV, fp32 softmax.
// 256 threads / (b,h,128-row q tile). kv tile = 64.
// Qs/Ks half stride 72 (144B rows); Vs float stride 68; Ps float stride 76.
// ---------------------------------------------------------------------------
#define QLDH 72
#define VLD 68
#define PLD 76
#define ATTN_SMEM ((128 * QLDH + 64 * QLDH) * 2 + (64 * VLD + 128 * PLD) * 4)

__global__ __launch_bounds__(256) void attn_kernel(
    const __half* __restrict__ Q, const __half* __restrict__ K,
    const float* __restrict__ V, __half* __restrict__ O)
{
    extern __shared__ char smc[];
    __half* Qs = reinterpret_cast<__half*>(smc);                    // [128][72]
    __half* Ks = Qs + 128 * QLDH;                                   // [64][72]
    float*  Vs = reinterpret_cast<float*>(Ks + 64 * QLDH);          // [64][68]
    float*  Ps = Vs + 64 * VLD;                                     // [128][76]
    __shared__ float s_alpha[128];

    const int tid = threadIdx.x;
    const int w = tid >> 5, lane = tid & 31;
    const int lr = lane >> 2, lk = lane & 3;
    const int wm = w >> 1, wn = w & 1;
    const int q0 = blockIdx.x * 128;
    const size_t base = (size_t)blockIdx.z * SDIM * EDIM + (size_t)blockIdx.y * 64;

    const uint32_t sQ = smem_u32(Qs), sK = smem_u32(Ks), sV = smem_u32(Vs);

    // Q tile (half): 128 rows x 8 segs of 16B
    #pragma unroll
    for (int u = 0; u < 4; u++) {
        const int idx = u * 256 + tid;
        const int r = idx >> 3, seg = idx & 7;
        cpa16(sQ + (uint32_t)(r * 144 + seg * 16),
              Q + base + (size_t)(q0 + r) * EDIM + seg * 8);
    }
    CP_COMMIT();

    float oacc[2][4][4];
    #pragma unroll
    for (int mt = 0; mt < 2; mt++)
        #pragma unroll
        for (int nt = 0; nt < 4; nt++)
            #pragma unroll
            for (int r = 0; r < 4; r++) oacc[mt][nt][r] = 0.f;
    float m_i = -1e30f, l_i = 0.f;

    const int srow = tid >> 1;
    const int shalf = (tid & 1) * 32;

    for (int kt = 0; kt < 32; kt++) {
        const int k0 = kt * 64;
        // K (half): 64 rows x 8 segs; V (float): 64 rows x 16 segs
        #pragma unroll
        for (int u = 0; u < 2; u++) {
            const int idx = u * 256 + tid;
            const int r = idx >> 3, seg = idx & 7;
            cpa16(sK + (uint32_t)(r * 144 + seg * 16),
                  K + base + (size_t)(k0 + r) * EDIM + seg * 8);
        }
        #pragma unroll
        for (int u = 0; u < 4; u++) {
            const int idx = u * 256 + tid;
            const int r = idx >> 4, seg = idx & 15;
            cpa16(sV + (uint32_t)(r * 272 + seg * 16),
                  V + base + (size_t)(k0 + r) * EDIM + seg * 4);
        }
        CP_COMMIT();
        CP_WAIT0();
        __syncthreads();

        // S = Q @ K^T (fp16, 4 x k16)
        float sacc[2][4][4];
        #pragma unroll
        for (int mt = 0; mt < 2; mt++)
            #pragma unroll
            for (int nt = 0; nt < 4; nt++)
                #pragma unroll
                for (int r = 0; r < 4; r++) sacc[mt][nt][r] = 0.f;

        const uint32_t* uQ = reinterpret_cast<const uint32_t*>(Qs);
        const uint32_t* uK = reinterpret_cast<const uint32_t*>(Ks);
        #pragma unroll
        for (int ks = 0; ks < 4; ks++) {
            uint32_t a[2][4];
            #pragma unroll
            for (int mt = 0; mt < 2; mt++) {
                const uint32_t* p = uQ + (wm * 32 + mt * 16 + lr) * AST + ks * 8 + lk;
                a[mt][0] = p[0];
                a[mt][1] = p[8 * AST];
                a[mt][2] = p[4];
                a[mt][3] = p[8 * AST + 4];
            }
            #pragma unroll
            for (int nt = 0; nt < 4; nt++) {
                const uint32_t* p = uK + (wn * 32 + nt * 8 + lr) * AST + ks * 8 + lk;
                const uint32_t b0 = p[0], b1 = p[4];
                #pragma unroll
                for (int mt = 0; mt < 2; mt++)
                    mma16(sacc[mt][nt], a[mt], b0, b1);
            }
        }
        // scale + scatter to Ps (fp32)
        #pragma unroll
        for (int mt = 0; mt < 2; mt++) {
            const int r0 = wm * 32 + mt * 16 + lr;
            #pragma unroll
            for (int nt = 0; nt < 4; nt++) {
                const int c = wn * 32 + nt * 8 + 2 * lk;
                *reinterpret_cast<float2*>(Ps + r0 * PLD + c)
                    = make_float2(sacc[mt][nt][0] * 0.125f, sacc[mt][nt][1] * 0.125f);
                *reinterpret_cast<float2*>(Ps + (r0 + 8) * PLD + c)
                    = make_float2(sacc[mt][nt][2] * 0.125f, sacc[mt][nt][3] * 0.125f);
            }
        }
        __syncthreads();

        // online softmax: 2 threads per row
        {
            float* pr = Ps + srow * PLD + shalf;
            float mx = -1e30f;
            #pragma unroll 8
            for (int c = 0; c < 32; c++) mx = fmaxf(mx, pr[c]);
            mx = fmaxf(mx, __shfl_xor_sync(0xffffffffu, mx, 1));
            const float mnew  = fmaxf(m_i, mx);
            const float alpha = __expf(m_i - mnew);
            float sum = 0.f;
            #pragma unroll 8
            for (int c = 0; c < 32; c++) {
                const float p = __expf(pr[c] - mnew);
                pr[c] = p;
                sum += p;
            }
            sum += __shfl_xor_sync(0xffffffffu, sum, 1);
            l_i = l_i * alpha + sum;
            m_i = mnew;
            s_alpha[srow] = alpha;
        }
        __syncthreads();

        // O = O*alpha + P @ V  (tf32, P fp32 in Ps, V fp32 row-major)
        #pragma unroll
        for (int mt = 0; mt < 2; mt++) {
            const int r0 = wm * 32 + mt * 16 + lr;
            const float al0 = s_alpha[r0], al1 = s_alpha[r0 + 8];
            #pragma unroll
            for (int nt = 0; nt < 4; nt++) {
                oacc[mt][nt][0] *= al0; oacc[mt][nt][1] *= al0;
                oacc[mt][nt][2] *= al1; oacc[mt][nt][3] *= al1;
            }
        }
        #pragma unroll
        for (int ks = 0; ks < 8; ks++) {
            uint32_t a[2][4];
            #pragma unroll
            for (int mt = 0; mt < 2; mt++) {
                const uint32_t* p = reinterpret_cast<const uint32_t*>(
                    Ps + (wm * 32 + mt * 16 + lr) * PLD + ks * 8 + lk);
                a[mt][0] = p[0];
                a[mt][1] = p[8 * PLD];
                a[mt][2] = p[4];
                a[mt][3] = p[8 * PLD + 4];
            }
            #pragma unroll
            for (int nt = 0; nt < 4; nt++) {
                const uint32_t b0 = *reinterpret_cast<const uint32_t*>(
                    Vs + (ks * 8 + lk) * VLD + wn * 32 + nt * 8 + lr);
                const uint32_t b1 = *reinterpret_cast<const uint32_t*>(
                    Vs + (ks * 8 + lk + 4) * VLD + wn * 32 + nt * 8 + lr);
                #pragma unroll
                for (int mt = 0; mt < 2; mt++)
                    mma8(oacc[mt][nt], a[mt], b0, b1);
            }
        }
        __syncthreads();
    }

    s_alpha[srow] = 1.0f / l_i;
    __syncthreads();

    #pragma unroll
    for (int mt = 0; mt < 2; mt++) {
        const int r0 = wm * 32 + mt * 16 + lr;
        const float inv0 = s_alpha[r0], inv1 = s_alpha[r0 + 8];
        #pragma unroll
        for (int nt = 0; nt < 4; nt++) {
            const int c = wn * 32 + nt * 8 + 2 * lk;
            __half2* p0 = reinterpret_cast<__half2*>(
                O + base + (size_t)(q0 + r0) * EDIM + c);
            __half2* p1 = reinterpret_cast<__half2*>(
                O + base + (size_t)(q0 + r0 + 8) * EDIM + c);
            *p0 = __halves2half2(__float2half_rn(oacc[mt][nt][0] * inv0),
                                 __float2half_rn(oacc[mt][nt][1] * inv0));
            *p1 = __halves2half2(__float2half_rn(oacc[mt][nt][2] * inv1),
                                 __float2half_rn(oacc[mt][nt][3] * inv1));
        }
    }
}

// ---------------------------------------------------------------------------
extern "C" void kernel_launch(void* const* d_in, const int* in_sizes, int n_in,
                              void* d_out, int out_size)
{
    const float* inp   = (const float*)d_in[0];
    const float* ln1_g = (const float*)d_in[1];
    const float* ln1_b = (const float*)d_in[2];
    const float* Wq    = (const float*)d_in[3];
    const float* bq    = (const float*)d_in[4];
    const float* Wk    = (const float*)d_in[5];
    const float* bk    = (const float*)d_in[6];
    const float* Wv    = (const float*)d_in[7];
    const float* bv    = (const float*)d_in[8];
    const float* Wo    = (const float*)d_in[9];
    const float* bo    = (const float*)d_in[10];
    const float* ln2_g = (const float*)d_in[11];
    const float* ln2_b = (const float*)d_in[12];
    const float* W1    = (const float*)d_in[13];
    const float* b1    = (const float*)d_in[14];
    const float* W2    = (const float*)d_in[15];
    const float* b2    = (const float*)d_in[16];
    float* out = (float*)d_out;

    __half *xln1h, *q, *k, *ctx, *x3h, *h1, *wtq, *wtk, *wtv, *wto, *wt1, *wt2;
    float *xln1f, *v, *x2, *x3f;
    cudaGetSymbolAddress((void**)&xln1h, g_xln1h);
    cudaGetSymbolAddress((void**)&xln1f, g_xln1f);
    cudaGetSymbolAddress((void**)&q,    g_q);
    cudaGetSymbolAddress((void**)&k,    g_k);
    cudaGetSymbolAddress((void**)&v,    g_v);
    cudaGetSymbolAddress((void**)&ctx,  g_ctx);
    cudaGetSymbolAddress((void**)&x2,   g_x2);
    cudaGetSymbolAddress((void**)&x3h,  g_x3h);
    cudaGetSymbolAddress((void**)&x3f,  g_x3f);
    cudaGetSymbolAddress((void**)&h1,   g_h1);
    cudaGetSymbolAddress((void**)&wtq,  g_wtq);
    cudaGetSymbolAddress((void**)&wtk,  g_wtk);
    cudaGetSymbolAddress((void**)&wtv,  g_wtv);
    cudaGetSymbolAddress((void**)&wto,  g_wto);
    cudaGetSymbolAddress((void**)&wt1,  g_wt1);
    cudaGetSymbolAddress((void**)&wt2,  g_wt2);

    cudaFuncSetAttribute(attn_kernel,
                         cudaFuncAttributeMaxDynamicSharedMemorySize, ATTN_SMEM);
    cudaFuncSetAttribute(mm_gemm<0>,
                         cudaFuncAttributeMaxDynamicSharedMemorySize, GEMM_SMEM);
    cudaFuncSetAttribute(mm_gemm<1>,
                         cudaFuncAttributeMaxDynamicSharedMemorySize, GEMM_SMEM);
    cudaFuncSetAttribute(mm_gemm<2>,
                         cudaFuncAttributeMaxDynamicSharedMemorySize, GEMM_SMEM);
    cudaFuncSetAttribute(mm_gemm<3>,
                         cudaFuncAttributeMaxDynamicSharedMemorySize, GEMM_SMEM);

    // 0. weight transposes (one launch)
    transpose_all<<<dim3(64, 64, 6), 256>>>(Wq, Wk, Wv, Wo, W1, W2,
                                            wtq, wtk, wtv, wto, wt1, wt2);
    // 1. LN1
    ln_kernel<<<MDIM, 256>>>(inp, ln1_g, ln1_b, xln1h, xln1f);

    // 2. QKV  (q,k half out; v float out for tf32 PV)
    dim3 gE(EDIM / 128, MDIM / 128);
    mm_gemm<0><<<gE, 128, GEMM_SMEM>>>(xln1h, wtq, bq, nullptr, q, MDIM, EDIM, EDIM);
    mm_gemm<0><<<gE, 128, GEMM_SMEM>>>(xln1h, wtk, bk, nullptr, k, MDIM, EDIM, EDIM);
    mm_gemm<3><<<gE, 128, GEMM_SMEM>>>(xln1h, wtv, bv, nullptr, v, MDIM, EDIM, EDIM);

    // 3. Attention -> ctx (half)
    dim3 gA(SDIM / 128, HDIM, BDIM);
    attn_kernel<<<gA, 256, ATTN_SMEM>>>(q, k, v, ctx);

    // 4. O-proj + residual(LN1 full) -> x2 (float)
    mm_gemm<1><<<gE, 128, GEMM_SMEM>>>(ctx, wto, bo, xln1f, x2, MDIM, EDIM, EDIM);

    // 5. LN2
    ln_kernel<<<MDIM, 256>>>(x2, ln2_g, ln2_b, x3h, x3f);

    // 6. MLP
    dim3 gF(FDIM / 128, MDIM / 128);
    mm_gemm<2><<<gF, 128, GEMM_SMEM>>>(x3h, wt1, b1, nullptr, h1, MDIM, FDIM, EDIM);
    mm_gemm<1><<<gE, 128, GEMM_SMEM>>>(h1, wt2, b2, x3f, out, MDIM, EDIM, FDIM);
}

// round 8
// speedup vs baseline: 4.1380x; 1.0298x over previous
#include <cuda_runtime.h>
#include <cuda_fp16.h>
#include <math.h>
#include <stdint.h>

// ---------------------------------------------------------------------------
// TransformerBlock B=4,S=2048,E=1024,H=16,D=64.
// R8: fragment loads via ldmatrix.x4 (GEMM A/B + attention Q/K).
// fp16 m16n8k16 GEMMs (fp32 accum), 128x128 CTA / 4 warps / 3 CTA/SM.
// ---------------------------------------------------------------------------

#define MDIM 8192
#define EDIM 1024
#define SDIM 2048
#define BDIM 4
#define HDIM 16
#define FDIM 2048

__device__ __half g_xln1h[MDIM * EDIM];
__device__ float  g_xln1f[MDIM * EDIM];
__device__ __half g_q  [MDIM * EDIM];
__device__ __half g_k  [MDIM * EDIM];
__device__ float  g_v  [MDIM * EDIM];
__device__ __half g_ctx[MDIM * EDIM];
__device__ float  g_x2 [MDIM * EDIM];
__device__ __half g_x3h[MDIM * EDIM];
__device__ float  g_x3f[MDIM * EDIM];
__device__ __half g_h1 [MDIM * FDIM];
__device__ __half g_wtq[EDIM * EDIM];
__device__ __half g_wtk[EDIM * EDIM];
__device__ __half g_wtv[EDIM * EDIM];
__device__ __half g_wto[EDIM * EDIM];
__device__ __half g_wt1[FDIM * EDIM];
__device__ __half g_wt2[EDIM * FDIM];

// ---------------------------------------------------------------------------
__device__ __forceinline__ uint32_t smem_u32(const void* p) {
    uint32_t a;
    asm("{ .reg .u64 t; cvta.to.shared.u64 t, %1; cvt.u32.u64 %0, t; }"
        : "=r"(a) : "l"(p));
    return a;
}
__device__ __forceinline__ void cpa16(uint32_t s, const void* g) {
    asm volatile("cp.async.cg.shared.global [%0], [%1], 16;" :: "r"(s), "l"(g));
}
#define CP_COMMIT() asm volatile("cp.async.commit_group;" ::: "memory")
#define CP_WAIT0()  asm volatile("cp.async.wait_group 0;" ::: "memory")
#define CP_WAIT1()  asm volatile("cp.async.wait_group 1;" ::: "memory")

// fp16 MMA, fp32 accumulate
__device__ __forceinline__ void mma16(float* c, const uint32_t* a,
                                      uint32_t b0, uint32_t b1) {
    asm volatile(
        "mma.sync.aligned.m16n8k16.row.col.f32.f16.f16.f32 "
        "{%0,%1,%2,%3}, {%4,%5,%6,%7}, {%8,%9}, {%0,%1,%2,%3};"
        : "+f"(c[0]), "+f"(c[1]), "+f"(c[2]), "+f"(c[3])
        : "r"(a[0]), "r"(a[1]), "r"(a[2]), "r"(a[3]), "r"(b0), "r"(b1));
}
// tf32 MMA (PV path)
__device__ __forceinline__ void mma8(float* c, const uint32_t* a,
                                     uint32_t b0, uint32_t b1) {
    asm volatile(
        "mma.sync.aligned.m16n8k8.row.col.f32.tf32.tf32.f32 "
        "{%0,%1,%2,%3}, {%4,%5,%6,%7}, {%8,%9}, {%0,%1,%2,%3};"
        : "+f"(c[0]), "+f"(c[1]), "+f"(c[2]), "+f"(c[3])
        : "r"(a[0]), "r"(a[1]), "r"(a[2]), "r"(a[3]), "r"(b0), "r"(b1));
}
// ldmatrix x4: four 8x8 f16 tiles
__device__ __forceinline__ void ldsm4(uint32_t* r, uint32_t addr) {
    asm volatile("ldmatrix.sync.aligned.m8n8.x4.shared.b16 {%0,%1,%2,%3}, [%4];"
        : "=r"(r[0]), "=r"(r[1]), "=r"(r[2]), "=r"(r[3]) : "r"(addr));
}

// ---------------------------------------------------------------------------
// All 6 weight transposes in ONE launch. WT[n*K+k] = half(W[k*N+n])
// ---------------------------------------------------------------------------
__global__ __launch_bounds__(256) void transpose_all(
    const float* __restrict__ Wq, const float* __restrict__ Wk,
    const float* __restrict__ Wv, const float* __restrict__ Wo,
    const float* __restrict__ W1, const float* __restrict__ W2,
    __half* __restrict__ wtq, __half* __restrict__ wtk,
    __half* __restrict__ wtv, __half* __restrict__ wto,
    __half* __restrict__ wt1, __half* __restrict__ wt2)
{
    const float* W; __half* WT; int K, N;
    switch (blockIdx.z) {
        case 0: W = Wq; WT = wtq; K = EDIM; N = EDIM; break;
        case 1: W = Wk; WT = wtk; K = EDIM; N = EDIM; break;
        case 2: W = Wv; WT = wtv; K = EDIM; N = EDIM; break;
        case 3: W = Wo; WT = wto; K = EDIM; N = EDIM; break;
        case 4: W = W1; WT = wt1; K = EDIM; N = FDIM; break;
        default: W = W2; WT = wt2; K = FDIM; N = EDIM; break;
    }
    const int n0 = blockIdx.x * 32, k0 = blockIdx.y * 32;
    if (n0 >= N || k0 >= K) return;
    __shared__ float t[32][33];
    const int x = threadIdx.x & 31, y = threadIdx.x >> 5;
    #pragma unroll
    for (int i = 0; i < 32; i += 8)
        t[y + i][x] = W[(size_t)(k0 + y + i) * N + n0 + x];
    __syncthreads();
    #pragma unroll
    for (int i = 0; i < 32; i += 8)
        WT[(size_t)(n0 + y + i) * K + k0 + x] = __float2half_rn(t[x][y + i]);
}

// ---------------------------------------------------------------------------
// LayerNorm: half copy (yh, GEMM input) + full fp32 copy (yf, residual)
// ---------------------------------------------------------------------------
__global__ __launch_bounds__(256) void ln_kernel(
    const float* __restrict__ x, const float* __restrict__ g,
    const float* __restrict__ b, __half* __restrict__ yh, float* __restrict__ yf)
{
    const int row = blockIdx.x;
    const int tid = threadIdx.x;
    const float4 v = reinterpret_cast<const float4*>(x + (size_t)row * EDIM)[tid];

    float s  = v.x + v.y + v.z + v.w;
    float ss = v.x * v.x + v.y * v.y + v.z * v.z + v.w * v.w;
    #pragma unroll
    for (int off = 16; off > 0; off >>= 1) {
        s  += __shfl_down_sync(0xffffffffu, s,  off);
        ss += __shfl_down_sync(0xffffffffu, ss, off);
    }
    __shared__ float wsum[8], wsq[8];
    __shared__ float s_mu, s_rstd;
    const int wid = tid >> 5, lane = tid & 31;
    if (lane == 0) { wsum[wid] = s; wsq[wid] = ss; }
    __syncthreads();
    if (tid == 0) {
        float ts = 0.f, tss = 0.f;
        #pragma unroll
        for (int i = 0; i < 8; i++) { ts += wsum[i]; tss += wsq[i]; }
        const float mu  = ts * (1.0f / EDIM);
        const float var = tss * (1.0f / EDIM) - mu * mu;
        s_mu = mu; s_rstd = rsqrtf(var + 1e-5f);
    }
    __syncthreads();
    const float mu = s_mu, rstd = s_rstd;
    const float4 gv = reinterpret_cast<const float4*>(g)[tid];
    const float4 bv = reinterpret_cast<const float4*>(b)[tid];
    float4 o;
    o.x = (v.x - mu) * rstd * gv.x + bv.x;
    o.y = (v.y - mu) * rstd * gv.y + bv.y;
    o.z = (v.z - mu) * rstd * gv.z + bv.z;
    o.w = (v.w - mu) * rstd * gv.w + bv.w;
    reinterpret_cast<float4*>(yf + (size_t)row * EDIM)[tid] = o;
    __half2* hp = reinterpret_cast<__half2*>(yh + (size_t)row * EDIM);
    hp[2 * tid + 0] = __halves2half2(__float2half_rn(o.x), __float2half_rn(o.y));
    hp[2 * tid + 1] = __halves2half2(__float2half_rn(o.z), __float2half_rn(o.w));
}

// ---------------------------------------------------------------------------
// fp16 GEMM: C[M,N] = A[M,K] @ Bt[N,K]^T + bias (+epilogue).
// CTA 128x128, 128 thr (4 warps 2x2, warp tile 64x64), KCH=64, 2 stages,
// ldmatrix.x4 fragment loads. 3 CTA/SM.
// OP: 0 half out (bias); 1 float out (bias+residual);
//     2 half out (bias+GELU); 3 float out (bias)
// ---------------------------------------------------------------------------
#define KCH 64
#define AST 36                         // uint32 per smem row (72 halves = 144B)
#define TILE_U32 (128 * AST)
#define STG_U32 (2 * TILE_U32)
#define GEMM_SMEM (2 * STG_U32 * 4)    // 73728 B

template <int OP>
__global__ __launch_bounds__(128, 3) void mm_gemm(
    const __half* __restrict__ A, const __half* __restrict__ Bt,
    const float* __restrict__ bias, const float* __restrict__ res,
    void* __restrict__ Cv, int M, int N, int K)
{
    extern __shared__ uint32_t sm[];
    const int tid = threadIdx.x;
    const int wid = tid >> 5, lane = tid & 31;
    const int row0 = blockIdx.y * 128, col0 = blockIdx.x * 128;

    // copy mapping: thread t -> A row t, B row t; 8 x 16B segments each
    const __half* gA = A  + (size_t)(row0 + tid) * K;
    const __half* gB = Bt + (size_t)(col0 + tid) * K;
    const uint32_t sm0 = smem_u32(sm);
    const uint32_t dA = sm0 + (uint32_t)(tid * 144);
    const uint32_t dB = sm0 + (uint32_t)(TILE_U32 * 4 + tid * 144);

    const int nch = K / KCH;

    // prologue: chunk 0 -> stage 0
    #pragma unroll
    for (int u = 0; u < 8; u++) {
        cpa16(dA + u * 16u, gA + u * 8);
        cpa16(dB + u * 16u, gB + u * 8);
    }
    CP_COMMIT();

    const int wm = wid & 1, wn = wid >> 1;
    // ldmatrix lane addressing:
    // A (16x16 tile): lanes 0-15 rows, 16-31 rows at k+8 halves
    const uint32_t aAddr = sm0
        + (uint32_t)((wm * 64 + (lane & 15)) * 144 + (lane >> 4) * 16);
    // B (pair of 8-col n tiles): lanes 0-15 -> ntE (k0|k8), 16-31 -> ntO
    const uint32_t bAddr = sm0 + (uint32_t)(TILE_U32 * 4)
        + (uint32_t)((wn * 64 + (lane & 7) + ((lane >> 4) << 3)) * 144
                     + ((lane >> 3) & 1) * 16);

    float acc[4][8][4];
    #pragma unroll
    for (int mt = 0; mt < 4; mt++)
        #pragma unroll
        for (int nt = 0; nt < 8; nt++)
            #pragma unroll
            for (int r = 0; r < 4; r++) acc[mt][nt][r] = 0.f;

    for (int i = 0; i < nch; i++) {
        __syncthreads();                         // prev compute done on other stage
        const int j = i + 1;
        if (j < nch) {
            const uint32_t so = (uint32_t)((j & 1) * STG_U32) * 4u;
            #pragma unroll
            for (int u = 0; u < 8; u++) {
                cpa16(dA + so + u * 16u, gA + j * KCH + u * 8);
                cpa16(dB + so + u * 16u, gB + j * KCH + u * 8);
            }
        }
        CP_COMMIT();
        CP_WAIT1();                              // chunk i resident
        __syncthreads();

        const uint32_t st = (uint32_t)((i & 1) * STG_U32) * 4u;

        #pragma unroll
        for (int ks = 0; ks < 4; ks++) {         // 4 x k16 = 64
            uint32_t a[4][4];
            #pragma unroll
            for (int mt = 0; mt < 4; mt++)
                ldsm4(a[mt], aAddr + st + mt * (16 * 144) + ks * 32);
            #pragma unroll
            for (int pr = 0; pr < 4; pr++) {     // nt pair: 2*pr, 2*pr+1
                uint32_t b[4];
                ldsm4(b, bAddr + st + pr * (16 * 144) + ks * 32);
                #pragma unroll
                for (int mt = 0; mt < 4; mt++)
                    mma16(acc[mt][2 * pr], a[mt], b[0], b[1]);
                #pragma unroll
                for (int mt = 0; mt < 4; mt++)
                    mma16(acc[mt][2 * pr + 1], a[mt], b[2], b[3]);
            }
        }
    }

    const int lr = lane >> 2, lk = lane & 3;
    const int lc = 2 * lk;
    #pragma unroll
    for (int nt = 0; nt < 8; nt++) {
        const int col = col0 + wn * 64 + nt * 8 + lc;
        const float bx = bias[col], by = bias[col + 1];
        #pragma unroll
        for (int mt = 0; mt < 4; mt++) {
            const int row = row0 + wm * 64 + mt * 16 + lr;
            #pragma unroll
            for (int h = 0; h < 2; h++) {
                const int r = row + h * 8;
                float vx = acc[mt][nt][2 * h + 0] + bx;
                float vy = acc[mt][nt][2 * h + 1] + by;
                if (OP == 2) {
                    vx = 0.5f * vx * (1.0f + erff(vx * 0.70710678118654752f));
                    vy = 0.5f * vy * (1.0f + erff(vy * 0.70710678118654752f));
                }
                if (OP == 1) {
                    const float* rp = res + (size_t)r * N + col;
                    vx += rp[0]; vy += rp[1];
                }
                if (OP == 0 || OP == 2) {
                    __half2* cp = reinterpret_cast<__half2*>(
                        (__half*)Cv + (size_t)r * N + col);
                    *cp = __halves2half2(__float2half_rn(vx), __float2half_rn(vy));
                } else {
                    *reinterpret_cast<float2*>((float*)Cv + (size_t)r * N + col)
                        = make_float2(vx, vy);
                }
            }
        }
    }
}

// ---------------------------------------------------------------------------
// Flash attention: fp16 QK^T (ldmatrix + m16n8k16), tf32 PV, fp32 softmax.
// 256 threads / (b,h,128-row q tile). kv tile = 64.
// ---------------------------------------------------------------------------
#define QLDH 72
#define VLD 68
#define PLD 76
#define ATTN_SMEM ((128 * QLDH + 64 * QLDH) * 2 + (64 * VLD + 128 * PLD) * 4)

__global__ __launch_bounds__(256) void attn_kernel(
    const __half* __restrict__ Q, const __half* __restrict__ K,
    const float* __restrict__ V, __half* __restrict__ O)
{
    extern __shared__ char smc[];
    __half* Qs = reinterpret_cast<__half*>(smc);                    // [128][72]
    __half* Ks = Qs + 128 * QLDH;                                   // [64][72]
    float*  Vs = reinterpret_cast<float*>(Ks + 64 * QLDH);          // [64][68]
    float*  Ps = Vs + 64 * VLD;                                     // [128][76]
    __shared__ float s_alpha[128];

    const int tid = threadIdx.x;
    const int w = tid >> 5, lane = tid & 31;
    const int lr = lane >> 2, lk = lane & 3;
    const int wm = w >> 1, wn = w & 1;
    const int q0 = blockIdx.x * 128;
    const size_t base = (size_t)blockIdx.z * SDIM * EDIM + (size_t)blockIdx.y * 64;

    const uint32_t sQ = smem_u32(Qs), sK = smem_u32(Ks), sV = smem_u32(Vs);

    // Q tile (half): 128 rows x 8 segs of 16B
    #pragma unroll
    for (int u = 0; u < 4; u++) {
        const int idx = u * 256 + tid;
        const int r = idx >> 3, seg = idx & 7;
        cpa16(sQ + (uint32_t)(r * 144 + seg * 16),
              Q + base + (size_t)(q0 + r) * EDIM + seg * 8);
    }
    CP_COMMIT();

    // ldmatrix addresses (QK^T)
    const uint32_t qAddr = sQ
        + (uint32_t)((wm * 32 + (lane & 15)) * 144 + (lane >> 4) * 16);
    const uint32_t kAddr = sK
        + (uint32_t)((wn * 32 + (lane & 7) + ((lane >> 4) << 3)) * 144
                     + ((lane >> 3) & 1) * 16);

    float oacc[2][4][4];
    #pragma unroll
    for (int mt = 0; mt < 2; mt++)
        #pragma unroll
        for (int nt = 0; nt < 4; nt++)
            #pragma unroll
            for (int r = 0; r < 4; r++) oacc[mt][nt][r] = 0.f;
    float m_i = -1e30f, l_i = 0.f;

    const int srow = tid >> 1;
    const int shalf = (tid & 1) * 32;

    for (int kt = 0; kt < 32; kt++) {
        const int k0 = kt * 64;
        #pragma unroll
        for (int u = 0; u < 2; u++) {
            const int idx = u * 256 + tid;
            const int r = idx >> 3, seg = idx & 7;
            cpa16(sK + (uint32_t)(r * 144 + seg * 16),
                  K + base + (size_t)(k0 + r) * EDIM + seg * 8);
        }
        #pragma unroll
        for (int u = 0; u < 4; u++) {
            const int idx = u * 256 + tid;
            const int r = idx >> 4, seg = idx & 15;
            cpa16(sV + (uint32_t)(r * 272 + seg * 16),
                  V + base + (size_t)(k0 + r) * EDIM + seg * 4);
        }
        CP_COMMIT();
        CP_WAIT0();
        __syncthreads();

        // S = Q @ K^T (fp16, ldmatrix)
        float sacc[2][4][4];
        #pragma unroll
        for (int mt = 0; mt < 2; mt++)
            #pragma unroll
            for (int nt = 0; nt < 4; nt++)
                #pragma unroll
                for (int r = 0; r < 4; r++) sacc[mt][nt][r] = 0.f;

        #pragma unroll
        for (int ks = 0; ks < 4; ks++) {
            uint32_t a[2][4];
            #pragma unroll
            for (int mt = 0; mt < 2; mt++)
                ldsm4(a[mt], qAddr + mt * (16 * 144) + ks * 32);
            #pragma unroll
            for (int pr = 0; pr < 2; pr++) {
                uint32_t b[4];
                ldsm4(b, kAddr + pr * (16 * 144) + ks * 32);
                #pragma unroll
                for (int mt = 0; mt < 2; mt++)
                    mma16(sacc[mt][2 * pr], a[mt], b[0], b[1]);
                #pragma unroll
                for (int mt = 0; mt < 2; mt++)
                    mma16(sacc[mt][2 * pr + 1], a[mt], b[2], b[3]);
            }
        }
        // scale + scatter to Ps (fp32)
        #pragma unroll
        for (int mt = 0; mt < 2; mt++) {
            const int r0 = wm * 32 + mt * 16 + lr;
            #pragma unroll
            for (int nt = 0; nt < 4; nt++) {
                const int c = wn * 32 + nt * 8 + 2 * lk;
                *reinterpret_cast<float2*>(Ps + r0 * PLD + c)
                    = make_float2(sacc[mt][nt][0] * 0.125f, sacc[mt][nt][1] * 0.125f);
                *reinterpret_cast<float2*>(Ps + (r0 + 8) * PLD + c)
                    = make_float2(sacc[mt][nt][2] * 0.125f, sacc[mt][nt][3] * 0.125f);
            }
        }
        __syncthreads();

        // online softmax: 2 threads per row
        {
            float* pr = Ps + srow * PLD + shalf;
            float mx = -1e30f;
            #pragma unroll 8
            for (int c = 0; c < 32; c++) mx = fmaxf(mx, pr[c]);
            mx = fmaxf(mx, __shfl_xor_sync(0xffffffffu, mx, 1));
            const float mnew  = fmaxf(m_i, mx);
            const float alpha = __expf(m_i - mnew);
            float sum = 0.f;
            #pragma unroll 8
            for (int c = 0; c < 32; c++) {
                const float p = __expf(pr[c] - mnew);
                pr[c] = p;
                sum += p;
            }
            sum += __shfl_xor_sync(0xffffffffu, sum, 1);
            l_i = l_i * alpha + sum;
            m_i = mnew;
            s_alpha[srow] = alpha;
        }
        __syncthreads();

        // O = O*alpha + P @ V  (tf32, P fp32 in Ps, V fp32 row-major)
        #pragma unroll
        for (int mt = 0; mt < 2; mt++) {
            const int r0 = wm * 32 + mt * 16 + lr;
            const float al0 = s_alpha[r0], al1 = s_alpha[r0 + 8];
            #pragma unroll
            for (int nt = 0; nt < 4; nt++) {
                oacc[mt][nt][0] *= al0; oacc[mt][nt][1] *= al0;
                oacc[mt][nt][2] *= al1; oacc[mt][nt][3] *= al1;
            }
        }
        #pragma unroll
        for (int ks = 0; ks < 8; ks++) {
            uint32_t a[2][4];
            #pragma unroll
            for (int mt = 0; mt < 2; mt++) {
                const uint32_t* p = reinterpret_cast<const uint32_t*>(
                    Ps + (wm * 32 + mt * 16 + lr) * PLD + ks * 8 + lk);
                a[mt][0] = p[0];
                a[mt][1] = p[8 * PLD];
                a[mt][2] = p[4];
                a[mt][3] = p[8 * PLD + 4];
            }
            #pragma unroll
            for (int nt = 0; nt < 4; nt++) {
                const uint32_t b0 = *reinterpret_cast<const uint32_t*>(
                    Vs + (ks * 8 + lk) * VLD + wn * 32 + nt * 8 + lr);
                const uint32_t b1 = *reinterpret_cast<const uint32_t*>(
                    Vs + (ks * 8 + lk + 4) * VLD + wn * 32 + nt * 8 + lr);
                #pragma unroll
                for (int mt = 0; mt < 2; mt++)
                    mma8(oacc[mt][nt], a[mt], b0, b1);
            }
        }
        __syncthreads();
    }

    s_alpha[srow] = 1.0f / l_i;
    __syncthreads();

    #pragma unroll
    for (int mt = 0; mt < 2; mt++) {
        const int r0 = wm * 32 + mt * 16 + lr;
        const float inv0 = s_alpha[r0], inv1 = s_alpha[r0 + 8];
        #pragma unroll
        for (int nt = 0; nt < 4; nt++) {
            const int c = wn * 32 + nt * 8 + 2 * lk;
            __half2* p0 = reinterpret_cast<__half2*>(
                O + base + (size_t)(q0 + r0) * EDIM + c);
            __half2* p1 = reinterpret_cast<__half2*>(
                O + base + (size_t)(q0 + r0 + 8) * EDIM + c);
            *p0 = __halves2half2(__float2half_rn(oacc[mt][nt][0] * inv0),
                                 __float2half_rn(oacc[mt][nt][1] * inv0));
            *p1 = __halves2half2(__float2half_rn(oacc[mt][nt][2] * inv1),
                                 __float2half_rn(oacc[mt][nt][3] * inv1));
        }
    }
}

// ---------------------------------------------------------------------------
extern "C" void kernel_launch(void* const* d_in, const int* in_sizes, int n_in,
                              void* d_out, int out_size)
{
    const float* inp   = (const float*)d_in[0];
    const float* ln1_g = (const float*)d_in[1];
    const float* ln1_b = (const float*)d_in[2];
    const float* Wq    = (const float*)d_in[3];
    const float* bq    = (const float*)d_in[4];
    const float* Wk    = (const float*)d_in[5];
    const float* bk    = (const float*)d_in[6];
    const float* Wv    = (const float*)d_in[7];
    const float* bv    = (const float*)d_in[8];
    const float* Wo    = (const float*)d_in[9];
    const float* bo    = (const float*)d_in[10];
    const float* ln2_g = (const float*)d_in[11];
    const float* ln2_b = (const float*)d_in[12];
    const float* W1    = (const float*)d_in[13];
    const float* b1    = (const float*)d_in[14];
    const float* W2    = (const float*)d_in[15];
    const float* b2    = (const float*)d_in[16];
    float* out = (float*)d_out;

    __half *xln1h, *q, *k, *ctx, *x3h, *h1, *wtq, *wtk, *wtv, *wto, *wt1, *wt2;
    float *xln1f, *v, *x2, *x3f;
    cudaGetSymbolAddress((void**)&xln1h, g_xln1h);
    cudaGetSymbolAddress((void**)&xln1f, g_xln1f);
    cudaGetSymbolAddress((void**)&q,    g_q);
    cudaGetSymbolAddress((void**)&k,    g_k);
    cudaGetSymbolAddress((void**)&v,    g_v);
    cudaGetSymbolAddress((void**)&ctx,  g_ctx);
    cudaGetSymbolAddress((void**)&x2,   g_x2);
    cudaGetSymbolAddress((void**)&x3h,  g_x3h);
    cudaGetSymbolAddress((void**)&x3f,  g_x3f);
    cudaGetSymbolAddress((void**)&h1,   g_h1);
    cudaGetSymbolAddress((void**)&wtq,  g_wtq);
    cudaGetSymbolAddress((void**)&wtk,  g_wtk);
    cudaGetSymbolAddress((void**)&wtv,  g_wtv);
    cudaGetSymbolAddress((void**)&wto,  g_wto);
    cudaGetSymbolAddress((void**)&wt1,  g_wt1);
    cudaGetSymbolAddress((void**)&wt2,  g_wt2);

    cudaFuncSetAttribute(attn_kernel,
                         cudaFuncAttributeMaxDynamicSharedMemorySize, ATTN_SMEM);
    cudaFuncSetAttribute(mm_gemm<0>,
                         cudaFuncAttributeMaxDynamicSharedMemorySize, GEMM_SMEM);
    cudaFuncSetAttribute(mm_gemm<1>,
                         cudaFuncAttributeMaxDynamicSharedMemorySize, GEMM_SMEM);
    cudaFuncSetAttribute(mm_gemm<2>,
                         cudaFuncAttributeMaxDynamicSharedMemorySize, GEMM_SMEM);
    cudaFuncSetAttribute(mm_gemm<3>,
                         cudaFuncAttributeMaxDynamicSharedMemorySize, GEMM_SMEM);

    // 0. weight transposes (one launch)
    transpose_all<<<dim3(64, 64, 6), 256>>>(Wq, Wk, Wv, Wo, W1, W2,
                                            wtq, wtk, wtv, wto, wt1, wt2);
    // 1. LN1
    ln_kernel<<<MDIM, 256>>>(inp, ln1_g, ln1_b, xln1h, xln1f);

    // 2. QKV  (q,k half out; v float out for tf32 PV)
    dim3 gE(EDIM / 128, MDIM / 128);
    mm_gemm<0><<<gE, 128, GEMM_SMEM>>>(xln1h, wtq, bq, nullptr, q, MDIM, EDIM, EDIM);
    mm_gemm<0><<<gE, 128, GEMM_SMEM>>>(xln1h, wtk, bk, nullptr, k, MDIM, EDIM, EDIM);
    mm_gemm<3><<<gE, 128, GEMM_SMEM>>>(xln1h, wtv, bv, nullptr, v, MDIM, EDIM, EDIM);

    // 3. Attention -> ctx (half)
    dim3 gA(SDIM / 128, HDIM, BDIM);
    attn_kernel<<<gA, 256, ATTN_SMEM>>>(q, k, v, ctx);

    // 4. O-proj + residual(LN1 full) -> x2 (float)
    mm_gemm<1><<<gE, 128, GEMM_SMEM>>>(ctx, wto, bo, xln1f, x2, MDIM, EDIM, EDIM);

    // 5. LN2
    ln_kernel<<<MDIM, 256>>>(x2, ln2_g, ln2_b, x3h, x3f);

    // 6. MLP
    dim3 gF(FDIM / 128, MDIM / 128);
    mm_gemm<2><<<gF, 128, GEMM_SMEM>>>(x3h, wt1, b1, nullptr, h1, MDIM, FDIM, EDIM);
    mm_gemm<1><<<gE, 128, GEMM_SMEM>>>(h1, wt2, b2, x3f, out, MDIM, EDIM, FDIM);
}

// round 10
// speedup vs baseline: 5.1627x; 1.2476x over previous
#include <cuda_runtime.h>
#include <cuda_fp16.h>
#include <math.h>
#include <stdint.h>

// ---------------------------------------------------------------------------
// TransformerBlock B=4,S=2048,E=1024,H=16,D=64.
// R10 (= R9 resubmit after infra failure):
//   GEMM 4-stage cp.async pipeline (prefetch 3 ahead, XOR-swizzled smem);
//   attention FA2-style: register softmax, fp16 P@V via ldmatrix.trans,
//   K/V double buffered. All matmuls fp16 with fp32 accumulation.
// ---------------------------------------------------------------------------

#define MDIM 8192
#define EDIM 1024
#define SDIM 2048
#define BDIM 4
#define HDIM 16
#define FDIM 2048

__device__ __half g_xln1h[MDIM * EDIM];
__device__ float  g_xln1f[MDIM * EDIM];
__device__ __half g_q  [MDIM * EDIM];
__device__ __half g_k  [MDIM * EDIM];
__device__ __half g_v  [MDIM * EDIM];
__device__ __half g_ctx[MDIM * EDIM];
__device__ float  g_x2 [MDIM * EDIM];
__device__ __half g_x3h[MDIM * EDIM];
__device__ float  g_x3f[MDIM * EDIM];
__device__ __half g_h1 [MDIM * FDIM];
__device__ __half g_wtq[EDIM * EDIM];
__device__ __half g_wtk[EDIM * EDIM];
__device__ __half g_wtv[EDIM * EDIM];
__device__ __half g_wto[EDIM * EDIM];
__device__ __half g_wt1[FDIM * EDIM];
__device__ __half g_wt2[EDIM * FDIM];

// ---------------------------------------------------------------------------
__device__ __forceinline__ uint32_t smem_u32(const void* p) {
    uint32_t a;
    asm("{ .reg .u64 t; cvta.to.shared.u64 t, %1; cvt.u32.u64 %0, t; }"
        : "=r"(a) : "l"(p));
    return a;
}
__device__ __forceinline__ void cpa16(uint32_t s, const void* g) {
    asm volatile("cp.async.cg.shared.global [%0], [%1], 16;" :: "r"(s), "l"(g));
}
#define CP_COMMIT() asm volatile("cp.async.commit_group;" ::: "memory")
#define CP_WAIT1()  asm volatile("cp.async.wait_group 1;" ::: "memory")
#define CP_WAIT3()  asm volatile("cp.async.wait_group 3;" ::: "memory")

__device__ __forceinline__ void mma16(float* c, const uint32_t* a,
                                      uint32_t b0, uint32_t b1) {
    asm volatile(
        "mma.sync.aligned.m16n8k16.row.col.f32.f16.f16.f32 "
        "{%0,%1,%2,%3}, {%4,%5,%6,%7}, {%8,%9}, {%0,%1,%2,%3};"
        : "+f"(c[0]), "+f"(c[1]), "+f"(c[2]), "+f"(c[3])
        : "r"(a[0]), "r"(a[1]), "r"(a[2]), "r"(a[3]), "r"(b0), "r"(b1));
}
__device__ __forceinline__ void ldsm4(uint32_t* r, uint32_t addr) {
    asm volatile("ldmatrix.sync.aligned.m8n8.x4.shared.b16 {%0,%1,%2,%3}, [%4];"
        : "=r"(r[0]), "=r"(r[1]), "=r"(r[2]), "=r"(r[3]) : "r"(addr));
}
__device__ __forceinline__ void ldsm4t(uint32_t* r, uint32_t addr) {
    asm volatile("ldmatrix.sync.aligned.m8n8.x4.trans.shared.b16 {%0,%1,%2,%3}, [%4];"
        : "=r"(r[0]), "=r"(r[1]), "=r"(r[2]), "=r"(r[3]) : "r"(addr));
}
__device__ __forceinline__ uint32_t pkhalf(float x, float y) {
    __half2 h = __floats2half2_rn(x, y);
    return *reinterpret_cast<uint32_t*>(&h);
}

// ---------------------------------------------------------------------------
// All 6 weight transposes in ONE launch. WT[n*K+k] = half(W[k*N+n])
// ---------------------------------------------------------------------------
__global__ __launch_bounds__(256) void transpose_all(
    const float* __restrict__ Wq, const float* __restrict__ Wk,
    const float* __restrict__ Wv, const float* __restrict__ Wo,
    const float* __restrict__ W1, const float* __restrict__ W2,
    __half* __restrict__ wtq, __half* __restrict__ wtk,
    __half* __restrict__ wtv, __half* __restrict__ wto,
    __half* __restrict__ wt1, __half* __restrict__ wt2)
{
    const float* W; __half* WT; int K, N;
    switch (blockIdx.z) {
        case 0: W = Wq; WT = wtq; K = EDIM; N = EDIM; break;
        case 1: W = Wk; WT = wtk; K = EDIM; N = EDIM; break;
        case 2: W = Wv; WT = wtv; K = EDIM; N = EDIM; break;
        case 3: W = Wo; WT = wto; K = EDIM; N = EDIM; break;
        case 4: W = W1; WT = wt1; K = EDIM; N = FDIM; break;
        default: W = W2; WT = wt2; K = FDIM; N = EDIM; break;
    }
    const int n0 = blockIdx.x * 32, k0 = blockIdx.y * 32;
    if (n0 >= N || k0 >= K) return;
    __shared__ float t[32][33];
    const int x = threadIdx.x & 31, y = threadIdx.x >> 5;
    #pragma unroll
    for (int i = 0; i < 32; i += 8)
        t[y + i][x] = W[(size_t)(k0 + y + i) * N + n0 + x];
    __syncthreads();
    #pragma unroll
    for (int i = 0; i < 32; i += 8)
        WT[(size_t)(n0 + y + i) * K + k0 + x] = __float2half_rn(t[x][y + i]);
}

// ---------------------------------------------------------------------------
// LayerNorm: half copy (yh) + full fp32 copy (yf)
// ---------------------------------------------------------------------------
__global__ __launch_bounds__(256) void ln_kernel(
    const float* __restrict__ x, const float* __restrict__ g,
    const float* __restrict__ b, __half* __restrict__ yh, float* __restrict__ yf)
{
    const int row = blockIdx.x;
    const int tid = threadIdx.x;
    const float4 v = reinterpret_cast<const float4*>(x + (size_t)row * EDIM)[tid];

    float s  = v.x + v.y + v.z + v.w;
    float ss = v.x * v.x + v.y * v.y + v.z * v.z + v.w * v.w;
    #pragma unroll
    for (int off = 16; off > 0; off >>= 1) {
        s  += __shfl_down_sync(0xffffffffu, s,  off);
        ss += __shfl_down_sync(0xffffffffu, ss, off);
    }
    __shared__ float wsum[8], wsq[8];
    __shared__ float s_mu, s_rstd;
    const int wid = tid >> 5, lane = tid & 31;
    if (lane == 0) { wsum[wid] = s; wsq[wid] = ss; }
    __syncthreads();
    if (tid == 0) {
        float ts = 0.f, tss = 0.f;
        #pragma unroll
        for (int i = 0; i < 8; i++) { ts += wsum[i]; tss += wsq[i]; }
        const float mu  = ts * (1.0f / EDIM);
        const float var = tss * (1.0f / EDIM) - mu * mu;
        s_mu = mu; s_rstd = rsqrtf(var + 1e-5f);
    }
    __syncthreads();
    const float mu = s_mu, rstd = s_rstd;
    const float4 gv = reinterpret_cast<const float4*>(g)[tid];
    const float4 bv = reinterpret_cast<const float4*>(b)[tid];
    float4 o;
    o.x = (v.x - mu) * rstd * gv.x + bv.x;
    o.y = (v.y - mu) * rstd * gv.y + bv.y;
    o.z = (v.z - mu) * rstd * gv.z + bv.z;
    o.w = (v.w - mu) * rstd * gv.w + bv.w;
    reinterpret_cast<float4*>(yf + (size_t)row * EDIM)[tid] = o;
    __half2* hp = reinterpret_cast<__half2*>(yh + (size_t)row * EDIM);
    hp[2 * tid + 0] = __halves2half2(__float2half_rn(o.x), __float2half_rn(o.y));
    hp[2 * tid + 1] = __halves2half2(__float2half_rn(o.z), __float2half_rn(o.w));
}

// ---------------------------------------------------------------------------
// fp16 GEMM: C[M,N] = A[M,K] @ Bt[N,K]^T + bias (+epilogue).
// CTA 128x128, 128 thr (4 warps 2x2, warp tile 64x64), KCH=32, 4 stages,
// prefetch 3 ahead, XOR-swizzled 64B rows (no padding). 3 CTA/SM.
// OP: 0 half out (bias); 1 float out (bias+residual); 2 half out (bias+GELU)
// ---------------------------------------------------------------------------
#define KCH 32
#define TILE_B 8192                       // 128 rows x 64B
#define STG_B  (2 * TILE_B)               // A + B
#define GEMM_SMEM (4 * STG_B)             // 65536

template <int OP>
__global__ __launch_bounds__(128, 3) void mm_gemm(
    const __half* __restrict__ A, const __half* __restrict__ Bt,
    const float* __restrict__ bias, const float* __restrict__ res,
    void* __restrict__ Cv, int M, int N, int K)
{
    extern __shared__ uint32_t sm[];
    const int tid = threadIdx.x;
    const int wid = tid >> 5, lane = tid & 31;
    const int row0 = blockIdx.y * 128, col0 = blockIdx.x * 128;

    const __half* gA = A  + (size_t)(row0 + tid) * K;
    const __half* gB = Bt + (size_t)(col0 + tid) * K;
    const uint32_t sm0 = smem_u32(sm);
    // write addresses: row tid, 4 segs of 16B, seg swizzle = u ^ ((row>>1)&3)
    const uint32_t swc = (uint32_t)((tid >> 1) & 3);
    const uint32_t dA = sm0 + (uint32_t)(tid * 64);
    const uint32_t dB = dA + TILE_B;

    const int nch = K >> 5;

    // prologue: chunks 0,1,2 -> stages 0,1,2
    #pragma unroll
    for (int c = 0; c < 3; c++) {
        const uint32_t so = (uint32_t)(c * STG_B);
        #pragma unroll
        for (int u = 0; u < 4; u++) {
            const uint32_t sw = ((u ^ swc) * 16u);
            cpa16(dA + so + sw, gA + c * KCH + u * 8);
            cpa16(dB + so + sw, gB + c * KCH + u * 8);
        }
        CP_COMMIT();
    }

    const int wm = wid & 1, wn = wid >> 1;
    int arow[4];
    #pragma unroll
    for (int mt = 0; mt < 4; mt++)
        arow[mt] = wm * 64 + (lane & 15) + mt * 16;
    int brow[4];
    #pragma unroll
    for (int pr = 0; pr < 4; pr++)
        brow[pr] = wn * 64 + (lane & 7) + ((lane >> 4) << 3) + pr * 16;
    const int ahi = lane >> 4;            // 16B selector for A
    const int bhi = (lane >> 3) & 1;      // 16B selector for B

    float acc[4][8][4];
    #pragma unroll
    for (int mt = 0; mt < 4; mt++)
        #pragma unroll
        for (int nt = 0; nt < 8; nt++)
            #pragma unroll
            for (int r = 0; r < 4; r++) acc[mt][nt][r] = 0.f;

    for (int i = 0; i < nch; i++) {
        __syncthreads();                  // stage (i+3)&3 free (read at chunk i-1)
        const int j = i + 3;
        if (j < nch) {
            const uint32_t so = (uint32_t)((j & 3) * STG_B);
            #pragma unroll
            for (int u = 0; u < 4; u++) {
                const uint32_t sw = ((u ^ swc) * 16u);
                cpa16(dA + so + sw, gA + j * KCH + u * 8);
                cpa16(dB + so + sw, gB + j * KCH + u * 8);
            }
        }
        CP_COMMIT();
        CP_WAIT3();                       // chunk i resident
        __syncthreads();

        const uint32_t st = sm0 + (uint32_t)((i & 3) * STG_B);

        #pragma unroll
        for (int ks = 0; ks < 2; ks++) {  // 2 x k16 = 32
            uint32_t a[4][4];
            #pragma unroll
            for (int mt = 0; mt < 4; mt++) {
                const int r = arow[mt];
                const uint32_t sw = (uint32_t)(((ks * 2 + ahi) ^ ((r >> 1) & 3)) * 16);
                ldsm4(a[mt], st + (uint32_t)(r * 64) + sw);
            }
            #pragma unroll
            for (int pr = 0; pr < 4; pr++) {
                const int r = brow[pr];
                const uint32_t sw = (uint32_t)(((ks * 2 + bhi) ^ ((r >> 1) & 3)) * 16);
                uint32_t b[4];
                ldsm4(b, st + TILE_B + (uint32_t)(r * 64) + sw);
                #pragma unroll
                for (int mt = 0; mt < 4; mt++)
                    mma16(acc[mt][2 * pr], a[mt], b[0], b[1]);
                #pragma unroll
                for (int mt = 0; mt < 4; mt++)
                    mma16(acc[mt][2 * pr + 1], a[mt], b[2], b[3]);
            }
        }
    }

    const int lr = lane >> 2, lk = lane & 3;
    const int lc = 2 * lk;
    #pragma unroll
    for (int nt = 0; nt < 8; nt++) {
        const int col = col0 + wn * 64 + nt * 8 + lc;
        const float bx = bias[col], by = bias[col + 1];
        #pragma unroll
        for (int mt = 0; mt < 4; mt++) {
            const int row = row0 + wm * 64 + mt * 16 + lr;
            #pragma unroll
            for (int h = 0; h < 2; h++) {
                const int r = row + h * 8;
                float vx = acc[mt][nt][2 * h + 0] + bx;
                float vy = acc[mt][nt][2 * h + 1] + by;
                if (OP == 2) {
                    vx = 0.5f * vx * (1.0f + erff(vx * 0.70710678118654752f));
                    vy = 0.5f * vy * (1.0f + erff(vy * 0.70710678118654752f));
                }
                if (OP == 1) {
                    const float* rp = res + (size_t)r * N + col;
                    vx += rp[0]; vy += rp[1];
                }
                if (OP == 0 || OP == 2) {
                    __half2* cp = reinterpret_cast<__half2*>(
                        (__half*)Cv + (size_t)r * N + col);
                    *cp = __halves2half2(__float2half_rn(vx), __float2half_rn(vy));
                } else {
                    *reinterpret_cast<float2*>((float*)Cv + (size_t)r * N + col)
                        = make_float2(vx, vy);
                }
            }
        }
    }
}

// ---------------------------------------------------------------------------
// Flash attention (FA2-style): 256 thr, warp w owns q rows w*16..+15 x all kv.
// fp16 QK^T and fp16 P@V (ldmatrix.trans on V), register softmax, K/V double
// buffered via cp.async. Q/K/V smem rows = 128B, SW128-style XOR swizzle.
// ---------------------------------------------------------------------------
#define AQ_B  16384                 // Q: 128 rows x 128B
#define AKV_B 8192                  // K or V stage: 64 rows x 128B
#define ATTN_SMEM (AQ_B + 4 * AKV_B)   // 49152

__global__ __launch_bounds__(256) void attn_kernel(
    const __half* __restrict__ Q, const __half* __restrict__ K,
    const __half* __restrict__ V, __half* __restrict__ O)
{
    extern __shared__ char smc[];
    const uint32_t sQ = smem_u32(smc);
    const uint32_t sK0 = sQ + AQ_B;           // K stages at +0, +AKV_B
    const uint32_t sV0 = sK0 + 2 * AKV_B;     // V stages at +0, +AKV_B

    const int tid = threadIdx.x;
    const int w = tid >> 5, lane = tid & 31;
    const int lr = lane >> 2, lk = lane & 3;
    const int q0 = blockIdx.x * 128;
    const size_t base = (size_t)blockIdx.z * SDIM * EDIM + (size_t)blockIdx.y * 64;

    // Q tile: 128 rows x 8 segs of 16B, swizzled seg = s ^ (r&7)
    #pragma unroll
    for (int u = 0; u < 4; u++) {
        const int idx = u * 256 + tid;
        const int r = idx >> 3, seg = idx & 7;
        cpa16(sQ + (uint32_t)(r * 128 + ((seg ^ (r & 7)) * 16)),
              Q + base + (size_t)(q0 + r) * EDIM + seg * 8);
    }
    CP_COMMIT();
    // K/V tile kt=0 -> stage 0
    {
        #pragma unroll
        for (int u = 0; u < 2; u++) {
            const int idx = u * 256 + tid;
            const int r = idx >> 3, seg = idx & 7;
            const uint32_t off = (uint32_t)(r * 128 + ((seg ^ (r & 7)) * 16));
            const size_t g = base + (size_t)r * EDIM + seg * 8;
            cpa16(sK0 + off, K + g);
            cpa16(sV0 + off, V + g);
        }
        CP_COMMIT();
    }

    float oacc[8][4];
    #pragma unroll
    for (int nt = 0; nt < 8; nt++)
        #pragma unroll
        for (int r = 0; r < 4; r++) oacc[nt][r] = 0.f;
    float m0 = -1e30f, m1 = -1e30f, l0 = 0.f, l1 = 0.f;

    const int qrow = w * 16 + (lane & 15);
    const int ahi = lane >> 4;
    const int krow_l = (lane & 7) + ((lane >> 4) << 3);        // + pr*16
    const int kbhi = (lane >> 3) & 1;
    const int vrow_l = (lane & 7) + (((lane >> 3) & 1) << 3);  // + pr*16
    const int vhi = lane >> 4;

    for (int kt = 0; kt < 32; kt++) {
        __syncthreads();                  // stage (kt+1)&1 free
        const int jn = kt + 1;
        if (jn < 32) {
            const uint32_t so = (uint32_t)((jn & 1) * AKV_B);
            const int k0n = jn * 64;
            #pragma unroll
            for (int u = 0; u < 2; u++) {
                const int idx = u * 256 + tid;
                const int r = idx >> 3, seg = idx & 7;
                const uint32_t off = (uint32_t)(r * 128 + ((seg ^ (r & 7)) * 16));
                const size_t g = base + (size_t)(k0n + r) * EDIM + seg * 8;
                cpa16(sK0 + so + off, K + g);
                cpa16(sV0 + so + off, V + g);
            }
        }
        CP_COMMIT();
        CP_WAIT1();
        __syncthreads();

        const uint32_t kb = sK0 + (uint32_t)((kt & 1) * AKV_B);
        const uint32_t vb = sV0 + (uint32_t)((kt & 1) * AKV_B);

        // S = Q K^T
        float sacc[8][4];
        #pragma unroll
        for (int nt = 0; nt < 8; nt++)
            #pragma unroll
            for (int r = 0; r < 4; r++) sacc[nt][r] = 0.f;

        #pragma unroll
        for (int ks = 0; ks < 4; ks++) {
            uint32_t a[4];
            {
                const uint32_t sw = (uint32_t)(((ks * 2 + ahi) ^ (qrow & 7)) * 16);
                ldsm4(a, sQ + (uint32_t)(qrow * 128) + sw);
            }
            #pragma unroll
            for (int pr = 0; pr < 4; pr++) {
                const int r = krow_l + pr * 16;
                const uint32_t sw = (uint32_t)(((ks * 2 + kbhi) ^ (r & 7)) * 16);
                uint32_t b[4];
                ldsm4(b, kb + (uint32_t)(r * 128) + sw);
                mma16(sacc[2 * pr], a, b[0], b[1]);
                mma16(sacc[2 * pr + 1], a, b[2], b[3]);
            }
        }

        // register softmax (rows lr, lr+8 of this warp's 16)
        float mx0 = -1e30f, mx1 = -1e30f;
        #pragma unroll
        for (int nt = 0; nt < 8; nt++) {
            sacc[nt][0] *= 0.125f; sacc[nt][1] *= 0.125f;
            sacc[nt][2] *= 0.125f; sacc[nt][3] *= 0.125f;
            mx0 = fmaxf(mx0, fmaxf(sacc[nt][0], sacc[nt][1]));
            mx1 = fmaxf(mx1, fmaxf(sacc[nt][2], sacc[nt][3]));
        }
        mx0 = fmaxf(mx0, __shfl_xor_sync(0xffffffffu, mx0, 1));
        mx0 = fmaxf(mx0, __shfl_xor_sync(0xffffffffu, mx0, 2));
        mx1 = fmaxf(mx1, __shfl_xor_sync(0xffffffffu, mx1, 1));
        mx1 = fmaxf(mx1, __shfl_xor_sync(0xffffffffu, mx1, 2));
        const float mn0 = fmaxf(m0, mx0), mn1 = fmaxf(m1, mx1);
        const float al0 = __expf(m0 - mn0), al1 = __expf(m1 - mn1);
        m0 = mn0; m1 = mn1;
        float s0 = 0.f, s1 = 0.f;
        #pragma unroll
        for (int nt = 0; nt < 8; nt++) {
            sacc[nt][0] = __expf(sacc[nt][0] - mn0); s0 += sacc[nt][0];
            sacc[nt][1] = __expf(sacc[nt][1] - mn0); s0 += sacc[nt][1];
            sacc[nt][2] = __expf(sacc[nt][2] - mn1); s1 += sacc[nt][2];
            sacc[nt][3] = __expf(sacc[nt][3] - mn1); s1 += sacc[nt][3];
        }
        s0 += __shfl_xor_sync(0xffffffffu, s0, 1);
        s0 += __shfl_xor_sync(0xffffffffu, s0, 2);
        s1 += __shfl_xor_sync(0xffffffffu, s1, 1);
        s1 += __shfl_xor_sync(0xffffffffu, s1, 2);
        l0 = l0 * al0 + s0;
        l1 = l1 * al1 + s1;
        #pragma unroll
        for (int nt = 0; nt < 8; nt++) {
            oacc[nt][0] *= al0; oacc[nt][1] *= al0;
            oacc[nt][2] *= al1; oacc[nt][3] *= al1;
        }

        // P -> fp16 A-fragments (per k16 step pr over kv)
        uint32_t pa[4][4];
        #pragma unroll
        for (int pr = 0; pr < 4; pr++) {
            pa[pr][0] = pkhalf(sacc[2 * pr][0], sacc[2 * pr][1]);
            pa[pr][1] = pkhalf(sacc[2 * pr][2], sacc[2 * pr][3]);
            pa[pr][2] = pkhalf(sacc[2 * pr + 1][0], sacc[2 * pr + 1][1]);
            pa[pr][3] = pkhalf(sacc[2 * pr + 1][2], sacc[2 * pr + 1][3]);
        }

        // O += P @ V  (fp16, V row-major -> ldmatrix.trans B-fragments)
        #pragma unroll
        for (int pr = 0; pr < 4; pr++) {
            #pragma unroll
            for (int pn = 0; pn < 4; pn++) {
                const int r = vrow_l + pr * 16;
                const uint32_t sw = (uint32_t)(((pn * 2 + vhi) ^ (r & 7)) * 16);
                uint32_t b[4];
                ldsm4t(b, vb + (uint32_t)(r * 128) + sw);
                mma16(oacc[2 * pn], pa[pr], b[0], b[1]);
                mma16(oacc[2 * pn + 1], pa[pr], b[2], b[3]);
            }
        }
    }

    const float inv0 = 1.0f / l0, inv1 = 1.0f / l1;
    const int r0g = q0 + w * 16 + lr;
    #pragma unroll
    for (int nt = 0; nt < 8; nt++) {
        const int c = nt * 8 + 2 * lk;
        __half2* p0 = reinterpret_cast<__half2*>(
            O + base + (size_t)r0g * EDIM + c);
        __half2* p1 = reinterpret_cast<__half2*>(
            O + base + (size_t)(r0g + 8) * EDIM + c);
        *p0 = __halves2half2(__float2half_rn(oacc[nt][0] * inv0),
                             __float2half_rn(oacc[nt][1] * inv0));
        *p1 = __halves2half2(__float2half_rn(oacc[nt][2] * inv1),
                             __float2half_rn(oacc[nt][3] * inv1));
    }
}

// ---------------------------------------------------------------------------
extern "C" void kernel_launch(void* const* d_in, const int* in_sizes, int n_in,
                              void* d_out, int out_size)
{
    const float* inp   = (const float*)d_in[0];
    const float* ln1_g = (const float*)d_in[1];
    const float* ln1_b = (const float*)d_in[2];
    const float* Wq    = (const float*)d_in[3];
    const float* bq    = (const float*)d_in[4];
    const float* Wk    = (const float*)d_in[5];
    const float* bk    = (const float*)d_in[6];
    const float* Wv    = (const float*)d_in[7];
    const float* bv    = (const float*)d_in[8];
    const float* Wo    = (const float*)d_in[9];
    const float* bo    = (const float*)d_in[10];
    const float* ln2_g = (const float*)d_in[11];
    const float* ln2_b = (const float*)d_in[12];
    const float* W1    = (const float*)d_in[13];
    const float* b1    = (const float*)d_in[14];
    const float* W2    = (const float*)d_in[15];
    const float* b2    = (const float*)d_in[16];
    float* out = (float*)d_out;

    __half *xln1h, *q, *k, *v, *ctx, *x3h, *h1, *wtq, *wtk, *wtv, *wto, *wt1, *wt2;
    float *xln1f, *x2, *x3f;
    cudaGetSymbolAddress((void**)&xln1h, g_xln1h);
    cudaGetSymbolAddress((void**)&xln1f, g_xln1f);
    cudaGetSymbolAddress((void**)&q,    g_q);
    cudaGetSymbolAddress((void**)&k,    g_k);
    cudaGetSymbolAddress((void**)&v,    g_v);
    cudaGetSymbolAddress((void**)&ctx,  g_ctx);
    cudaGetSymbolAddress((void**)&x2,   g_x2);
    cudaGetSymbolAddress((void**)&x3h,  g_x3h);
    cudaGetSymbolAddress((void**)&x3f,  g_x3f);
    cudaGetSymbolAddress((void**)&h1,   g_h1);
    cudaGetSymbolAddress((void**)&wtq,  g_wtq);
    cudaGetSymbolAddress((void**)&wtk,  g_wtk);
    cudaGetSymbolAddress((void**)&wtv,  g_wtv);
    cudaGetSymbolAddress((void**)&wto,  g_wto);
    cudaGetSymbolAddress((void**)&wt1,  g_wt1);
    cudaGetSymbolAddress((void**)&wt2,  g_wt2);

    cudaFuncSetAttribute(attn_kernel,
                         cudaFuncAttributeMaxDynamicSharedMemorySize, ATTN_SMEM);
    cudaFuncSetAttribute(mm_gemm<0>,
                         cudaFuncAttributeMaxDynamicSharedMemorySize, GEMM_SMEM);
    cudaFuncSetAttribute(mm_gemm<1>,
                         cudaFuncAttributeMaxDynamicSharedMemorySize, GEMM_SMEM);
    cudaFuncSetAttribute(mm_gemm<2>,
                         cudaFuncAttributeMaxDynamicSharedMemorySize, GEMM_SMEM);

    // 0. weight transposes (one launch)
    transpose_all<<<dim3(64, 64, 6), 256>>>(Wq, Wk, Wv, Wo, W1, W2,
                                            wtq, wtk, wtv, wto, wt1, wt2);
    // 1. LN1
    ln_kernel<<<MDIM, 256>>>(inp, ln1_g, ln1_b, xln1h, xln1f);

    // 2. QKV (all half out)
    dim3 gE(EDIM / 128, MDIM / 128);
    mm_gemm<0><<<gE, 128, GEMM_SMEM>>>(xln1h, wtq, bq, nullptr, q, MDIM, EDIM, EDIM);
    mm_gemm<0><<<gE, 128, GEMM_SMEM>>>(xln1h, wtk, bk, nullptr, k, MDIM, EDIM, EDIM);
    mm_gemm<0><<<gE, 128, GEMM_SMEM>>>(xln1h, wtv, bv, nullptr, v, MDIM, EDIM, EDIM);

    // 3. Attention -> ctx (half)
    dim3 gA(SDIM / 128, HDIM, BDIM);
    attn_kernel<<<gA, 256, ATTN_SMEM>>>(q, k, v, ctx);

    // 4. O-proj + residual(LN1 full) -> x2 (float)
    mm_gemm<1><<<gE, 128, GEMM_SMEM>>>(ctx, wto, bo, xln1f, x2, MDIM, EDIM, EDIM);

    // 5. LN2
    ln_kernel<<<MDIM, 256>>>(x2, ln2_g, ln2_b, x3h, x3f);

    // 6. MLP
    dim3 gF(FDIM / 128, MDIM / 128);
    mm_gemm<2><<<gF, 128, GEMM_SMEM>>>(x3h, wt1, b1, nullptr, h1, MDIM, FDIM, EDIM);
    mm_gemm<1><<<gE, 128, GEMM_SMEM>>>(h1, wt2, b2, x3f, out, MDIM, EDIM, FDIM);
}

// round 13
// speedup vs baseline: 5.5709x; 1.0791x over previous
#include <cuda_runtime.h>
#include <cuda_fp16.h>
#include <math.h>
#include <stdint.h>

// ---------------------------------------------------------------------------
// TransformerBlock B=4,S=2048,E=1024,H=16,D=64.
// R13 (third submit of the R11 design; two prior broker failures):
//   fused QKV GEMM (N=3072), single-barrier GEMM mainloop (4 stages,
//   prefetch 3, wait_group 2), FA2 attention reading strided qkv buffer.
// ---------------------------------------------------------------------------

#define MDIM 8192
#define EDIM 1024
#define SDIM 2048
#define BDIM 4
#define HDIM 16
#define FDIM 2048
#define QKVD 3072

__device__ __half g_xln1h[MDIM * EDIM];
__device__ float  g_xln1f[MDIM * EDIM];
__device__ __half g_qkv [MDIM * QKVD];
__device__ __half g_ctx[MDIM * EDIM];
__device__ float  g_x2 [MDIM * EDIM];
__device__ __half g_x3h[MDIM * EDIM];
__device__ float  g_x3f[MDIM * EDIM];
__device__ __half g_h1 [MDIM * FDIM];
__device__ __half g_wqkv[QKVD * EDIM];   // [3072][1024] rows n, cols k
__device__ float  g_bqkv[QKVD];
__device__ __half g_wto[EDIM * EDIM];
__device__ __half g_wt1[FDIM * EDIM];
__device__ __half g_wt2[EDIM * FDIM];

// ---------------------------------------------------------------------------
__device__ __forceinline__ uint32_t smem_u32(const void* p) {
    uint32_t a;
    asm("{ .reg .u64 t; cvta.to.shared.u64 t, %1; cvt.u32.u64 %0, t; }"
        : "=r"(a) : "l"(p));
    return a;
}
__device__ __forceinline__ void cpa16(uint32_t s, const void* g) {
    asm volatile("cp.async.cg.shared.global [%0], [%1], 16;" :: "r"(s), "l"(g));
}
#define CP_COMMIT() asm volatile("cp.async.commit_group;" ::: "memory")
#define CP_WAIT1()  asm volatile("cp.async.wait_group 1;" ::: "memory")
#define CP_WAIT2()  asm volatile("cp.async.wait_group 2;" ::: "memory")

__device__ __forceinline__ void mma16(float* c, const uint32_t* a,
                                      uint32_t b0, uint32_t b1) {
    asm volatile(
        "mma.sync.aligned.m16n8k16.row.col.f32.f16.f16.f32 "
        "{%0,%1,%2,%3}, {%4,%5,%6,%7}, {%8,%9}, {%0,%1,%2,%3};"
        : "+f"(c[0]), "+f"(c[1]), "+f"(c[2]), "+f"(c[3])
        : "r"(a[0]), "r"(a[1]), "r"(a[2]), "r"(a[3]), "r"(b0), "r"(b1));
}
__device__ __forceinline__ void ldsm4(uint32_t* r, uint32_t addr) {
    asm volatile("ldmatrix.sync.aligned.m8n8.x4.shared.b16 {%0,%1,%2,%3}, [%4];"
        : "=r"(r[0]), "=r"(r[1]), "=r"(r[2]), "=r"(r[3]) : "r"(addr));
}
__device__ __forceinline__ void ldsm4t(uint32_t* r, uint32_t addr) {
    asm volatile("ldmatrix.sync.aligned.m8n8.x4.trans.shared.b16 {%0,%1,%2,%3}, [%4];"
        : "=r"(r[0]), "=r"(r[1]), "=r"(r[2]), "=r"(r[3]) : "r"(addr));
}
__device__ __forceinline__ uint32_t pkhalf(float x, float y) {
    __half2 h = __floats2half2_rn(x, y);
    return *reinterpret_cast<uint32_t*>(&h);
}

// ---------------------------------------------------------------------------
// Weight transposes: QKV (3 x [1024,1024] -> g_wqkv rows z*1024+n)
// ---------------------------------------------------------------------------
__global__ __launch_bounds__(256) void transpose_qkv(
    const float* __restrict__ Wq, const float* __restrict__ Wk,
    const float* __restrict__ Wv, __half* __restrict__ wqkv)
{
    const float* W = (blockIdx.z == 0) ? Wq : (blockIdx.z == 1) ? Wk : Wv;
    const int n0 = blockIdx.x * 32, k0 = blockIdx.y * 32;
    __shared__ float t[32][33];
    const int x = threadIdx.x & 31, y = threadIdx.x >> 5;
    #pragma unroll
    for (int i = 0; i < 32; i += 8)
        t[y + i][x] = W[(size_t)(k0 + y + i) * EDIM + n0 + x];
    __syncthreads();
    #pragma unroll
    for (int i = 0; i < 32; i += 8)
        wqkv[(size_t)(blockIdx.z * 1024 + n0 + y + i) * EDIM + k0 + x]
            = __float2half_rn(t[x][y + i]);
}

// Wo [1024,1024], W1 [1024,2048], W2 [2048,1024]
__global__ __launch_bounds__(256) void transpose_rest(
    const float* __restrict__ Wo, const float* __restrict__ W1,
    const float* __restrict__ W2, __half* __restrict__ wto,
    __half* __restrict__ wt1, __half* __restrict__ wt2)
{
    const float* W; __half* WT; int K, N;
    switch (blockIdx.z) {
        case 0: W = Wo; WT = wto; K = EDIM; N = EDIM; break;
        case 1: W = W1; WT = wt1; K = EDIM; N = FDIM; break;
        default: W = W2; WT = wt2; K = FDIM; N = EDIM; break;
    }
    const int n0 = blockIdx.x * 32, k0 = blockIdx.y * 32;
    if (n0 >= N || k0 >= K) return;
    __shared__ float t[32][33];
    const int x = threadIdx.x & 31, y = threadIdx.x >> 5;
    #pragma unroll
    for (int i = 0; i < 32; i += 8)
        t[y + i][x] = W[(size_t)(k0 + y + i) * N + n0 + x];
    __syncthreads();
    #pragma unroll
    for (int i = 0; i < 32; i += 8)
        WT[(size_t)(n0 + y + i) * K + k0 + x] = __float2half_rn(t[x][y + i]);
}

__global__ __launch_bounds__(256) void biascat(
    const float* __restrict__ bq, const float* __restrict__ bk,
    const float* __restrict__ bv, float* __restrict__ bqkv)
{
    const int j = blockIdx.x * 256 + threadIdx.x;
    if (j < 1024)       bqkv[j] = bq[j];
    else if (j < 2048)  bqkv[j] = bk[j - 1024];
    else                bqkv[j] = bv[j - 2048];
}

// ---------------------------------------------------------------------------
// LayerNorm: half copy (yh) + full fp32 copy (yf)
// ---------------------------------------------------------------------------
__global__ __launch_bounds__(256) void ln_kernel(
    const float* __restrict__ x, const float* __restrict__ g,
    const float* __restrict__ b, __half* __restrict__ yh, float* __restrict__ yf)
{
    const int row = blockIdx.x;
    const int tid = threadIdx.x;
    const float4 v = reinterpret_cast<const float4*>(x + (size_t)row * EDIM)[tid];

    float s  = v.x + v.y + v.z + v.w;
    float ss = v.x * v.x + v.y * v.y + v.z * v.z + v.w * v.w;
    #pragma unroll
    for (int off = 16; off > 0; off >>= 1) {
        s  += __shfl_down_sync(0xffffffffu, s,  off);
        ss += __shfl_down_sync(0xffffffffu, ss, off);
    }
    __shared__ float wsum[8], wsq[8];
    __shared__ float s_mu, s_rstd;
    const int wid = tid >> 5, lane = tid & 31;
    if (lane == 0) { wsum[wid] = s; wsq[wid] = ss; }
    __syncthreads();
    if (tid == 0) {
        float ts = 0.f, tss = 0.f;
        #pragma unroll
        for (int i = 0; i < 8; i++) { ts += wsum[i]; tss += wsq[i]; }
        const float mu  = ts * (1.0f / EDIM);
        const float var = tss * (1.0f / EDIM) - mu * mu;
        s_mu = mu; s_rstd = rsqrtf(var + 1e-5f);
    }
    __syncthreads();
    const float mu = s_mu, rstd = s_rstd;
    const float4 gv = reinterpret_cast<const float4*>(g)[tid];
    const float4 bv = reinterpret_cast<const float4*>(b)[tid];
    float4 o;
    o.x = (v.x - mu) * rstd * gv.x + bv.x;
    o.y = (v.y - mu) * rstd * gv.y + bv.y;
    o.z = (v.z - mu) * rstd * gv.z + bv.z;
    o.w = (v.w - mu) * rstd * gv.w + bv.w;
    reinterpret_cast<float4*>(yf + (size_t)row * EDIM)[tid] = o;
    __half2* hp = reinterpret_cast<__half2*>(yh + (size_t)row * EDIM);
    hp[2 * tid + 0] = __halves2half2(__float2half_rn(o.x), __float2half_rn(o.y));
    hp[2 * tid + 1] = __halves2half2(__float2half_rn(o.z), __float2half_rn(o.w));
}

// ---------------------------------------------------------------------------
// fp16 GEMM: C[M,N] = A[M,K] @ Bt[N,K]^T + bias (+epilogue).
// CTA 128x128, 128 thr (4 warps 2x2, warp tile 64x64), KCH=32, 4 stages,
// SINGLE barrier per iter: wait_group 2 -> sync -> issue i+3 -> compute i.
// XOR-swizzled 64B rows. 3 CTA/SM.
// OP: 0 half out (bias); 1 float out (bias+residual); 2 half out (bias+GELU)
// ---------------------------------------------------------------------------
#define KCH 32
#define TILE_B 8192
#define STG_B  (2 * TILE_B)
#define GEMM_SMEM (4 * STG_B)             // 65536

template <int OP>
__global__ __launch_bounds__(128, 3) void mm_gemm(
    const __half* __restrict__ A, const __half* __restrict__ Bt,
    const float* __restrict__ bias, const float* __restrict__ res,
    void* __restrict__ Cv, int M, int N, int K)
{
    extern __shared__ uint32_t sm[];
    const int tid = threadIdx.x;
    const int wid = tid >> 5, lane = tid & 31;
    const int row0 = blockIdx.y * 128, col0 = blockIdx.x * 128;

    const __half* gA = A  + (size_t)(row0 + tid) * K;
    const __half* gB = Bt + (size_t)(col0 + tid) * K;
    const uint32_t sm0 = smem_u32(sm);
    const uint32_t swc = (uint32_t)((tid >> 1) & 3);
    const uint32_t dA = sm0 + (uint32_t)(tid * 64);
    const uint32_t dB = dA + TILE_B;

    const int nch = K >> 5;

    // prologue: chunks 0,1,2 -> stages 0,1,2
    #pragma unroll
    for (int c = 0; c < 3; c++) {
        const uint32_t so = (uint32_t)(c * STG_B);
        #pragma unroll
        for (int u = 0; u < 4; u++) {
            const uint32_t sw = ((u ^ swc) * 16u);
            cpa16(dA + so + sw, gA + c * KCH + u * 8);
            cpa16(dB + so + sw, gB + c * KCH + u * 8);
        }
        CP_COMMIT();
    }

    const int wm = wid & 1, wn = wid >> 1;
    int arow[4];
    #pragma unroll
    for (int mt = 0; mt < 4; mt++)
        arow[mt] = wm * 64 + (lane & 15) + mt * 16;
    int brow[4];
    #pragma unroll
    for (int pr = 0; pr < 4; pr++)
        brow[pr] = wn * 64 + (lane & 7) + ((lane >> 4) << 3) + pr * 16;
    const int ahi = lane >> 4;
    const int bhi = (lane >> 3) & 1;

    float acc[4][8][4];
    #pragma unroll
    for (int mt = 0; mt < 4; mt++)
        #pragma unroll
        for (int nt = 0; nt < 8; nt++)
            #pragma unroll
            for (int r = 0; r < 4; r++) acc[mt][nt][r] = 0.f;

    for (int i = 0; i < nch; i++) {
        CP_WAIT2();                       // chunk i resident (group i retired)
        __syncthreads();                  // publish cross-warp; stage (i+3)&3 free
        const int j = i + 3;
        if (j < nch) {
            const uint32_t so = (uint32_t)((j & 3) * STG_B);
            #pragma unroll
            for (int u = 0; u < 4; u++) {
                const uint32_t sw = ((u ^ swc) * 16u);
                cpa16(dA + so + sw, gA + j * KCH + u * 8);
                cpa16(dB + so + sw, gB + j * KCH + u * 8);
            }
        }
        CP_COMMIT();

        const uint32_t st = sm0 + (uint32_t)((i & 3) * STG_B);

        #pragma unroll
        for (int ks = 0; ks < 2; ks++) {
            uint32_t a[4][4];
            #pragma unroll
            for (int mt = 0; mt < 4; mt++) {
                const int r = arow[mt];
                const uint32_t sw = (uint32_t)(((ks * 2 + ahi) ^ ((r >> 1) & 3)) * 16);
                ldsm4(a[mt], st + (uint32_t)(r * 64) + sw);
            }
            #pragma unroll
            for (int pr = 0; pr < 4; pr++) {
                const int r = brow[pr];
                const uint32_t sw = (uint32_t)(((ks * 2 + bhi) ^ ((r >> 1) & 3)) * 16);
                uint32_t b[4];
                ldsm4(b, st + TILE_B + (uint32_t)(r * 64) + sw);
                #pragma unroll
                for (int mt = 0; mt < 4; mt++)
                    mma16(acc[mt][2 * pr], a[mt], b[0], b[1]);
                #pragma unroll
                for (int mt = 0; mt < 4; mt++)
                    mma16(acc[mt][2 * pr + 1], a[mt], b[2], b[3]);
            }
        }
    }

    const int lr = lane >> 2, lk = lane & 3;
    const int lc = 2 * lk;
    #pragma unroll
    for (int nt = 0; nt < 8; nt++) {
        const int col = col0 + wn * 64 + nt * 8 + lc;
        const float bx = bias[col], by = bias[col + 1];
        #pragma unroll
        for (int mt = 0; mt < 4; mt++) {
            const int row = row0 + wm * 64 + mt * 16 + lr;
            #pragma unroll
            for (int h = 0; h < 2; h++) {
                const int r = row + h * 8;
                float vx = acc[mt][nt][2 * h + 0] + bx;
                float vy = acc[mt][nt][2 * h + 1] + by;
                if (OP == 2) {
                    vx = 0.5f * vx * (1.0f + erff(vx * 0.70710678118654752f));
                    vy = 0.5f * vy * (1.0f + erff(vy * 0.70710678118654752f));
                }
                if (OP == 1) {
                    const float* rp = res + (size_t)r * N + col;
                    vx += rp[0]; vy += rp[1];
                }
                if (OP == 0 || OP == 2) {
                    __half2* cp = reinterpret_cast<__half2*>(
                        (__half*)Cv + (size_t)r * N + col);
                    *cp = __halves2half2(__float2half_rn(vx), __float2half_rn(vy));
                } else {
                    *reinterpret_cast<float2*>((float*)Cv + (size_t)r * N + col)
                        = make_float2(vx, vy);
                }
            }
        }
    }
}

// ---------------------------------------------------------------------------
// Flash attention (FA2): q/k/v read from fused qkv buffer with row stride
// 3072 (col offsets 0 / 1024 / 2048). Output stride 1024.
// ---------------------------------------------------------------------------
#define AQ_B  16384
#define AKV_B 8192
#define ATTN_SMEM (AQ_B + 4 * AKV_B)   // 49152

__global__ __launch_bounds__(256) void attn_kernel(
    const __half* __restrict__ QKV, __half* __restrict__ O)
{
    extern __shared__ char smc[];
    const uint32_t sQ = smem_u32(smc);
    const uint32_t sK0 = sQ + AQ_B;
    const uint32_t sV0 = sK0 + 2 * AKV_B;

    const int tid = threadIdx.x;
    const int w = tid >> 5, lane = tid & 31;
    const int lr = lane >> 2, lk = lane & 3;
    const int q0 = blockIdx.x * 128;
    const size_t baseq = (size_t)blockIdx.z * SDIM * QKVD + (size_t)blockIdx.y * 64;
    const size_t baseo = (size_t)blockIdx.z * SDIM * EDIM + (size_t)blockIdx.y * 64;
    const __half* Qp = QKV + baseq;
    const __half* Kp = QKV + baseq + 1024;
    const __half* Vp = QKV + baseq + 2048;

    // Q tile
    #pragma unroll
    for (int u = 0; u < 4; u++) {
        const int idx = u * 256 + tid;
        const int r = idx >> 3, seg = idx & 7;
        cpa16(sQ + (uint32_t)(r * 128 + ((seg ^ (r & 7)) * 16)),
              Qp + (size_t)(q0 + r) * QKVD + seg * 8);
    }
    CP_COMMIT();
    // K/V tile kt=0 -> stage 0
    {
        #pragma unroll
        for (int u = 0; u < 2; u++) {
            const int idx = u * 256 + tid;
            const int r = idx >> 3, seg = idx & 7;
            const uint32_t off = (uint32_t)(r * 128 + ((seg ^ (r & 7)) * 16));
            cpa16(sK0 + off, Kp + (size_t)r * QKVD + seg * 8);
            cpa16(sV0 + off, Vp + (size_t)r * QKVD + seg * 8);
        }
        CP_COMMIT();
    }

    float oacc[8][4];
    #pragma unroll
    for (int nt = 0; nt < 8; nt++)
        #pragma unroll
        for (int r = 0; r < 4; r++) oacc[nt][r] = 0.f;
    float m0 = -1e30f, m1 = -1e30f, l0 = 0.f, l1 = 0.f;

    const int qrow = w * 16 + (lane & 15);
    const int ahi = lane >> 4;
    const int krow_l = (lane & 7) + ((lane >> 4) << 3);
    const int kbhi = (lane >> 3) & 1;
    const int vrow_l = (lane & 7) + (((lane >> 3) & 1) << 3);
    const int vhi = lane >> 4;

    for (int kt = 0; kt < 32; kt++) {
        __syncthreads();
        const int jn = kt + 1;
        if (jn < 32) {
            const uint32_t so = (uint32_t)((jn & 1) * AKV_B);
            const int k0n = jn * 64;
            #pragma unroll
            for (int u = 0; u < 2; u++) {
                const int idx = u * 256 + tid;
                const int r = idx >> 3, seg = idx & 7;
                const uint32_t off = (uint32_t)(r * 128 + ((seg ^ (r & 7)) * 16));
                cpa16(sK0 + so + off, Kp + (size_t)(k0n + r) * QKVD + seg * 8);
                cpa16(sV0 + so + off, Vp + (size_t)(k0n + r) * QKVD + seg * 8);
            }
        }
        CP_COMMIT();
        CP_WAIT1();
        __syncthreads();

        const uint32_t kb = sK0 + (uint32_t)((kt & 1) * AKV_B);
        const uint32_t vb = sV0 + (uint32_t)((kt & 1) * AKV_B);

        float sacc[8][4];
        #pragma unroll
        for (int nt = 0; nt < 8; nt++)
            #pragma unroll
            for (int r = 0; r < 4; r++) sacc[nt][r] = 0.f;

        #pragma unroll
        for (int ks = 0; ks < 4; ks++) {
            uint32_t a[4];
            {
                const uint32_t sw = (uint32_t)(((ks * 2 + ahi) ^ (qrow & 7)) * 16);
                ldsm4(a, sQ + (uint32_t)(qrow * 128) + sw);
            }
            #pragma unroll
            for (int pr = 0; pr < 4; pr++) {
                const int r = krow_l + pr * 16;
                const uint32_t sw = (uint32_t)(((ks * 2 + kbhi) ^ (r & 7)) * 16);
                uint32_t b[4];
                ldsm4(b, kb + (uint32_t)(r * 128) + sw);
                mma16(sacc[2 * pr], a, b[0], b[1]);
                mma16(sacc[2 * pr + 1], a, b[2], b[3]);
            }
        }

        float mx0 = -1e30f, mx1 = -1e30f;
        #pragma unroll
        for (int nt = 0; nt < 8; nt++) {
            sacc[nt][0] *= 0.125f; sacc[nt][1] *= 0.125f;
            sacc[nt][2] *= 0.125f; sacc[nt][3] *= 0.125f;
            mx0 = fmaxf(mx0, fmaxf(sacc[nt][0], sacc[nt][1]));
            mx1 = fmaxf(mx1, fmaxf(sacc[nt][2], sacc[nt][3]));
        }
        mx0 = fmaxf(mx0, __shfl_xor_sync(0xffffffffu, mx0, 1));
        mx0 = fmaxf(mx0, __shfl_xor_sync(0xffffffffu, mx0, 2));
        mx1 = fmaxf(mx1, __shfl_xor_sync(0xffffffffu, mx1, 1));
        mx1 = fmaxf(mx1, __shfl_xor_sync(0xffffffffu, mx1, 2));
        const float mn0 = fmaxf(m0, mx0), mn1 = fmaxf(m1, mx1);
        const float al0 = __expf(m0 - mn0), al1 = __expf(m1 - mn1);
        m0 = mn0; m1 = mn1;
        float s0 = 0.f, s1 = 0.f;
        #pragma unroll
        for (int nt = 0; nt < 8; nt++) {
            sacc[nt][0] = __expf(sacc[nt][0] - mn0); s0 += sacc[nt][0];
            sacc[nt][1] = __expf(sacc[nt][1] - mn0); s0 += sacc[nt][1];
            sacc[nt][2] = __expf(sacc[nt][2] - mn1); s1 += sacc[nt][2];
            sacc[nt][3] = __expf(sacc[nt][3] - mn1); s1 += sacc[nt][3];
        }
        s0 += __shfl_xor_sync(0xffffffffu, s0, 1);
        s0 += __shfl_xor_sync(0xffffffffu, s0, 2);
        s1 += __shfl_xor_sync(0xffffffffu, s1, 1);
        s1 += __shfl_xor_sync(0xffffffffu, s1, 2);
        l0 = l0 * al0 + s0;
        l1 = l1 * al1 + s1;
        #pragma unroll
        for (int nt = 0; nt < 8; nt++) {
            oacc[nt][0] *= al0; oacc[nt][1] *= al0;
            oacc[nt][2] *= al1; oacc[nt][3] *= al1;
        }

        uint32_t pa[4][4];
        #pragma unroll
        for (int pr = 0; pr < 4; pr++) {
            pa[pr][0] = pkhalf(sacc[2 * pr][0], sacc[2 * pr][1]);
            pa[pr][1] = pkhalf(sacc[2 * pr][2], sacc[2 * pr][3]);
            pa[pr][2] = pkhalf(sacc[2 * pr + 1][0], sacc[2 * pr + 1][1]);
            pa[pr][3] = pkhalf(sacc[2 * pr + 1][2], sacc[2 * pr + 1][3]);
        }

        #pragma unroll
        for (int pr = 0; pr < 4; pr++) {
            #pragma unroll
            for (int pn = 0; pn < 4; pn++) {
                const int r = vrow_l + pr * 16;
                const uint32_t sw = (uint32_t)(((pn * 2 + vhi) ^ (r & 7)) * 16);
                uint32_t b[4];
                ldsm4t(b, vb + (uint32_t)(r * 128) + sw);
                mma16(oacc[2 * pn], pa[pr], b[0], b[1]);
                mma16(oacc[2 * pn + 1], pa[pr], b[2], b[3]);
            }
        }
    }

    const float inv0 = 1.0f / l0, inv1 = 1.0f / l1;
    const int r0g = q0 + w * 16 + lr;
    #pragma unroll
    for (int nt = 0; nt < 8; nt++) {
        const int c = nt * 8 + 2 * lk;
        __half2* p0 = reinterpret_cast<__half2*>(
            O + baseo + (size_t)r0g * EDIM + c);
        __half2* p1 = reinterpret_cast<__half2*>(
            O + baseo + (size_t)(r0g + 8) * EDIM + c);
        *p0 = __halves2half2(__float2half_rn(oacc[nt][0] * inv0),
                             __float2half_rn(oacc[nt][1] * inv0));
        *p1 = __halves2half2(__float2half_rn(oacc[nt][2] * inv1),
                             __float2half_rn(oacc[nt][3] * inv1));
    }
}

// ---------------------------------------------------------------------------
extern "C" void kernel_launch(void* const* d_in, const int* in_sizes, int n_in,
                              void* d_out, int out_size)
{
    const float* inp   = (const float*)d_in[0];
    const float* ln1_g = (const float*)d_in[1];
    const float* ln1_b = (const float*)d_in[2];
    const float* Wq    = (const float*)d_in[3];
    const float* bq    = (const float*)d_in[4];
    const float* Wk    = (const float*)d_in[5];
    const float* bk    = (const float*)d_in[6];
    const float* Wv    = (const float*)d_in[7];
    const float* bv    = (const float*)d_in[8];
    const float* Wo    = (const float*)d_in[9];
    const float* bo    = (const float*)d_in[10];
    const float* ln2_g = (const float*)d_in[11];
    const float* ln2_b = (const float*)d_in[12];
    const float* W1    = (const float*)d_in[13];
    const float* b1    = (const float*)d_in[14];
    const float* W2    = (const float*)d_in[15];
    const float* b2    = (const float*)d_in[16];
    float* out = (float*)d_out;

    __half *xln1h, *qkv, *ctx, *x3h, *h1, *wqkv, *wto, *wt1, *wt2;
    float *xln1f, *x2, *x3f, *bqkv;
    cudaGetSymbolAddress((void**)&xln1h, g_xln1h);
    cudaGetSymbolAddress((void**)&xln1f, g_xln1f);
    cudaGetSymbolAddress((void**)&qkv,  g_qkv);
    cudaGetSymbolAddress((void**)&ctx,  g_ctx);
    cudaGetSymbolAddress((void**)&x2,   g_x2);
    cudaGetSymbolAddress((void**)&x3h,  g_x3h);
    cudaGetSymbolAddress((void**)&x3f,  g_x3f);
    cudaGetSymbolAddress((void**)&h1,   g_h1);
    cudaGetSymbolAddress((void**)&wqkv, g_wqkv);
    cudaGetSymbolAddress((void**)&bqkv, g_bqkv);
    cudaGetSymbolAddress((void**)&wto,  g_wto);
    cudaGetSymbolAddress((void**)&wt1,  g_wt1);
    cudaGetSymbolAddress((void**)&wt2,  g_wt2);

    cudaFuncSetAttribute(attn_kernel,
                         cudaFuncAttributeMaxDynamicSharedMemorySize, ATTN_SMEM);
    cudaFuncSetAttribute(mm_gemm<0>,
                         cudaFuncAttributeMaxDynamicSharedMemorySize, GEMM_SMEM);
    cudaFuncSetAttribute(mm_gemm<1>,
                         cudaFuncAttributeMaxDynamicSharedMemorySize, GEMM_SMEM);
    cudaFuncSetAttribute(mm_gemm<2>,
                         cudaFuncAttributeMaxDynamicSharedMemorySize, GEMM_SMEM);

    // 0,1,2: weight transposes + bias concat
    transpose_qkv<<<dim3(32, 32, 3), 256>>>(Wq, Wk, Wv, wqkv);
    transpose_rest<<<dim3(64, 64, 3), 256>>>(Wo, W1, W2, wto, wt1, wt2);
    biascat<<<12, 256>>>(bq, bk, bv, bqkv);

    // 3: LN1
    ln_kernel<<<MDIM, 256>>>(inp, ln1_g, ln1_b, xln1h, xln1f);

    // 4: fused QKV GEMM -> qkv [M,3072]
    dim3 gQKV(QKVD / 128, MDIM / 128);
    mm_gemm<0><<<gQKV, 128, GEMM_SMEM>>>(xln1h, wqkv, bqkv, nullptr, qkv,
                                         MDIM, QKVD, EDIM);

    // 5: Attention -> ctx (ncu capture lands here)
    dim3 gA(SDIM / 128, HDIM, BDIM);
    attn_kernel<<<gA, 256, ATTN_SMEM>>>(qkv, ctx);

    // 6: O-proj + residual(LN1 full) -> x2 (float)
    dim3 gE(EDIM / 128, MDIM / 128);
    mm_gemm<1><<<gE, 128, GEMM_SMEM>>>(ctx, wto, bo, xln1f, x2, MDIM, EDIM, EDIM);

    // 7: LN2
    ln_kernel<<<MDIM, 256>>>(x2, ln2_g, ln2_b, x3h, x3f);

    // 8,9: MLP
    dim3 gF(FDIM / 128, MDIM / 128);
    mm_gemm<2><<<gF, 128, GEMM_SMEM>>>(x3h, wt1, b1, nullptr, h1, MDIM, FDIM, EDIM);
    mm_gemm<1><<<gE, 128, GEMM_SMEM>>>(h1, wt2, b2, x3f, out, MDIM, EDIM, FDIM);
}

// round 16
// speedup vs baseline: 7.3025x; 1.3108x over previous
#include <cuda_runtime.h>
#include <cuda_fp16.h>
#include <math.h>
#include <stdint.h>

// ---------------------------------------------------------------------------
// TransformerBlock B=4,S=2048,E=1024,H=16,D=64.
// R16 (third submit of the R14 design; two prior broker failures):
// GEMM 128x128 CTA / 256 thr / 8 warps (2x4), warp tile 64x32,
// __launch_bounds__(256,2) -> 16 warps/SM. 4-stage pipeline, prefetch 3,
// single barrier. Fused QKV GEMM + FA2 attention.
// ---------------------------------------------------------------------------

#define MDIM 8192
#define EDIM 1024
#define SDIM 2048
#define BDIM 4
#define HDIM 16
#define FDIM 2048
#define QKVD 3072

__device__ __half g_xln1h[MDIM * EDIM];
__device__ float  g_xln1f[MDIM * EDIM];
__device__ __half g_qkv [MDIM * QKVD];
__device__ __half g_ctx[MDIM * EDIM];
__device__ float  g_x2 [MDIM * EDIM];
__device__ __half g_x3h[MDIM * EDIM];
__device__ float  g_x3f[MDIM * EDIM];
__device__ __half g_h1 [MDIM * FDIM];
__device__ __half g_wqkv[QKVD * EDIM];
__device__ float  g_bqkv[QKVD];
__device__ __half g_wto[EDIM * EDIM];
__device__ __half g_wt1[FDIM * EDIM];
__device__ __half g_wt2[EDIM * FDIM];

// ---------------------------------------------------------------------------
__device__ __forceinline__ uint32_t smem_u32(const void* p) {
    uint32_t a;
    asm("{ .reg .u64 t; cvta.to.shared.u64 t, %1; cvt.u32.u64 %0, t; }"
        : "=r"(a) : "l"(p));
    return a;
}
__device__ __forceinline__ void cpa16(uint32_t s, const void* g) {
    asm volatile("cp.async.cg.shared.global [%0], [%1], 16;" :: "r"(s), "l"(g));
}
#define CP_COMMIT() asm volatile("cp.async.commit_group;" ::: "memory")
#define CP_WAIT1()  asm volatile("cp.async.wait_group 1;" ::: "memory")
#define CP_WAIT2()  asm volatile("cp.async.wait_group 2;" ::: "memory")

__device__ __forceinline__ void mma16(float* c, const uint32_t* a,
                                      uint32_t b0, uint32_t b1) {
    asm volatile(
        "mma.sync.aligned.m16n8k16.row.col.f32.f16.f16.f32 "
        "{%0,%1,%2,%3}, {%4,%5,%6,%7}, {%8,%9}, {%0,%1,%2,%3};"
        : "+f"(c[0]), "+f"(c[1]), "+f"(c[2]), "+f"(c[3])
        : "r"(a[0]), "r"(a[1]), "r"(a[2]), "r"(a[3]), "r"(b0), "r"(b1));
}
__device__ __forceinline__ void ldsm4(uint32_t* r, uint32_t addr) {
    asm volatile("ldmatrix.sync.aligned.m8n8.x4.shared.b16 {%0,%1,%2,%3}, [%4];"
        : "=r"(r[0]), "=r"(r[1]), "=r"(r[2]), "=r"(r[3]) : "r"(addr));
}
__device__ __forceinline__ void ldsm4t(uint32_t* r, uint32_t addr) {
    asm volatile("ldmatrix.sync.aligned.m8n8.x4.trans.shared.b16 {%0,%1,%2,%3}, [%4];"
        : "=r"(r[0]), "=r"(r[1]), "=r"(r[2]), "=r"(r[3]) : "r"(addr));
}
__device__ __forceinline__ uint32_t pkhalf(float x, float y) {
    __half2 h = __floats2half2_rn(x, y);
    return *reinterpret_cast<uint32_t*>(&h);
}

// ---------------------------------------------------------------------------
// Weight transposes + bias concat
// ---------------------------------------------------------------------------
__global__ __launch_bounds__(256) void transpose_qkv(
    const float* __restrict__ Wq, const float* __restrict__ Wk,
    const float* __restrict__ Wv, __half* __restrict__ wqkv)
{
    const float* W = (blockIdx.z == 0) ? Wq : (blockIdx.z == 1) ? Wk : Wv;
    const int n0 = blockIdx.x * 32, k0 = blockIdx.y * 32;
    __shared__ float t[32][33];
    const int x = threadIdx.x & 31, y = threadIdx.x >> 5;
    #pragma unroll
    for (int i = 0; i < 32; i += 8)
        t[y + i][x] = W[(size_t)(k0 + y + i) * EDIM + n0 + x];
    __syncthreads();
    #pragma unroll
    for (int i = 0; i < 32; i += 8)
        wqkv[(size_t)(blockIdx.z * 1024 + n0 + y + i) * EDIM + k0 + x]
            = __float2half_rn(t[x][y + i]);
}

__global__ __launch_bounds__(256) void transpose_rest(
    const float* __restrict__ Wo, const float* __restrict__ W1,
    const float* __restrict__ W2, __half* __restrict__ wto,
    __half* __restrict__ wt1, __half* __restrict__ wt2)
{
    const float* W; __half* WT; int K, N;
    switch (blockIdx.z) {
        case 0: W = Wo; WT = wto; K = EDIM; N = EDIM; break;
        case 1: W = W1; WT = wt1; K = EDIM; N = FDIM; break;
        default: W = W2; WT = wt2; K = FDIM; N = EDIM; break;
    }
    const int n0 = blockIdx.x * 32, k0 = blockIdx.y * 32;
    if (n0 >= N || k0 >= K) return;
    __shared__ float t[32][33];
    const int x = threadIdx.x & 31, y = threadIdx.x >> 5;
    #pragma unroll
    for (int i = 0; i < 32; i += 8)
        t[y + i][x] = W[(size_t)(k0 + y + i) * N + n0 + x];
    __syncthreads();
    #pragma unroll
    for (int i = 0; i < 32; i += 8)
        WT[(size_t)(n0 + y + i) * K + k0 + x] = __float2half_rn(t[x][y + i]);
}

__global__ __launch_bounds__(256) void biascat(
    const float* __restrict__ bq, const float* __restrict__ bk,
    const float* __restrict__ bv, float* __restrict__ bqkv)
{
    const int j = blockIdx.x * 256 + threadIdx.x;
    if (j < 1024)       bqkv[j] = bq[j];
    else if (j < 2048)  bqkv[j] = bk[j - 1024];
    else                bqkv[j] = bv[j - 2048];
}

// ---------------------------------------------------------------------------
// LayerNorm
// ---------------------------------------------------------------------------
__global__ __launch_bounds__(256) void ln_kernel(
    const float* __restrict__ x, const float* __restrict__ g,
    const float* __restrict__ b, __half* __restrict__ yh, float* __restrict__ yf)
{
    const int row = blockIdx.x;
    const int tid = threadIdx.x;
    const float4 v = reinterpret_cast<const float4*>(x + (size_t)row * EDIM)[tid];

    float s  = v.x + v.y + v.z + v.w;
    float ss = v.x * v.x + v.y * v.y + v.z * v.z + v.w * v.w;
    #pragma unroll
    for (int off = 16; off > 0; off >>= 1) {
        s  += __shfl_down_sync(0xffffffffu, s,  off);
        ss += __shfl_down_sync(0xffffffffu, ss, off);
    }
    __shared__ float wsum[8], wsq[8];
    __shared__ float s_mu, s_rstd;
    const int wid = tid >> 5, lane = tid & 31;
    if (lane == 0) { wsum[wid] = s; wsq[wid] = ss; }
    __syncthreads();
    if (tid == 0) {
        float ts = 0.f, tss = 0.f;
        #pragma unroll
        for (int i = 0; i < 8; i++) { ts += wsum[i]; tss += wsq[i]; }
        const float mu  = ts * (1.0f / EDIM);
        const float var = tss * (1.0f / EDIM) - mu * mu;
        s_mu = mu; s_rstd = rsqrtf(var + 1e-5f);
    }
    __syncthreads();
    const float mu = s_mu, rstd = s_rstd;
    const float4 gv = reinterpret_cast<const float4*>(g)[tid];
    const float4 bv = reinterpret_cast<const float4*>(b)[tid];
    float4 o;
    o.x = (v.x - mu) * rstd * gv.x + bv.x;
    o.y = (v.y - mu) * rstd * gv.y + bv.y;
    o.z = (v.z - mu) * rstd * gv.z + bv.z;
    o.w = (v.w - mu) * rstd * gv.w + bv.w;
    reinterpret_cast<float4*>(yf + (size_t)row * EDIM)[tid] = o;
    __half2* hp = reinterpret_cast<__half2*>(yh + (size_t)row * EDIM);
    hp[2 * tid + 0] = __halves2half2(__float2half_rn(o.x), __float2half_rn(o.y));
    hp[2 * tid + 1] = __halves2half2(__float2half_rn(o.z), __float2half_rn(o.w));
}

// ---------------------------------------------------------------------------
// fp16 GEMM: C[M,N] = A[M,K] @ Bt[N,K]^T + bias (+epilogue).
// CTA 128x128, 256 thr (8 warps 2x4), warp tile 64x32, KCH=32, 4 stages,
// prefetch 3, single barrier per iter, XOR-swizzled 64B rows.
// __launch_bounds__(256,2) -> 2 CTA/SM = 16 warps/SM.
// OP: 0 half out (bias); 1 float out (bias+residual); 2 half out (bias+GELU)
// ---------------------------------------------------------------------------
#define KCH 32
#define TILE_B 8192
#define STG_B  (2 * TILE_B)
#define GEMM_SMEM (4 * STG_B)             // 65536

template <int OP>
__global__ __launch_bounds__(256, 2) void mm_gemm(
    const __half* __restrict__ A, const __half* __restrict__ Bt,
    const float* __restrict__ bias, const float* __restrict__ res,
    void* __restrict__ Cv, int M, int N, int K)
{
    extern __shared__ uint32_t sm[];
    const int tid = threadIdx.x;
    const int wid = tid >> 5, lane = tid & 31;
    const int row0 = blockIdx.y * 128, col0 = blockIdx.x * 128;

    // copy mapping: 256 thr, row = tid>>1, segs {0,1}+2*(tid&1); 2 cp.async each
    const int crow = tid >> 1;
    const int cseg0 = (tid & 1) * 2;
    const __half* gA = A  + (size_t)(row0 + crow) * K;
    const __half* gB = Bt + (size_t)(col0 + crow) * K;
    const uint32_t sm0 = smem_u32(sm);
    const uint32_t swc = (uint32_t)((crow >> 1) & 3);
    const uint32_t dA = sm0 + (uint32_t)(crow * 64);
    const uint32_t dB = dA + TILE_B;

    const int nch = K >> 5;

    // prologue: chunks 0,1,2 -> stages 0,1,2
    #pragma unroll
    for (int c = 0; c < 3; c++) {
        const uint32_t so = (uint32_t)(c * STG_B);
        #pragma unroll
        for (int u = 0; u < 2; u++) {
            const int seg = cseg0 + u;
            const uint32_t sw = (uint32_t)((seg ^ swc) * 16);
            cpa16(dA + so + sw, gA + c * KCH + seg * 8);
            cpa16(dB + so + sw, gB + c * KCH + seg * 8);
        }
        CP_COMMIT();
    }

    const int wm = wid & 1, wn = wid >> 1;   // 2 x 4 warp grid, warp 64x32
    int arow[4];
    #pragma unroll
    for (int mt = 0; mt < 4; mt++)
        arow[mt] = wm * 64 + (lane & 15) + mt * 16;
    int brow[2];
    #pragma unroll
    for (int pr = 0; pr < 2; pr++)
        brow[pr] = wn * 32 + (lane & 7) + ((lane >> 4) << 3) + pr * 16;
    const int ahi = lane >> 4;
    const int bhi = (lane >> 3) & 1;

    float acc[4][4][4];
    #pragma unroll
    for (int mt = 0; mt < 4; mt++)
        #pragma unroll
        for (int nt = 0; nt < 4; nt++)
            #pragma unroll
            for (int r = 0; r < 4; r++) acc[mt][nt][r] = 0.f;

    for (int i = 0; i < nch; i++) {
        CP_WAIT2();                       // chunk i resident
        __syncthreads();                  // publish; stage (i+3)&3 free
        const int j = i + 3;
        if (j < nch) {
            const uint32_t so = (uint32_t)((j & 3) * STG_B);
            #pragma unroll
            for (int u = 0; u < 2; u++) {
                const int seg = cseg0 + u;
                const uint32_t sw = (uint32_t)((seg ^ swc) * 16);
                cpa16(dA + so + sw, gA + j * KCH + seg * 8);
                cpa16(dB + so + sw, gB + j * KCH + seg * 8);
            }
        }
        CP_COMMIT();

        const uint32_t st = sm0 + (uint32_t)((i & 3) * STG_B);

        #pragma unroll
        for (int ks = 0; ks < 2; ks++) {
            uint32_t a[4][4];
            #pragma unroll
            for (int mt = 0; mt < 4; mt++) {
                const int r = arow[mt];
                const uint32_t sw = (uint32_t)(((ks * 2 + ahi) ^ ((r >> 1) & 3)) * 16);
                ldsm4(a[mt], st + (uint32_t)(r * 64) + sw);
            }
            #pragma unroll
            for (int pr = 0; pr < 2; pr++) {
                const int r = brow[pr];
                const uint32_t sw = (uint32_t)(((ks * 2 + bhi) ^ ((r >> 1) & 3)) * 16);
                uint32_t b[4];
                ldsm4(b, st + TILE_B + (uint32_t)(r * 64) + sw);
                #pragma unroll
                for (int mt = 0; mt < 4; mt++)
                    mma16(acc[mt][2 * pr], a[mt], b[0], b[1]);
                #pragma unroll
                for (int mt = 0; mt < 4; mt++)
                    mma16(acc[mt][2 * pr + 1], a[mt], b[2], b[3]);
            }
        }
    }

    const int lr = lane >> 2, lk = lane & 3;
    const int lc = 2 * lk;
    #pragma unroll
    for (int nt = 0; nt < 4; nt++) {
        const int col = col0 + wn * 32 + nt * 8 + lc;
        const float bx = bias[col], by = bias[col + 1];
        #pragma unroll
        for (int mt = 0; mt < 4; mt++) {
            const int row = row0 + wm * 64 + mt * 16 + lr;
            #pragma unroll
            for (int h = 0; h < 2; h++) {
                const int r = row + h * 8;
                float vx = acc[mt][nt][2 * h + 0] + bx;
                float vy = acc[mt][nt][2 * h + 1] + by;
                if (OP == 2) {
                    vx = 0.5f * vx * (1.0f + erff(vx * 0.70710678118654752f));
                    vy = 0.5f * vy * (1.0f + erff(vy * 0.70710678118654752f));
                }
                if (OP == 1) {
                    const float* rp = res + (size_t)r * N + col;
                    vx += rp[0]; vy += rp[1];
                }
                if (OP == 0 || OP == 2) {
                    __half2* cp = reinterpret_cast<__half2*>(
                        (__half*)Cv + (size_t)r * N + col);
                    *cp = __halves2half2(__float2half_rn(vx), __float2half_rn(vy));
                } else {
                    *reinterpret_cast<float2*>((float*)Cv + (size_t)r * N + col)
                        = make_float2(vx, vy);
                }
            }
        }
    }
}

// ---------------------------------------------------------------------------
// Flash attention (FA2): fused qkv buffer, row stride 3072.
// ---------------------------------------------------------------------------
#define AQ_B  16384
#define AKV_B 8192
#define ATTN_SMEM (AQ_B + 4 * AKV_B)   // 49152

__global__ __launch_bounds__(256) void attn_kernel(
    const __half* __restrict__ QKV, __half* __restrict__ O)
{
    extern __shared__ char smc[];
    const uint32_t sQ = smem_u32(smc);
    const uint32_t sK0 = sQ + AQ_B;
    const uint32_t sV0 = sK0 + 2 * AKV_B;

    const int tid = threadIdx.x;
    const int w = tid >> 5, lane = tid & 31;
    const int lr = lane >> 2, lk = lane & 3;
    const int q0 = blockIdx.x * 128;
    const size_t baseq = (size_t)blockIdx.z * SDIM * QKVD + (size_t)blockIdx.y * 64;
    const size_t baseo = (size_t)blockIdx.z * SDIM * EDIM + (size_t)blockIdx.y * 64;
    const __half* Qp = QKV + baseq;
    const __half* Kp = QKV + baseq + 1024;
    const __half* Vp = QKV + baseq + 2048;

    #pragma unroll
    for (int u = 0; u < 4; u++) {
        const int idx = u * 256 + tid;
        const int r = idx >> 3, seg = idx & 7;
        cpa16(sQ + (uint32_t)(r * 128 + ((seg ^ (r & 7)) * 16)),
              Qp + (size_t)(q0 + r) * QKVD + seg * 8);
    }
    CP_COMMIT();
    {
        #pragma unroll
        for (int u = 0; u < 2; u++) {
            const int idx = u * 256 + tid;
            const int r = idx >> 3, seg = idx & 7;
            const uint32_t off = (uint32_t)(r * 128 + ((seg ^ (r & 7)) * 16));
            cpa16(sK0 + off, Kp + (size_t)r * QKVD + seg * 8);
            cpa16(sV0 + off, Vp + (size_t)r * QKVD + seg * 8);
        }
        CP_COMMIT();
    }

    float oacc[8][4];
    #pragma unroll
    for (int nt = 0; nt < 8; nt++)
        #pragma unroll
        for (int r = 0; r < 4; r++) oacc[nt][r] = 0.f;
    float m0 = -1e30f, m1 = -1e30f, l0 = 0.f, l1 = 0.f;

    const int qrow = w * 16 + (lane & 15);
    const int ahi = lane >> 4;
    const int krow_l = (lane & 7) + ((lane >> 4) << 3);
    const int kbhi = (lane >> 3) & 1;
    const int vrow_l = (lane & 7) + (((lane >> 3) & 1) << 3);
    const int vhi = lane >> 4;

    for (int kt = 0; kt < 32; kt++) {
        __syncthreads();
        const int jn = kt + 1;
        if (jn < 32) {
            const uint32_t so = (uint32_t)((jn & 1) * AKV_B);
            const int k0n = jn * 64;
            #pragma unroll
            for (int u = 0; u < 2; u++) {
                const int idx = u * 256 + tid;
                const int r = idx >> 3, seg = idx & 7;
                const uint32_t off = (uint32_t)(r * 128 + ((seg ^ (r & 7)) * 16));
                cpa16(sK0 + so + off, Kp + (size_t)(k0n + r) * QKVD + seg * 8);
                cpa16(sV0 + so + off, Vp + (size_t)(k0n + r) * QKVD + seg * 8);
            }
        }
        CP_COMMIT();
        CP_WAIT1();
        __syncthreads();

        const uint32_t kb = sK0 + (uint32_t)((kt & 1) * AKV_B);
        const uint32_t vb = sV0 + (uint32_t)((kt & 1) * AKV_B);

        float sacc[8][4];
        #pragma unroll
        for (int nt = 0; nt < 8; nt++)
            #pragma unroll
            for (int r = 0; r < 4; r++) sacc[nt][r] = 0.f;

        #pragma unroll
        for (int ks = 0; ks < 4; ks++) {
            uint32_t a[4];
            {
                const uint32_t sw = (uint32_t)(((ks * 2 + ahi) ^ (qrow & 7)) * 16);
                ldsm4(a, sQ + (uint32_t)(qrow * 128) + sw);
            }
            #pragma unroll
            for (int pr = 0; pr < 4; pr++) {
                const int r = krow_l + pr * 16;
                const uint32_t sw = (uint32_t)(((ks * 2 + kbhi) ^ (r & 7)) * 16);
                uint32_t b[4];
                ldsm4(b, kb + (uint32_t)(r * 128) + sw);
                mma16(sacc[2 * pr], a, b[0], b[1]);
                mma16(sacc[2 * pr + 1], a, b[2], b[3]);
            }
        }

        float mx0 = -1e30f, mx1 = -1e30f;
        #pragma unroll
        for (int nt = 0; nt < 8; nt++) {
            sacc[nt][0] *= 0.125f; sacc[nt][1] *= 0.125f;
            sacc[nt][2] *= 0.125f; sacc[nt][3] *= 0.125f;
            mx0 = fmaxf(mx0, fmaxf(sacc[nt][0], sacc[nt][1]));
            mx1 = fmaxf(mx1, fmaxf(sacc[nt][2], sacc[nt][3]));
        }
        mx0 = fmaxf(mx0, __shfl_xor_sync(0xffffffffu, mx0, 1));
        mx0 = fmaxf(mx0, __shfl_xor_sync(0xffffffffu, mx0, 2));
        mx1 = fmaxf(mx1, __shfl_xor_sync(0xffffffffu, mx1, 1));
        mx1 = fmaxf(mx1, __shfl_xor_sync(0xffffffffu, mx1, 2));
        const float mn0 = fmaxf(m0, mx0), mn1 = fmaxf(m1, mx1);
        const float al0 = __expf(m0 - mn0), al1 = __expf(m1 - mn1);
        m0 = mn0; m1 = mn1;
        float s0 = 0.f, s1 = 0.f;
        #pragma unroll
        for (int nt = 0; nt < 8; nt++) {
            sacc[nt][0] = __expf(sacc[nt][0] - mn0); s0 += sacc[nt][0];
            sacc[nt][1] = __expf(sacc[nt][1] - mn0); s0 += sacc[nt][1];
            sacc[nt][2] = __expf(sacc[nt][2] - mn1); s1 += sacc[nt][2];
            sacc[nt][3] = __expf(sacc[nt][3] - mn1); s1 += sacc[nt][3];
        }
        s0 += __shfl_xor_sync(0xffffffffu, s0, 1);
        s0 += __shfl_xor_sync(0xffffffffu, s0, 2);
        s1 += __shfl_xor_sync(0xffffffffu, s1, 1);
        s1 += __shfl_xor_sync(0xffffffffu, s1, 2);
        l0 = l0 * al0 + s0;
        l1 = l1 * al1 + s1;
        #pragma unroll
        for (int nt = 0; nt < 8; nt++) {
            oacc[nt][0] *= al0; oacc[nt][1] *= al0;
            oacc[nt][2] *= al1; oacc[nt][3] *= al1;
        }

        uint32_t pa[4][4];
        #pragma unroll
        for (int pr = 0; pr < 4; pr++) {
            pa[pr][0] = pkhalf(sacc[2 * pr][0], sacc[2 * pr][1]);
            pa[pr][1] = pkhalf(sacc[2 * pr][2], sacc[2 * pr][3]);
            pa[pr][2] = pkhalf(sacc[2 * pr + 1][0], sacc[2 * pr + 1][1]);
            pa[pr][3] = pkhalf(sacc[2 * pr + 1][2], sacc[2 * pr + 1][3]);
        }

        #pragma unroll
        for (int pr = 0; pr < 4; pr++) {
            #pragma unroll
            for (int pn = 0; pn < 4; pn++) {
                const int r = vrow_l + pr * 16;
                const uint32_t sw = (uint32_t)(((pn * 2 + vhi) ^ (r & 7)) * 16);
                uint32_t b[4];
                ldsm4t(b, vb + (uint32_t)(r * 128) + sw);
                mma16(oacc[2 * pn], pa[pr], b[0], b[1]);
                mma16(oacc[2 * pn + 1], pa[pr], b[2], b[3]);
            }
        }
    }

    const float inv0 = 1.0f / l0, inv1 = 1.0f / l1;
    const int r0g = q0 + w * 16 + lr;
    #pragma unroll
    for (int nt = 0; nt < 8; nt++) {
        const int c = nt * 8 + 2 * lk;
        __half2* p0 = reinterpret_cast<__half2*>(
            O + baseo + (size_t)r0g * EDIM + c);
        __half2* p1 = reinterpret_cast<__half2*>(
            O + baseo + (size_t)(r0g + 8) * EDIM + c);
        *p0 = __halves2half2(__float2half_rn(oacc[nt][0] * inv0),
                             __float2half_rn(oacc[nt][1] * inv0));
        *p1 = __halves2half2(__float2half_rn(oacc[nt][2] * inv1),
                             __float2half_rn(oacc[nt][3] * inv1));
    }
}

// ---------------------------------------------------------------------------
extern "C" void kernel_launch(void* const* d_in, const int* in_sizes, int n_in,
                              void* d_out, int out_size)
{
    const float* inp   = (const float*)d_in[0];
    const float* ln1_g = (const float*)d_in[1];
    const float* ln1_b = (const float*)d_in[2];
    const float* Wq    = (const float*)d_in[3];
    const float* bq    = (const float*)d_in[4];
    const float* Wk    = (const float*)d_in[5];
    const float* bk    = (const float*)d_in[6];
    const float* Wv    = (const float*)d_in[7];
    const float* bv    = (const float*)d_in[8];
    const float* Wo    = (const float*)d_in[9];
    const float* bo    = (const float*)d_in[10];
    const float* ln2_g = (const float*)d_in[11];
    const float* ln2_b = (const float*)d_in[12];
    const float* W1    = (const float*)d_in[13];
    const float* b1    = (const float*)d_in[14];
    const float* W2    = (const float*)d_in[15];
    const float* b2    = (const float*)d_in[16];
    float* out = (float*)d_out;

    __half *xln1h, *qkv, *ctx, *x3h, *h1, *wqkv, *wto, *wt1, *wt2;
    float *xln1f, *x2, *x3f, *bqkv;
    cudaGetSymbolAddress((void**)&xln1h, g_xln1h);
    cudaGetSymbolAddress((void**)&xln1f, g_xln1f);
    cudaGetSymbolAddress((void**)&qkv,  g_qkv);
    cudaGetSymbolAddress((void**)&ctx,  g_ctx);
    cudaGetSymbolAddress((void**)&x2,   g_x2);
    cudaGetSymbolAddress((void**)&x3h,  g_x3h);
    cudaGetSymbolAddress((void**)&x3f,  g_x3f);
    cudaGetSymbolAddress((void**)&h1,   g_h1);
    cudaGetSymbolAddress((void**)&wqkv, g_wqkv);
    cudaGetSymbolAddress((void**)&bqkv, g_bqkv);
    cudaGetSymbolAddress((void**)&wto,  g_wto);
    cudaGetSymbolAddress((void**)&wt1,  g_wt1);
    cudaGetSymbolAddress((void**)&wt2,  g_wt2);

    cudaFuncSetAttribute(attn_kernel,
                         cudaFuncAttributeMaxDynamicSharedMemorySize, ATTN_SMEM);
    cudaFuncSetAttribute(mm_gemm<0>,
                         cudaFuncAttributeMaxDynamicSharedMemorySize, GEMM_SMEM);
    cudaFuncSetAttribute(mm_gemm<1>,
                         cudaFuncAttributeMaxDynamicSharedMemorySize, GEMM_SMEM);
    cudaFuncSetAttribute(mm_gemm<2>,
                         cudaFuncAttributeMaxDynamicSharedMemorySize, GEMM_SMEM);

    // 0,1,2: weight transposes + bias concat
    transpose_qkv<<<dim3(32, 32, 3), 256>>>(Wq, Wk, Wv, wqkv);
    transpose_rest<<<dim3(64, 64, 3), 256>>>(Wo, W1, W2, wto, wt1, wt2);
    biascat<<<12, 256>>>(bq, bk, bv, bqkv);

    // 3: LN1
    ln_kernel<<<MDIM, 256>>>(inp, ln1_g, ln1_b, xln1h, xln1f);

    // 4: fused QKV GEMM -> qkv [M,3072]
    dim3 gQKV(QKVD / 128, MDIM / 128);
    mm_gemm<0><<<gQKV, 256, GEMM_SMEM>>>(xln1h, wqkv, bqkv, nullptr, qkv,
                                         MDIM, QKVD, EDIM);

    // 5: Attention -> ctx
    dim3 gA(SDIM / 128, HDIM, BDIM);
    attn_kernel<<<gA, 256, ATTN_SMEM>>>(qkv, ctx);

    // 6: O-proj + residual(LN1 full) -> x2 (float)
    dim3 gE(EDIM / 128, MDIM / 128);
    mm_gemm<1><<<gE, 256, GEMM_SMEM>>>(ctx, wto, bo, xln1f, x2, MDIM, EDIM, EDIM);

    // 7: LN2
    ln_kernel<<<MDIM, 256>>>(x2, ln2_g, ln2_b, x3h, x3f);

    // 8,9: MLP
    dim3 gF(FDIM / 128, MDIM / 128);
    mm_gemm<2><<<gF, 256, GEMM_SMEM>>>(x3h, wt1, b1, nullptr, h1, MDIM, FDIM, EDIM);
    mm_gemm<1><<<gE, 256, GEMM_SMEM>>>(h1, wt2, b2, x3f, out, MDIM, EDIM, FDIM);
}